// round 10
// baseline (speedup 1.0000x reference)
#include <cuda_runtime.h>
#include <cstdint>

#define B_  8
#define L_  1024
#define D_  256
#define H_  8
#define HD_ 2048
#define F_  1024
#define ROWS_ (B_*L_)
#define EPS_ 1e-5f

#if defined(__CUDA_ARCH_FEAT_SM103_ALL) || defined(__CUDA_ARCH_FEAT_SM100_ALL)
#define TC_OK 1
#else
#define TC_OK 0
#endif

// --------------------------- scratch (device globals) ------------------------
__device__ float g_Q[(size_t)ROWS_ * HD_];
__device__ float g_K[(size_t)ROWS_ * HD_];
__device__ float g_V[(size_t)ROWS_ * HD_];
__device__ float g_Vt[(size_t)B_ * H_ * D_ * L_];
__device__ float g_S[(size_t)B_ * H_ * L_ * L_];
__device__ float g_O[(size_t)ROWS_ * HD_];
__device__ float g_R1[(size_t)ROWS_ * D_];
__device__ float g_Z1[(size_t)ROWS_ * D_];
__device__ float g_Z1r[(size_t)ROWS_ * D_];
__device__ float g_Hb[(size_t)ROWS_ * F_];
__device__ float g_F[(size_t)ROWS_ * D_];
__device__ float g_L[(size_t)B_ * H_ * L_];
__device__ float g_xr[(size_t)ROWS_ * D_];
__device__ float g_Wqr[(size_t)HD_ * D_];
__device__ float g_Wkr[(size_t)HD_ * D_];
__device__ float g_Wvr[(size_t)HD_ * D_];
__device__ float g_Wur[(size_t)D_ * HD_];
__device__ float g_W1r[(size_t)F_ * D_];
__device__ float g_W2r[(size_t)D_ * F_];

// --------------------------- common helpers ----------------------------------
__device__ __forceinline__ uint32_t f2tf(float f) {
    uint32_t u; asm("cvt.rna.tf32.f32 %0, %1;" : "=r"(u) : "f"(f)); return u;
}
__device__ __forceinline__ float f2tf_f(float f) { return __uint_as_float(f2tf(f)); }

__device__ __forceinline__ void cp16(uint32_t saddr, const void* gptr) {
    asm volatile("cp.async.cg.shared.global [%0], [%1], 16;" :: "r"(saddr), "l"(gptr));
}
__device__ __forceinline__ void cp_commit() { asm volatile("cp.async.commit_group;"); }
__device__ __forceinline__ void cp_wait1()  { asm volatile("cp.async.wait_group 1;"); }
__device__ __forceinline__ void cp_wait0()  { asm volatile("cp.async.wait_group 0;"); }

__device__ __forceinline__ void mma8(float* c, const uint32_t* a, const uint32_t* b) {
    asm volatile(
        "mma.sync.aligned.m16n8k8.row.col.f32.tf32.tf32.f32 "
        "{%0,%1,%2,%3}, {%4,%5,%6,%7}, {%8,%9}, {%0,%1,%2,%3};"
        : "+f"(c[0]), "+f"(c[1]), "+f"(c[2]), "+f"(c[3])
        : "r"(a[0]), "r"(a[1]), "r"(a[2]), "r"(a[3]), "r"(b[0]), "r"(b[1]));
}

#if TC_OK
// --------------------------- tcgen05 helpers (sm_103a pass only) -------------
__device__ __forceinline__ bool elect1() {
    uint32_t p;
    asm volatile("{\n\t.reg .pred p;\n\telect.sync _|p, 0xFFFFFFFF;\n\tselp.b32 %0,1,0,p;\n\t}" : "=r"(p));
    return p != 0;
}
__device__ __forceinline__ void mbar_init(uint32_t a, uint32_t cnt) {
    asm volatile("mbarrier.init.shared.b64 [%0], %1;" :: "r"(a), "r"(cnt) : "memory");
}
__device__ __forceinline__ void mbar_wait(uint32_t a, uint32_t parity) {
    asm volatile(
        "{\n\t.reg .pred P;\n\t"
        "WL%=:\n\t"
        "mbarrier.try_wait.parity.acquire.cta.shared::cta.b64 P, [%0], %1, 0x989680;\n\t"
        "@P bra WD%=;\n\t"
        "bra WL%=;\n\t"
        "WD%=:\n\t}"
        :: "r"(a), "r"(parity) : "memory");
}
__device__ __forceinline__ void cp_arrive_noinc(uint32_t mbar) {
    asm volatile("cp.async.mbarrier.arrive.noinc.shared::cta.b64 [%0];" :: "r"(mbar) : "memory");
}
__device__ __forceinline__ void tc_fence_after() {
    asm volatile("tcgen05.fence::after_thread_sync;" ::: "memory");
}
__device__ __forceinline__ void tcalloc(uint32_t smem_addr, uint32_t ncols) {
    asm volatile("tcgen05.alloc.cta_group::1.sync.aligned.shared::cta.b32 [%0], %1;"
                 :: "r"(smem_addr), "r"(ncols) : "memory");
}
__device__ __forceinline__ void tcdealloc(uint32_t tmem, uint32_t ncols) {
    asm volatile("tcgen05.dealloc.cta_group::1.sync.aligned.b32 %0, %1;" :: "r"(tmem), "r"(ncols));
}
__device__ __forceinline__ void tcrelinquish() {
    asm volatile("tcgen05.relinquish_alloc_permit.cta_group::1.sync.aligned;");
}
__device__ __forceinline__ void tc_commit(uint32_t mbar) {
    asm volatile("tcgen05.commit.cta_group::1.mbarrier::arrive::one.shared::cluster.b64 [%0];"
                 :: "r"(mbar) : "memory");
}
__device__ __forceinline__ void wait_ld() {
    asm volatile("tcgen05.wait::ld.sync.aligned;" ::: "memory");
}
__device__ __forceinline__ void mma_tf32_ss(uint32_t d, uint64_t ad, uint64_t bd,
                                            uint32_t idesc, uint32_t en) {
    asm volatile(
        "{\n\t.reg .pred p;\n\tsetp.ne.u32 p, %4, 0;\n\t"
        "tcgen05.mma.cta_group::1.kind::tf32 [%0], %1, %2, %3, {%5,%5,%5,%5}, p;\n\t}"
        :: "r"(d), "l"(ad), "l"(bd), "r"(idesc), "r"(en), "r"(0u) : "memory");
}
__device__ __forceinline__ void ldtm32(uint32_t* r, uint32_t a) {
    asm volatile(
        "tcgen05.ld.sync.aligned.32x32b.x32.b32 "
        "{%0,%1,%2,%3,%4,%5,%6,%7,%8,%9,%10,%11,%12,%13,%14,%15,"
        "%16,%17,%18,%19,%20,%21,%22,%23,%24,%25,%26,%27,%28,%29,%30,%31}, [%32];"
        : "=r"(r[0]), "=r"(r[1]), "=r"(r[2]), "=r"(r[3]),
          "=r"(r[4]), "=r"(r[5]), "=r"(r[6]), "=r"(r[7]),
          "=r"(r[8]), "=r"(r[9]), "=r"(r[10]), "=r"(r[11]),
          "=r"(r[12]), "=r"(r[13]), "=r"(r[14]), "=r"(r[15]),
          "=r"(r[16]), "=r"(r[17]), "=r"(r[18]), "=r"(r[19]),
          "=r"(r[20]), "=r"(r[21]), "=r"(r[22]), "=r"(r[23]),
          "=r"(r[24]), "=r"(r[25]), "=r"(r[26]), "=r"(r[27]),
          "=r"(r[28]), "=r"(r[29]), "=r"(r[30]), "=r"(r[31])
        : "r"(a));
}
static constexpr uint64_t DESC_BASE =
    (uint64_t(2) << 61) | (uint64_t(1) << 46) | (uint64_t(64) << 32) | (uint64_t(1) << 16);
__device__ __forceinline__ uint64_t mk_desc(uint32_t a) {
    return DESC_BASE | ((uint64_t)(a >> 4) & 0x3FFFull);
}
#endif // TC_OK

// ============================================================================
// GEMM: C = A @ B^T  (A [M,K] lda, B [N,K] ldb, K-major, tf32-prerounded)
// CTA tile (MH*128) x NT, KC=32, 3-stage mbarrier pipeline.
// 288 threads: warps 0-7 produce (hoisted row addressing), warp 8 issues MMA.
// Vectorized float4 epilogue; for MH=1 all 8 warps split the column blocks.
// Lsum -> exp(v*escale)+row sums; Ldiv -> /Ldiv.
// ============================================================================
template<int MH, int NT>
__global__ __launch_bounds__(288)
void gemm_tc(const float* __restrict__ A, const float* __restrict__ Bm,
             float* __restrict__ C, int K, int lda, int ldb, int ldc,
             long long sA1, long long sA2, long long sB1, long long sB2,
             long long sC1, long long sC2,
             const float* __restrict__ bias, const float* __restrict__ resid, int ldres,
             int relu, int round_out, float escale,
             float* __restrict__ Lsum, const float* __restrict__ Ldiv)
{
    extern __shared__ __align__(1024) uint8_t smraw[];

    const int z = blockIdx.z;
    A  += (size_t)(z >> 3) * sA1 + (size_t)(z & 7) * sA2;
    Bm += (size_t)(z >> 3) * sB1 + (size_t)(z & 7) * sB2;
    C  += (size_t)(z >> 3) * sC1 + (size_t)(z & 7) * sC2;

    const int tid = threadIdx.x, wid = tid >> 5, lane = tid & 31;
    const int row0 = blockIdx.y * (MH * 128);
    const int col0 = blockIdx.x * NT;

#if TC_OK
    constexpr int ABYTES = MH * 16384;
    constexpr int BBYTES = (NT / 128) * 16384;
    constexpr int STG = ABYTES + BBYTES;
    constexpr int CTRL = 3 * STG;
    constexpr int RT = MH * 128 + NT;              // staged rows per chunk
    constexpr uint32_t IDESC =
        (1u << 4) | (2u << 7) | (2u << 10) | ((uint32_t)(NT / 8) << 17) | (8u << 24);

    const uint32_t smb = (uint32_t)__cvta_generic_to_shared(smraw);
    const uint32_t tptr = smb + CTRL;
    const uint32_t mbF = smb + CTRL + 8;     // full[0..2]
    const uint32_t mbE = smb + CTRL + 32;    // empty[0..2]
    const uint32_t mbD = smb + CTRL + 56;    // done

    if (wid == 0) tcalloc(tptr, MH * NT);
    if (tid == 0) {
        for (int s = 0; s < 3; ++s) { mbar_init(mbF + 8 * s, 256); mbar_init(mbE + 8 * s, 1); }
        mbar_init(mbD, 1);
    }
    __syncthreads();
    uint32_t tmem;
    asm volatile("ld.shared.b32 %0, [%1];" : "=r"(tmem) : "r"(tptr));

    const int T = K >> 5;

    if (wid < 8) {
        // ---- producers: each thread owns <=2 whole rows, addressing hoisted
        const float* gp[2]; uint32_t so[2]; int x7[2]; int nr = 0;
#pragma unroll
        for (int rr = 0; rr < 2; ++rr) {
            const int r = tid + rr * 256;
            if (r < RT) {
                const bool isB = (r >= MH * 128);
                const int rb = isB ? r - MH * 128 : r;
                gp[nr] = isB ? (Bm + (size_t)(col0 + rb) * ldb)
                             : (A + (size_t)(row0 + rb) * lda);
                so[nr] = (isB ? (uint32_t)(ABYTES + rb * 128) : (uint32_t)(r * 128));
                x7[nr] = r & 7;
                ++nr;
            }
        }
        int eph[3] = {1, 1, 1};
        int s = 0;
        for (int c = 0; c < T; ++c) {
            mbar_wait(mbE + 8 * s, eph[s]); eph[s] ^= 1;
            const uint32_t sb = smb + s * STG;
            const int k0 = c << 5;
            for (int i = 0; i < nr; ++i) {
                const float* g = gp[i] + k0;
                const uint32_t base = sb + so[i];
                const int x = x7[i];
#pragma unroll
                for (int q = 0; q < 8; ++q)
                    cp16(base + (uint32_t)((q ^ x) << 4), g + q * 4);
            }
            cp_arrive_noinc(mbF + 8 * s);
            if (++s == 3) s = 0;
        }
    } else if (elect1()) {
        // ---- MMA issuer (warp 8)
        int fph[3] = {0, 0, 0};
        int s = 0;
        for (int c = 0; c < T; ++c) {
            mbar_wait(mbF + 8 * s, fph[s]); fph[s] ^= 1;
            const uint32_t bA = smb + s * STG, bB = bA + ABYTES;
            const uint64_t bd = mk_desc(bB);
#pragma unroll
            for (int m = 0; m < MH; ++m) {
                const uint64_t ad = mk_desc(bA + m * 16384);
#pragma unroll
                for (int k8 = 0; k8 < 4; ++k8)
                    mma_tf32_ss(tmem + m * NT, ad + 2 * k8, bd + 2 * k8, IDESC,
                                (c > 0 || k8 > 0) ? 1u : 0u);
            }
            tc_commit(mbE + 8 * s);
            if (++s == 3) s = 0;
        }
        tc_commit(mbD);
    }

    mbar_wait(mbD, 0);
    tc_fence_after();
    __syncthreads();

    // ---- vectorized epilogue: TMEM -> regs -> smem(9-f4 pitch) -> STG.128
    // MH=2: warps 0-3 handle acc0 (rows 0-127), 4-7 acc1 (rows 128-255), all cols.
    // MH=1: all 8 warps on acc0; warps 0-3 take cols [0,NT/2), 4-7 [NT/2,NT).
    if (wid < 8) {
        const int sw = wid & 3;
        const int hsel = (MH == 2) ? (wid >> 2) : 0;
        const int cb0  = (MH == 2) ? 0 : (wid >> 2) * (NT / 64);
        const int cbN  = (MH == 2) ? (NT / 32) : (NT / 64);
        float4* wsm4 = (float4*)smraw + wid * (32 * 9);
        const int rloc = hsel * 128 + sw * 32 + lane;
        float rowsum = 0.f;
#pragma unroll 1
        for (int ci = 0; ci < cbN; ++ci) {
            const int cb = cb0 + ci;
            uint32_t rg[32];
            ldtm32(rg, tmem + hsel * NT + cb * 32);
            wait_ld();
            if (Lsum) {
#pragma unroll
                for (int j = 0; j < 32; ++j) {
                    float v = f2tf_f(__expf(__uint_as_float(rg[j]) * escale));
                    rowsum += v;
                    rg[j] = __float_as_uint(v);
                }
            }
            __syncwarp();
#pragma unroll
            for (int jq = 0; jq < 8; ++jq) {
                float4 v4 = make_float4(__uint_as_float(rg[jq * 4 + 0]),
                                        __uint_as_float(rg[jq * 4 + 1]),
                                        __uint_as_float(rg[jq * 4 + 2]),
                                        __uint_as_float(rg[jq * 4 + 3]));
                wsm4[lane * 9 + jq] = v4;
            }
            __syncwarp();
            const int cq = lane & 7;
            const int rsub = lane >> 3;
#pragma unroll 1
            for (int it = 0; it < 8; ++it) {
                const int r = it * 4 + rsub;
                float4 v = wsm4[r * 9 + cq];
                const int orow = row0 + hsel * 128 + sw * 32 + r;
                const int ocol = col0 + cb * 32 + cq * 4;
                if (bias) {
                    const float4 bv = *(const float4*)&bias[ocol];
                    v.x += bv.x; v.y += bv.y; v.z += bv.z; v.w += bv.w;
                }
                if (resid) {
                    const float4 rv = *(const float4*)&resid[(size_t)orow * ldres + ocol];
                    v.x += rv.x; v.y += rv.y; v.z += rv.z; v.w += rv.w;
                }
                if (Ldiv) {
                    const float inv = __frcp_rn(Ldiv[(size_t)z * L_ + orow]);
                    v.x *= inv; v.y *= inv; v.z *= inv; v.w *= inv;
                }
                if (relu) {
                    v.x = fmaxf(v.x, 0.f); v.y = fmaxf(v.y, 0.f);
                    v.z = fmaxf(v.z, 0.f); v.w = fmaxf(v.w, 0.f);
                }
                if (round_out) {
                    v.x = f2tf_f(v.x); v.y = f2tf_f(v.y);
                    v.z = f2tf_f(v.z); v.w = f2tf_f(v.w);
                }
                *(float4*)&C[(size_t)orow * ldc + ocol] = v;
            }
            __syncwarp();
        }
        if (Lsum) atomicAdd(&Lsum[(size_t)z * L_ + row0 + rloc], rowsum);
    }
    __syncthreads();
    if (wid == 0) { tcrelinquish(); tcdealloc(tmem, MH * NT); }

#else  // ----------------- mma.sync fallback (compute_103 pass only) ---------
    constexpr int ASTG = 128 * 36, STG2 = 2 * ASTG;
    uint32_t* sm = (uint32_t*)smraw;
    const int wm = wid & 3, wn = wid >> 2;
    const int g = lane >> 2, tg = lane & 3;
    const uint32_t smb = (uint32_t)__cvta_generic_to_shared(sm);

    for (int mh = 0; mh < MH; ++mh)
    for (int nh = 0; nh < NT / 128; ++nh) {
        const int r0 = row0 + mh * 128, c0 = col0 + nh * 128;
        float acc[2][8][4] = {};

        auto stage = [&](int st, int k0) {
#pragma unroll
            for (int i = 0; i < 4; i++) {
                const int s = tid + i * 256;
                if (s < 1024) {
                    const int r = s >> 3, kq = s & 7;
                    const uint32_t baseA = smb + (uint32_t)(st * STG2) * 4u;
                    const uint32_t baseB = baseA + (uint32_t)ASTG * 4u;
                    cp16(baseA + (uint32_t)(r * 36 + kq * 4) * 4u, A + (size_t)(r0 + r) * lda + k0 + kq * 4);
                    cp16(baseB + (uint32_t)(r * 36 + kq * 4) * 4u, Bm + (size_t)(c0 + r) * ldb + k0 + kq * 4);
                }
            }
        };

        const int T = K >> 5;
        stage(0, 0); cp_commit();
        for (int t = 0; t < T; ++t) {
            if (t + 1 < T) { stage((t + 1) & 1, (t + 1) << 5); cp_commit(); cp_wait1(); }
            else           { cp_wait0(); }
            __syncthreads();
            if (wid < 8) {
                const uint32_t* As = sm + (t & 1) * STG2;
                const uint32_t* Bs = As + ASTG;
#pragma unroll
                for (int ks = 0; ks < 32; ks += 8) {
                    uint32_t a[2][4], b[8][2];
#pragma unroll
                    for (int mf = 0; mf < 2; mf++) {
                        const int m0 = wm * 32 + mf * 16;
                        a[mf][0] = As[(m0 + g) * 36 + ks + tg];
                        a[mf][1] = As[(m0 + 8 + g) * 36 + ks + tg];
                        a[mf][2] = As[(m0 + g) * 36 + ks + 4 + tg];
                        a[mf][3] = As[(m0 + 8 + g) * 36 + ks + 4 + tg];
                    }
#pragma unroll
                    for (int nf = 0; nf < 8; nf++) {
                        const int n0 = wn * 64 + nf * 8;
                        b[nf][0] = Bs[(n0 + g) * 36 + ks + tg];
                        b[nf][1] = Bs[(n0 + g) * 36 + ks + 4 + tg];
                    }
#pragma unroll
                    for (int mf = 0; mf < 2; mf++)
#pragma unroll
                        for (int nf = 0; nf < 8; nf++)
                            mma8(acc[mf][nf], a[mf], b[nf]);
                }
            }
            __syncthreads();
        }

        if (wid < 8) {
            float rowsum[2][2] = {};
#pragma unroll
            for (int mf = 0; mf < 2; mf++)
#pragma unroll
                for (int nf = 0; nf < 8; nf++)
#pragma unroll
                    for (int q = 0; q < 4; q++) {
                        const int rr = r0 + wm * 32 + mf * 16 + g + (q >> 1) * 8;
                        const int cc = c0 + wn * 64 + nf * 8 + 2 * tg + (q & 1);
                        float v = acc[mf][nf][q];
                        if (Lsum) { v = f2tf_f(__expf(v * escale)); rowsum[mf][q >> 1] += v; }
                        if (bias)  v += bias[cc];
                        if (resid) v += resid[(size_t)rr * ldres + cc];
                        if (Ldiv)  v *= __frcp_rn(Ldiv[(size_t)z * L_ + rr]);
                        if (relu)  v = fmaxf(v, 0.f);
                        if (round_out) v = f2tf_f(v);
                        C[(size_t)rr * ldc + cc] = v;
                    }
            if (Lsum) {
#pragma unroll
                for (int mf = 0; mf < 2; mf++)
#pragma unroll
                    for (int qh = 0; qh < 2; qh++) {
                        float s = rowsum[mf][qh];
                        s += __shfl_xor_sync(~0u, s, 1);
                        s += __shfl_xor_sync(~0u, s, 2);
                        if (tg == 0)
                            atomicAdd(&Lsum[(size_t)z * L_ + r0 + wm * 32 + mf * 16 + g + qh * 8], s);
                    }
            }
        }
        __syncthreads();
    }
#endif
}

// --------------------------- merged tf32 rounding pass -----------------------
__global__ void cvt_all_kernel(const float4* x, float4* xr,
                               const float4* wq, float4* wqr,
                               const float4* wk, float4* wkr,
                               const float4* wv, float4* wvr,
                               const float4* wu, float4* wur,
                               const float4* w1, float4* w1r,
                               const float4* w2, float4* w2r)
{
    const int total = 524288 + 4 * 131072 + 2 * 65536;   // 1179648 float4
    for (int i = blockIdx.x * blockDim.x + threadIdx.x; i < total; i += gridDim.x * blockDim.x) {
        const float4* in; float4* out; int j = i;
        if (j < 524288) { in = x; out = xr; }
        else if ((j -= 524288) < 131072) { in = wq; out = wqr; }
        else if ((j -= 131072) < 131072) { in = wk; out = wkr; }
        else if ((j -= 131072) < 131072) { in = wv; out = wvr; }
        else if ((j -= 131072) < 131072) { in = wu; out = wur; }
        else if ((j -= 131072) < 65536)  { in = w1; out = w1r; }
        else { j -= 65536; in = w2; out = w2r; }
        float4 v = in[j];
        v.x = f2tf_f(v.x); v.y = f2tf_f(v.y); v.z = f2tf_f(v.z); v.w = f2tf_f(v.w);
        out[j] = v;
    }
}

// --------------------------- V transpose: Vt[z][e][j] = V[b, j, h*256+e] -----
__global__ void transpose_v(const float* __restrict__ V, float* __restrict__ Vt)
{
    __shared__ float t[32][33];
    const int z = blockIdx.z, b = z >> 3, h = z & 7;
    const int j0 = blockIdx.x * 32, e0 = blockIdx.y * 32;
    const int tx = threadIdx.x, ty = threadIdx.y;
#pragma unroll
    for (int k = 0; k < 4; k++)
        t[ty + k * 8][tx] = V[(size_t)(b * L_ + j0 + ty + k * 8) * HD_ + h * D_ + e0 + tx];
    __syncthreads();
#pragma unroll
    for (int k = 0; k < 4; k++)
        Vt[(size_t)z * D_ * L_ + (size_t)(e0 + ty + k * 8) * L_ + j0 + tx] = t[tx][ty + k * 8];
}

// --------------------------- layernorm over d=256 ----------------------------
__global__ void ln_kernel(const float* __restrict__ in, float* __restrict__ out,
                          float* __restrict__ out_r,
                          const float* __restrict__ g, const float* __restrict__ be)
{
    __shared__ float r1[8], r2[8];
    const int row = blockIdx.x, t = threadIdx.x;
    const float v = in[(size_t)row * D_ + t];
    float s = v, q = v * v;
#pragma unroll
    for (int o = 16; o; o >>= 1) {
        s += __shfl_xor_sync(~0u, s, o);
        q += __shfl_xor_sync(~0u, q, o);
    }
    if ((t & 31) == 0) { r1[t >> 5] = s; r2[t >> 5] = q; }
    __syncthreads();
    float S = 0.f, Q = 0.f;
#pragma unroll
    for (int i = 0; i < 8; i++) { S += r1[i]; Q += r2[i]; }
    const float mean = S * (1.f / D_);
    const float var = Q * (1.f / D_) - mean * mean;
    const float y = (v - mean) * rsqrtf(var + EPS_) * g[t] + be[t];
    out[(size_t)row * D_ + t] = y;
    if (out_r) out_r[(size_t)row * D_ + t] = f2tf_f(y);
}

// --------------------------- launch ------------------------------------------
extern "C" void kernel_launch(void* const* d_in, const int* in_sizes, int n_in,
                              void* d_out, int out_size)
{
    const float* x   = (const float*)d_in[0];
    const float* Wq  = (const float*)d_in[1];
    const float* Wk  = (const float*)d_in[2];
    const float* Wv  = (const float*)d_in[3];
    const float* Wu  = (const float*)d_in[4];
    const float* bu  = (const float*)d_in[5];
    const float* W1  = (const float*)d_in[6];
    const float* b1  = (const float*)d_in[7];
    const float* W2  = (const float*)d_in[8];
    const float* b2  = (const float*)d_in[9];
    const float* g1  = (const float*)d_in[10];
    const float* be1 = (const float*)d_in[11];
    const float* g2  = (const float*)d_in[12];
    const float* be2 = (const float*)d_in[13];
    float* out = (float*)d_out;

    float *Qb, *Kb, *Vb, *Vt, *S, *O, *R1, *Z1, *Z1r, *Hb, *F, *Lb;
    float *xr, *Wqr, *Wkr, *Wvr, *Wur, *W1r, *W2r;
    cudaGetSymbolAddress((void**)&Qb, g_Q);
    cudaGetSymbolAddress((void**)&Kb, g_K);
    cudaGetSymbolAddress((void**)&Vb, g_V);
    cudaGetSymbolAddress((void**)&Vt, g_Vt);
    cudaGetSymbolAddress((void**)&S,  g_S);
    cudaGetSymbolAddress((void**)&O,  g_O);
    cudaGetSymbolAddress((void**)&R1, g_R1);
    cudaGetSymbolAddress((void**)&Z1, g_Z1);
    cudaGetSymbolAddress((void**)&Z1r, g_Z1r);
    cudaGetSymbolAddress((void**)&Hb, g_Hb);
    cudaGetSymbolAddress((void**)&F,  g_F);
    cudaGetSymbolAddress((void**)&Lb, g_L);
    cudaGetSymbolAddress((void**)&xr,  g_xr);
    cudaGetSymbolAddress((void**)&Wqr, g_Wqr);
    cudaGetSymbolAddress((void**)&Wkr, g_Wkr);
    cudaGetSymbolAddress((void**)&Wvr, g_Wvr);
    cudaGetSymbolAddress((void**)&Wur, g_Wur);
    cudaGetSymbolAddress((void**)&W1r, g_W1r);
    cudaGetSymbolAddress((void**)&W2r, g_W2r);

    constexpr int SMEM22 = 3 * 65536 + 64;   // <2,256>
    constexpr int SMEM12 = 3 * 49152 + 64;   // <1,256>
    cudaFuncSetAttribute(gemm_tc<2,256>, cudaFuncAttributeMaxDynamicSharedMemorySize, SMEM22);
    cudaFuncSetAttribute(gemm_tc<1,256>, cudaFuncAttributeMaxDynamicSharedMemorySize, SMEM12);

    cvt_all_kernel<<<1184, 256>>>((const float4*)x,  (float4*)xr,
                                  (const float4*)Wq, (float4*)Wqr,
                                  (const float4*)Wk, (float4*)Wkr,
                                  (const float4*)Wv, (float4*)Wvr,
                                  (const float4*)Wu, (float4*)Wur,
                                  (const float4*)W1, (float4*)W1r,
                                  (const float4*)W2, (float4*)W2r);

    const long long LL2 = (long long)L_ * L_;

    // QKV projections
    gemm_tc<2,256><<<dim3(HD_/256, ROWS_/256, 1), 288, SMEM22>>>(xr, Wqr, Qb, D_, D_, D_, HD_,
        0,0,0,0,0,0, nullptr, nullptr, 0, 0, 1, 0.f, nullptr, nullptr);
    gemm_tc<2,256><<<dim3(HD_/256, ROWS_/256, 1), 288, SMEM22>>>(xr, Wkr, Kb, D_, D_, D_, HD_,
        0,0,0,0,0,0, nullptr, nullptr, 0, 0, 1, 0.f, nullptr, nullptr);
    gemm_tc<2,256><<<dim3(HD_/256, ROWS_/256, 1), 288, SMEM22>>>(xr, Wvr, Vb, D_, D_, D_, HD_,
        0,0,0,0,0,0, nullptr, nullptr, 0, 0, 1, 0.f, nullptr, nullptr);

    transpose_v<<<dim3(L_/32, D_/32, B_*H_), dim3(32, 8)>>>(Vb, Vt);

    // scores + fused exp & row-sum
    cudaMemsetAsync(Lb, 0, (size_t)B_ * H_ * L_ * sizeof(float));
    gemm_tc<2,256><<<dim3(L_/256, L_/256, B_*H_), 288, SMEM22>>>(Qb, Kb, S, D_, HD_, HD_, L_,
        (long long)L_*HD_, D_, (long long)L_*HD_, D_, 8*LL2, LL2,
        nullptr, nullptr, 0, 0, 0, 0.0625f, Lb, nullptr);

    // PV: O = (S @ Vt^T) / l
    gemm_tc<2,256><<<dim3(D_/256, L_/256, B_*H_), 288, SMEM22>>>(S, Vt, O, L_, L_, L_, HD_,
        8*LL2, LL2, 8LL*D_*L_, (long long)D_*L_, (long long)L_*HD_, D_,
        nullptr, nullptr, 0, 0, 1, 0.f, nullptr, Lb);

    // output projection + bias + residual(x)
    gemm_tc<1,256><<<dim3(D_/256, ROWS_/128, 1), 288, SMEM12>>>(O, Wur, R1, HD_, HD_, HD_, D_,
        0,0,0,0,0,0, bu, x, D_, 0, 0, 0.f, nullptr, nullptr);
    ln_kernel<<<ROWS_, 256>>>(R1, Z1, Z1r, g1, be1);

    // FFN
    gemm_tc<2,256><<<dim3(F_/256, ROWS_/256, 1), 288, SMEM22>>>(Z1r, W1r, Hb, D_, D_, D_, F_,
        0,0,0,0,0,0, b1, nullptr, 0, 1, 1, 0.f, nullptr, nullptr);
    gemm_tc<1,256><<<dim3(D_/256, ROWS_/128, 1), 288, SMEM12>>>(Hb, W2r, F, F_, F_, F_, D_,
        0,0,0,0,0,0, b2, Z1, D_, 0, 0, 0.f, nullptr, nullptr);
    ln_kernel<<<ROWS_, 256>>>(F, out, nullptr, g2, be2);
}

// round 11
// speedup vs baseline: 1.2476x; 1.2476x over previous
#include <cuda_runtime.h>
#include <cuda.h>
#include <cstdint>

#define B_  8
#define L_  1024
#define D_  256
#define H_  8
#define HD_ 2048
#define F_  1024
#define ROWS_ (B_*L_)
#define EPS_ 1e-5f

#if defined(__CUDA_ARCH_FEAT_SM103_ALL) || defined(__CUDA_ARCH_FEAT_SM100_ALL)
#define TC_OK 1
#else
#define TC_OK 0
#endif

// --------------------------- scratch (device globals) ------------------------
__device__ float g_Q[(size_t)ROWS_ * HD_];
__device__ float g_K[(size_t)ROWS_ * HD_];
__device__ float g_V[(size_t)ROWS_ * HD_];
__device__ float g_Vt[(size_t)B_ * H_ * D_ * L_];
__device__ float g_S[(size_t)B_ * H_ * L_ * L_];
__device__ float g_O[(size_t)ROWS_ * HD_];
__device__ float g_R1[(size_t)ROWS_ * D_];
__device__ float g_Z1[(size_t)ROWS_ * D_];
__device__ float g_Z1r[(size_t)ROWS_ * D_];
__device__ float g_Hb[(size_t)ROWS_ * F_];
__device__ float g_F[(size_t)ROWS_ * D_];
__device__ float g_L[(size_t)B_ * H_ * L_];
__device__ float g_xr[(size_t)ROWS_ * D_];
__device__ float g_Wqr[(size_t)HD_ * D_];
__device__ float g_Wkr[(size_t)HD_ * D_];
__device__ float g_Wvr[(size_t)HD_ * D_];
__device__ float g_Wur[(size_t)D_ * HD_];
__device__ float g_W1r[(size_t)F_ * D_];
__device__ float g_W2r[(size_t)D_ * F_];

// --------------------------- common helpers ----------------------------------
__device__ __forceinline__ uint32_t f2tf(float f) {
    uint32_t u; asm("cvt.rna.tf32.f32 %0, %1;" : "=r"(u) : "f"(f)); return u;
}
__device__ __forceinline__ float f2tf_f(float f) { return __uint_as_float(f2tf(f)); }

__device__ __forceinline__ void cp16(uint32_t saddr, const void* gptr) {
    asm volatile("cp.async.cg.shared.global [%0], [%1], 16;" :: "r"(saddr), "l"(gptr));
}
__device__ __forceinline__ void cp_commit() { asm volatile("cp.async.commit_group;"); }
__device__ __forceinline__ void cp_wait1()  { asm volatile("cp.async.wait_group 1;"); }
__device__ __forceinline__ void cp_wait0()  { asm volatile("cp.async.wait_group 0;"); }

__device__ __forceinline__ void mma8(float* c, const uint32_t* a, const uint32_t* b) {
    asm volatile(
        "mma.sync.aligned.m16n8k8.row.col.f32.tf32.tf32.f32 "
        "{%0,%1,%2,%3}, {%4,%5,%6,%7}, {%8,%9}, {%0,%1,%2,%3};"
        : "+f"(c[0]), "+f"(c[1]), "+f"(c[2]), "+f"(c[3])
        : "r"(a[0]), "r"(a[1]), "r"(a[2]), "r"(a[3]), "r"(b[0]), "r"(b[1]));
}

#if TC_OK
// --------------------------- tcgen05/TMA helpers (sm_103a pass only) ---------
__device__ __forceinline__ bool elect1() {
    uint32_t p;
    asm volatile("{\n\t.reg .pred p;\n\telect.sync _|p, 0xFFFFFFFF;\n\tselp.b32 %0,1,0,p;\n\t}" : "=r"(p));
    return p != 0;
}
__device__ __forceinline__ void mbar_init(uint32_t a, uint32_t cnt) {
    asm volatile("mbarrier.init.shared.b64 [%0], %1;" :: "r"(a), "r"(cnt) : "memory");
}
__device__ __forceinline__ void mbar_wait(uint32_t a, uint32_t parity) {
    asm volatile(
        "{\n\t.reg .pred P;\n\t"
        "WL%=:\n\t"
        "mbarrier.try_wait.parity.acquire.cta.shared::cta.b64 P, [%0], %1, 0x989680;\n\t"
        "@P bra WD%=;\n\t"
        "bra WL%=;\n\t"
        "WD%=:\n\t}"
        :: "r"(a), "r"(parity) : "memory");
}
__device__ __forceinline__ void mbar_expect_tx(uint32_t a, uint32_t bytes) {
    asm volatile("mbarrier.arrive.expect_tx.shared.b64 _, [%0], %1;"
                 :: "r"(a), "r"(bytes) : "memory");
}
__device__ __forceinline__ void tma3d(uint32_t smem, const void* tm,
                                      int c0, int c1, int c2, uint32_t mbar) {
    asm volatile(
        "cp.async.bulk.tensor.3d.shared::cta.global.tile.mbarrier::complete_tx::bytes "
        "[%0], [%1, {%2, %3, %4}], [%5];"
        :: "r"(smem), "l"(tm), "r"(c0), "r"(c1), "r"(c2), "r"(mbar) : "memory");
}
__device__ __forceinline__ void tc_fence_after() {
    asm volatile("tcgen05.fence::after_thread_sync;" ::: "memory");
}
__device__ __forceinline__ void tcalloc(uint32_t smem_addr, uint32_t ncols) {
    asm volatile("tcgen05.alloc.cta_group::1.sync.aligned.shared::cta.b32 [%0], %1;"
                 :: "r"(smem_addr), "r"(ncols) : "memory");
}
__device__ __forceinline__ void tcdealloc(uint32_t tmem, uint32_t ncols) {
    asm volatile("tcgen05.dealloc.cta_group::1.sync.aligned.b32 %0, %1;" :: "r"(tmem), "r"(ncols));
}
__device__ __forceinline__ void tcrelinquish() {
    asm volatile("tcgen05.relinquish_alloc_permit.cta_group::1.sync.aligned;");
}
__device__ __forceinline__ void tc_commit(uint32_t mbar) {
    asm volatile("tcgen05.commit.cta_group::1.mbarrier::arrive::one.shared::cluster.b64 [%0];"
                 :: "r"(mbar) : "memory");
}
__device__ __forceinline__ void wait_ld() {
    asm volatile("tcgen05.wait::ld.sync.aligned;" ::: "memory");
}
__device__ __forceinline__ void mma_tf32_ss(uint32_t d, uint64_t ad, uint64_t bd,
                                            uint32_t idesc, uint32_t en) {
    asm volatile(
        "{\n\t.reg .pred p;\n\tsetp.ne.u32 p, %4, 0;\n\t"
        "tcgen05.mma.cta_group::1.kind::tf32 [%0], %1, %2, %3, {%5,%5,%5,%5}, p;\n\t}"
        :: "r"(d), "l"(ad), "l"(bd), "r"(idesc), "r"(en), "r"(0u) : "memory");
}
__device__ __forceinline__ void ldtm32(uint32_t* r, uint32_t a) {
    asm volatile(
        "tcgen05.ld.sync.aligned.32x32b.x32.b32 "
        "{%0,%1,%2,%3,%4,%5,%6,%7,%8,%9,%10,%11,%12,%13,%14,%15,"
        "%16,%17,%18,%19,%20,%21,%22,%23,%24,%25,%26,%27,%28,%29,%30,%31}, [%32];"
        : "=r"(r[0]), "=r"(r[1]), "=r"(r[2]), "=r"(r[3]),
          "=r"(r[4]), "=r"(r[5]), "=r"(r[6]), "=r"(r[7]),
          "=r"(r[8]), "=r"(r[9]), "=r"(r[10]), "=r"(r[11]),
          "=r"(r[12]), "=r"(r[13]), "=r"(r[14]), "=r"(r[15]),
          "=r"(r[16]), "=r"(r[17]), "=r"(r[18]), "=r"(r[19]),
          "=r"(r[20]), "=r"(r[21]), "=r"(r[22]), "=r"(r[23]),
          "=r"(r[24]), "=r"(r[25]), "=r"(r[26]), "=r"(r[27]),
          "=r"(r[28]), "=r"(r[29]), "=r"(r[30]), "=r"(r[31])
        : "r"(a));
}
static constexpr uint64_t DESC_BASE =
    (uint64_t(2) << 61) | (uint64_t(1) << 46) | (uint64_t(64) << 32) | (uint64_t(1) << 16);
__device__ __forceinline__ uint64_t mk_desc(uint32_t a) {
    return DESC_BASE | ((uint64_t)(a >> 4) & 0x3FFFull);
}
#endif // TC_OK

// ============================================================================
// GEMM: C = A @ B^T (K-major, tf32-prerounded), CTA tile (MH*128) x NT, KC=32.
// sm_103a: TMA producer (1 elected thread) + warp-1 MMA issuer, 3-stage
// mbarrier pipeline, TMEM accumulators, vectorized epilogue.
// Batched coords: zA = z>>zsh, inner offset = (z & ((1<<zsh)-1))*koMul.
// ============================================================================
template<int MH, int NT>
__global__ __launch_bounds__(256)
void gemm_tc(const __grid_constant__ CUtensorMap tmA,
             const __grid_constant__ CUtensorMap tmB,
             const float* __restrict__ A, const float* __restrict__ Bm,
             float* __restrict__ C, int K, int lda, int ldb, int ldc,
             long long sA1, long long sA2, long long sB1, long long sB2,
             long long sC1, long long sC2,
             int zsh, int koMul,
             const float* __restrict__ bias, const float* __restrict__ resid, int ldres,
             int relu, int round_out, float escale,
             float* __restrict__ Lsum, const float* __restrict__ Ldiv)
{
    extern __shared__ __align__(1024) uint8_t smraw[];

    const int z = blockIdx.z;
    A  += (size_t)(z >> 3) * sA1 + (size_t)(z & 7) * sA2;
    Bm += (size_t)(z >> 3) * sB1 + (size_t)(z & 7) * sB2;
    C  += (size_t)(z >> 3) * sC1 + (size_t)(z & 7) * sC2;

    const int tid = threadIdx.x, wid = tid >> 5, lane = tid & 31;
    const int row0 = blockIdx.y * (MH * 128);
    const int col0 = blockIdx.x * NT;

#if TC_OK
    constexpr int ABYTES = MH * 16384;
    constexpr int BBYTES = (NT / 128) * 16384;
    constexpr int STGB = ABYTES + BBYTES;
    constexpr int CTRL = 3 * STGB;
    constexpr uint32_t IDESC =
        (1u << 4) | (2u << 7) | (2u << 10) | ((uint32_t)(NT / 8) << 17) | (8u << 24);

    const uint32_t smb = (uint32_t)__cvta_generic_to_shared(smraw);
    const uint32_t tptr = smb + CTRL;
    const uint32_t mbF = smb + CTRL + 8;     // full[0..2]
    const uint32_t mbE = smb + CTRL + 32;    // empty[0..2]
    const uint32_t mbD = smb + CTRL + 56;    // done

    if (wid == 0) tcalloc(tptr, MH * NT);
    if (tid == 0) {
        for (int s = 0; s < 3; ++s) { mbar_init(mbF + 8 * s, 1); mbar_init(mbE + 8 * s, 1); }
        mbar_init(mbD, 1);
    }
    __syncthreads();
    uint32_t tmem;
    asm volatile("ld.shared.b32 %0, [%1];" : "=r"(tmem) : "r"(tptr));

    const int T = K >> 5;
    const int zA = z >> zsh;
    const int ko = (z & ((1 << zsh) - 1)) * koMul;

    if (wid == 0) {
        if (elect1()) {
            // ---- TMA producer
            int eph[3] = {1, 1, 1};
            int s = 0;
            for (int c = 0; c < T; ++c) {
                mbar_wait(mbE + 8 * s, eph[s]); eph[s] ^= 1;
                const uint32_t bA = smb + s * STGB;
                const uint32_t fb = mbF + 8 * s;
                const int kc = ko + (c << 5);
                mbar_expect_tx(fb, STGB);
                tma3d(bA, &tmA, kc, row0, zA, fb);
                tma3d(bA + ABYTES, &tmB, kc, col0, zA, fb);
                if (++s == 3) s = 0;
            }
        }
    } else if (wid == 1) {
        if (elect1()) {
            // ---- MMA issuer
            int fph[3] = {0, 0, 0};
            int s = 0;
            for (int c = 0; c < T; ++c) {
                mbar_wait(mbF + 8 * s, fph[s]); fph[s] ^= 1;
                const uint32_t bA = smb + s * STGB, bB = bA + ABYTES;
                const uint64_t bd = mk_desc(bB);
#pragma unroll
                for (int m = 0; m < MH; ++m) {
                    const uint64_t ad = mk_desc(bA + m * 16384);
#pragma unroll
                    for (int k8 = 0; k8 < 4; ++k8)
                        mma_tf32_ss(tmem + m * NT, ad + 2 * k8, bd + 2 * k8, IDESC,
                                    (c > 0 || k8 > 0) ? 1u : 0u);
                }
                tc_commit(mbE + 8 * s);
                if (++s == 3) s = 0;
            }
            tc_commit(mbD);
        }
    }

    mbar_wait(mbD, 0);
    tc_fence_after();
    __syncthreads();

    // ---- vectorized epilogue: TMEM -> regs -> smem(9-f4 pitch) -> STG.128
    // MH=2: warps 0-3 on acc0 rows, 4-7 on acc1 rows; all column blocks.
    // MH=1: all 8 warps on acc0; warps 0-3 cols [0,NT/2), 4-7 [NT/2,NT).
    if (wid < 8) {
        const int sw = wid & 3;
        const int hsel = (MH == 2) ? (wid >> 2) : 0;
        const int cb0  = (MH == 2) ? 0 : (wid >> 2) * (NT / 64);
        const int cbN  = (MH == 2) ? (NT / 32) : (NT / 64);
        float4* wsm4 = (float4*)smraw + wid * (32 * 9);
        const int rloc = hsel * 128 + sw * 32 + lane;
        float rowsum = 0.f;
#pragma unroll 1
        for (int ci = 0; ci < cbN; ++ci) {
            const int cb = cb0 + ci;
            uint32_t rg[32];
            ldtm32(rg, tmem + hsel * NT + cb * 32);
            wait_ld();
            if (Lsum) {
#pragma unroll
                for (int j = 0; j < 32; ++j) {
                    float v = f2tf_f(__expf(__uint_as_float(rg[j]) * escale));
                    rowsum += v;
                    rg[j] = __float_as_uint(v);
                }
            }
            __syncwarp();
#pragma unroll
            for (int jq = 0; jq < 8; ++jq) {
                float4 v4 = make_float4(__uint_as_float(rg[jq * 4 + 0]),
                                        __uint_as_float(rg[jq * 4 + 1]),
                                        __uint_as_float(rg[jq * 4 + 2]),
                                        __uint_as_float(rg[jq * 4 + 3]));
                wsm4[lane * 9 + jq] = v4;
            }
            __syncwarp();
            const int cq = lane & 7;
            const int rsub = lane >> 3;
#pragma unroll 1
            for (int it = 0; it < 8; ++it) {
                const int r = it * 4 + rsub;
                float4 v = wsm4[r * 9 + cq];
                const int orow = row0 + hsel * 128 + sw * 32 + r;
                const int ocol = col0 + cb * 32 + cq * 4;
                if (bias) {
                    const float4 bv = *(const float4*)&bias[ocol];
                    v.x += bv.x; v.y += bv.y; v.z += bv.z; v.w += bv.w;
                }
                if (resid) {
                    const float4 rv = *(const float4*)&resid[(size_t)orow * ldres + ocol];
                    v.x += rv.x; v.y += rv.y; v.z += rv.z; v.w += rv.w;
                }
                if (Ldiv) {
                    const float inv = __frcp_rn(Ldiv[(size_t)z * L_ + orow]);
                    v.x *= inv; v.y *= inv; v.z *= inv; v.w *= inv;
                }
                if (relu) {
                    v.x = fmaxf(v.x, 0.f); v.y = fmaxf(v.y, 0.f);
                    v.z = fmaxf(v.z, 0.f); v.w = fmaxf(v.w, 0.f);
                }
                if (round_out) {
                    v.x = f2tf_f(v.x); v.y = f2tf_f(v.y);
                    v.z = f2tf_f(v.z); v.w = f2tf_f(v.w);
                }
                *(float4*)&C[(size_t)orow * ldc + ocol] = v;
            }
            __syncwarp();
        }
        if (Lsum) atomicAdd(&Lsum[(size_t)z * L_ + row0 + rloc], rowsum);
    }
    __syncthreads();
    if (wid == 0) { tcrelinquish(); tcdealloc(tmem, MH * NT); }

#else  // ----------------- mma.sync fallback (compute_103 pass only) ---------
    constexpr int ASTG = 128 * 36, STG2 = 2 * ASTG;
    uint32_t* sm = (uint32_t*)smraw;
    const int wm = wid & 3, wn = wid >> 2;
    const int g = lane >> 2, tg = lane & 3;
    const uint32_t smb = (uint32_t)__cvta_generic_to_shared(sm);

    for (int mh = 0; mh < MH; ++mh)
    for (int nh = 0; nh < NT / 128; ++nh) {
        const int r0 = row0 + mh * 128, c0 = col0 + nh * 128;
        float acc[2][8][4] = {};

        auto stage = [&](int st, int k0) {
#pragma unroll
            for (int i = 0; i < 4; i++) {
                const int s = tid + i * 256;
                const int r = s >> 3, kq = s & 7;
                const uint32_t baseA = smb + (uint32_t)(st * STG2) * 4u;
                const uint32_t baseB = baseA + (uint32_t)ASTG * 4u;
                cp16(baseA + (uint32_t)(r * 36 + kq * 4) * 4u, A + (size_t)(r0 + r) * lda + k0 + kq * 4);
                cp16(baseB + (uint32_t)(r * 36 + kq * 4) * 4u, Bm + (size_t)(c0 + r) * ldb + k0 + kq * 4);
            }
        };

        const int T = K >> 5;
        stage(0, 0); cp_commit();
        for (int t = 0; t < T; ++t) {
            if (t + 1 < T) { stage((t + 1) & 1, (t + 1) << 5); cp_commit(); cp_wait1(); }
            else           { cp_wait0(); }
            __syncthreads();
            const uint32_t* As = sm + (t & 1) * STG2;
            const uint32_t* Bs = As + ASTG;
#pragma unroll
            for (int ks = 0; ks < 32; ks += 8) {
                uint32_t a[2][4], b[8][2];
#pragma unroll
                for (int mf = 0; mf < 2; mf++) {
                    const int m0 = wm * 32 + mf * 16;
                    a[mf][0] = As[(m0 + g) * 36 + ks + tg];
                    a[mf][1] = As[(m0 + 8 + g) * 36 + ks + tg];
                    a[mf][2] = As[(m0 + g) * 36 + ks + 4 + tg];
                    a[mf][3] = As[(m0 + 8 + g) * 36 + ks + 4 + tg];
                }
#pragma unroll
                for (int nf = 0; nf < 8; nf++) {
                    const int n0 = wn * 64 + nf * 8;
                    b[nf][0] = Bs[(n0 + g) * 36 + ks + tg];
                    b[nf][1] = Bs[(n0 + g) * 36 + ks + 4 + tg];
                }
#pragma unroll
                for (int mf = 0; mf < 2; mf++)
#pragma unroll
                    for (int nf = 0; nf < 8; nf++)
                        mma8(acc[mf][nf], a[mf], b[nf]);
            }
            __syncthreads();
        }

        float rowsum[2][2] = {};
#pragma unroll
        for (int mf = 0; mf < 2; mf++)
#pragma unroll
            for (int nf = 0; nf < 8; nf++)
#pragma unroll
                for (int q = 0; q < 4; q++) {
                    const int rr = r0 + wm * 32 + mf * 16 + g + (q >> 1) * 8;
                    const int cc = c0 + wn * 64 + nf * 8 + 2 * tg + (q & 1);
                    float v = acc[mf][nf][q];
                    if (Lsum) { v = f2tf_f(__expf(v * escale)); rowsum[mf][q >> 1] += v; }
                    if (bias)  v += bias[cc];
                    if (resid) v += resid[(size_t)rr * ldres + cc];
                    if (Ldiv)  v *= __frcp_rn(Ldiv[(size_t)z * L_ + rr]);
                    if (relu)  v = fmaxf(v, 0.f);
                    if (round_out) v = f2tf_f(v);
                    C[(size_t)rr * ldc + cc] = v;
                }
        if (Lsum) {
#pragma unroll
            for (int mf = 0; mf < 2; mf++)
#pragma unroll
                for (int qh = 0; qh < 2; qh++) {
                    float s = rowsum[mf][qh];
                    s += __shfl_xor_sync(~0u, s, 1);
                    s += __shfl_xor_sync(~0u, s, 2);
                    if (tg == 0)
                        atomicAdd(&Lsum[(size_t)z * L_ + r0 + wm * 32 + mf * 16 + g + qh * 8], s);
                }
        }
        __syncthreads();
    }
#endif
}

// --------------------------- merged tf32 rounding pass -----------------------
__global__ void cvt_all_kernel(const float4* x, float4* xr,
                               const float4* wq, float4* wqr,
                               const float4* wk, float4* wkr,
                               const float4* wv, float4* wvr,
                               const float4* wu, float4* wur,
                               const float4* w1, float4* w1r,
                               const float4* w2, float4* w2r)
{
    const int total = 524288 + 4 * 131072 + 2 * 65536;   // 1179648 float4
    for (int i = blockIdx.x * blockDim.x + threadIdx.x; i < total; i += gridDim.x * blockDim.x) {
        const float4* in; float4* out; int j = i;
        if (j < 524288) { in = x; out = xr; }
        else if ((j -= 524288) < 131072) { in = wq; out = wqr; }
        else if ((j -= 131072) < 131072) { in = wk; out = wkr; }
        else if ((j -= 131072) < 131072) { in = wv; out = wvr; }
        else if ((j -= 131072) < 131072) { in = wu; out = wur; }
        else if ((j -= 131072) < 65536)  { in = w1; out = w1r; }
        else { j -= 65536; in = w2; out = w2r; }
        float4 v = in[j];
        v.x = f2tf_f(v.x); v.y = f2tf_f(v.y); v.z = f2tf_f(v.z); v.w = f2tf_f(v.w);
        out[j] = v;
    }
}

// --------------------------- V transpose: Vt[z][e][j] = V[b, j, h*256+e] -----
__global__ void transpose_v(const float* __restrict__ V, float* __restrict__ Vt)
{
    __shared__ float t[32][33];
    const int z = blockIdx.z, b = z >> 3, h = z & 7;
    const int j0 = blockIdx.x * 32, e0 = blockIdx.y * 32;
    const int tx = threadIdx.x, ty = threadIdx.y;
#pragma unroll
    for (int k = 0; k < 4; k++)
        t[ty + k * 8][tx] = V[(size_t)(b * L_ + j0 + ty + k * 8) * HD_ + h * D_ + e0 + tx];
    __syncthreads();
#pragma unroll
    for (int k = 0; k < 4; k++)
        Vt[(size_t)z * D_ * L_ + (size_t)(e0 + ty + k * 8) * L_ + j0 + tx] = t[tx][ty + k * 8];
}

// --------------------------- layernorm over d=256 ----------------------------
__global__ void ln_kernel(const float* __restrict__ in, float* __restrict__ out,
                          float* __restrict__ out_r,
                          const float* __restrict__ g, const float* __restrict__ be)
{
    __shared__ float r1[8], r2[8];
    const int row = blockIdx.x, t = threadIdx.x;
    const float v = in[(size_t)row * D_ + t];
    float s = v, q = v * v;
#pragma unroll
    for (int o = 16; o; o >>= 1) {
        s += __shfl_xor_sync(~0u, s, o);
        q += __shfl_xor_sync(~0u, q, o);
    }
    if ((t & 31) == 0) { r1[t >> 5] = s; r2[t >> 5] = q; }
    __syncthreads();
    float S = 0.f, Q = 0.f;
#pragma unroll
    for (int i = 0; i < 8; i++) { S += r1[i]; Q += r2[i]; }
    const float mean = S * (1.f / D_);
    const float var = Q * (1.f / D_) - mean * mean;
    const float y = (v - mean) * rsqrtf(var + EPS_) * g[t] + be[t];
    out[(size_t)row * D_ + t] = y;
    if (out_r) out_r[(size_t)row * D_ + t] = f2tf_f(y);
}

// --------------------------- host: tensormap encoding ------------------------
typedef CUresult (*EncFn)(CUtensorMap*, CUtensorMapDataType, cuuint32_t, void*,
                          const cuuint64_t*, const cuuint64_t*, const cuuint32_t*,
                          const cuuint32_t*, CUtensorMapInterleave, CUtensorMapSwizzle,
                          CUtensorMapL2promotion, CUtensorMapFloatOOBfill);

static EncFn get_enc() {
    static EncFn fn = nullptr;
    if (!fn) {
        void* p = nullptr;
        cudaDriverEntryPointQueryResult st;
        cudaGetDriverEntryPoint("cuTensorMapEncodeTiled", &p, cudaEnableDefault, &st);
        fn = (EncFn)p;
    }
    return fn;
}

static void mk3d(CUtensorMap* tm, void* ptr,
                 unsigned long long d0, unsigned long long d1, unsigned long long d2,
                 unsigned long long s1B, unsigned long long s2B,
                 unsigned b0, unsigned b1)
{
    cuuint64_t dims[3] = {d0, d1, d2};
    cuuint64_t strides[2] = {s1B, s2B};
    cuuint32_t box[3] = {b0, b1, 1};
    cuuint32_t es[3] = {1, 1, 1};
    get_enc()(tm, CU_TENSOR_MAP_DATA_TYPE_FLOAT32, 3, ptr, dims, strides, box, es,
              CU_TENSOR_MAP_INTERLEAVE_NONE, CU_TENSOR_MAP_SWIZZLE_128B,
              CU_TENSOR_MAP_L2_PROMOTION_L2_128B, CU_TENSOR_MAP_FLOAT_OOB_FILL_NONE);
}

// --------------------------- launch ------------------------------------------
extern "C" void kernel_launch(void* const* d_in, const int* in_sizes, int n_in,
                              void* d_out, int out_size)
{
    const float* x   = (const float*)d_in[0];
    const float* Wq  = (const float*)d_in[1];
    const float* Wk  = (const float*)d_in[2];
    const float* Wv  = (const float*)d_in[3];
    const float* Wu  = (const float*)d_in[4];
    const float* bu  = (const float*)d_in[5];
    const float* W1  = (const float*)d_in[6];
    const float* b1  = (const float*)d_in[7];
    const float* W2  = (const float*)d_in[8];
    const float* b2  = (const float*)d_in[9];
    const float* g1  = (const float*)d_in[10];
    const float* be1 = (const float*)d_in[11];
    const float* g2  = (const float*)d_in[12];
    const float* be2 = (const float*)d_in[13];
    float* out = (float*)d_out;

    float *Qb, *Kb, *Vb, *Vt, *S, *O, *R1, *Z1, *Z1r, *Hb, *F, *Lb;
    float *xr, *Wqr, *Wkr, *Wvr, *Wur, *W1r, *W2r;
    cudaGetSymbolAddress((void**)&Qb, g_Q);
    cudaGetSymbolAddress((void**)&Kb, g_K);
    cudaGetSymbolAddress((void**)&Vb, g_V);
    cudaGetSymbolAddress((void**)&Vt, g_Vt);
    cudaGetSymbolAddress((void**)&S,  g_S);
    cudaGetSymbolAddress((void**)&O,  g_O);
    cudaGetSymbolAddress((void**)&R1, g_R1);
    cudaGetSymbolAddress((void**)&Z1, g_Z1);
    cudaGetSymbolAddress((void**)&Z1r, g_Z1r);
    cudaGetSymbolAddress((void**)&Hb, g_Hb);
    cudaGetSymbolAddress((void**)&F,  g_F);
    cudaGetSymbolAddress((void**)&Lb, g_L);
    cudaGetSymbolAddress((void**)&xr,  g_xr);
    cudaGetSymbolAddress((void**)&Wqr, g_Wqr);
    cudaGetSymbolAddress((void**)&Wkr, g_Wkr);
    cudaGetSymbolAddress((void**)&Wvr, g_Wvr);
    cudaGetSymbolAddress((void**)&Wur, g_Wur);
    cudaGetSymbolAddress((void**)&W1r, g_W1r);
    cudaGetSymbolAddress((void**)&W2r, g_W2r);

    // ---- tensor maps (host structs, passed by value; no allocations)
    CUtensorMap tXr, tWq, tWk, tWv, tQ, tK, tS, tVt, tO, tWu, tZ1, tW1, tHb, tW2;
    const unsigned long long F4 = sizeof(float);
    mk3d(&tXr, xr,  D_,  ROWS_, 1, D_ * F4,  0,                 32, 256);
    mk3d(&tWq, Wqr, D_,  HD_,   1, D_ * F4,  0,                 32, 256);
    mk3d(&tWk, Wkr, D_,  HD_,   1, D_ * F4,  0,                 32, 256);
    mk3d(&tWv, Wvr, D_,  HD_,   1, D_ * F4,  0,                 32, 256);
    mk3d(&tQ,  Qb,  HD_, L_,    B_, (unsigned long long)HD_ * F4, (unsigned long long)L_ * HD_ * F4, 32, 256);
    mk3d(&tK,  Kb,  HD_, L_,    B_, (unsigned long long)HD_ * F4, (unsigned long long)L_ * HD_ * F4, 32, 256);
    mk3d(&tS,  S,   L_,  L_,    B_ * H_, (unsigned long long)L_ * F4, (unsigned long long)L_ * L_ * F4, 32, 256);
    mk3d(&tVt, Vt,  L_,  D_,    B_ * H_, (unsigned long long)L_ * F4, (unsigned long long)D_ * L_ * F4, 32, 256);
    mk3d(&tO,  O,   HD_, ROWS_, 1, (unsigned long long)HD_ * F4, 0,  32, 128);
    mk3d(&tWu, Wur, HD_, D_,    1, (unsigned long long)HD_ * F4, 0,  32, 256);
    mk3d(&tZ1, Z1r, D_,  ROWS_, 1, D_ * F4, 0,                  32, 256);
    mk3d(&tW1, W1r, D_,  F_,    1, D_ * F4, 0,                  32, 256);
    mk3d(&tHb, Hb,  F_,  ROWS_, 1, (unsigned long long)F_ * F4, 0,  32, 128);
    mk3d(&tW2, W2r, F_,  D_,    1, (unsigned long long)F_ * F4, 0,  32, 256);

    constexpr int SMEM22 = 3 * 65536 + 64;   // <2,256>
    constexpr int SMEM12 = 3 * 49152 + 64;   // <1,256>
    cudaFuncSetAttribute(gemm_tc<2,256>, cudaFuncAttributeMaxDynamicSharedMemorySize, SMEM22);
    cudaFuncSetAttribute(gemm_tc<1,256>, cudaFuncAttributeMaxDynamicSharedMemorySize, SMEM12);

    cvt_all_kernel<<<1184, 256>>>((const float4*)x,  (float4*)xr,
                                  (const float4*)Wq, (float4*)Wqr,
                                  (const float4*)Wk, (float4*)Wkr,
                                  (const float4*)Wv, (float4*)Wvr,
                                  (const float4*)Wu, (float4*)Wur,
                                  (const float4*)W1, (float4*)W1r,
                                  (const float4*)W2, (float4*)W2r);

    const long long LL2 = (long long)L_ * L_;

    // QKV projections
    gemm_tc<2,256><<<dim3(HD_/256, ROWS_/256, 1), 256, SMEM22>>>(tXr, tWq, xr, Wqr, Qb,
        D_, D_, D_, HD_, 0,0,0,0,0,0, 0, 0,
        nullptr, nullptr, 0, 0, 1, 0.f, nullptr, nullptr);
    gemm_tc<2,256><<<dim3(HD_/256, ROWS_/256, 1), 256, SMEM22>>>(tXr, tWk, xr, Wkr, Kb,
        D_, D_, D_, HD_, 0,0,0,0,0,0, 0, 0,
        nullptr, nullptr, 0, 0, 1, 0.f, nullptr, nullptr);
    gemm_tc<2,256><<<dim3(HD_/256, ROWS_/256, 1), 256, SMEM22>>>(tXr, tWv, xr, Wvr, Vb,
        D_, D_, D_, HD_, 0,0,0,0,0,0, 0, 0,
        nullptr, nullptr, 0, 0, 1, 0.f, nullptr, nullptr);

    transpose_v<<<dim3(L_/32, D_/32, B_*H_), dim3(32, 8)>>>(Vb, Vt);

    // scores + fused exp & row-sum
    cudaMemsetAsync(Lb, 0, (size_t)B_ * H_ * L_ * sizeof(float));
    gemm_tc<2,256><<<dim3(L_/256, L_/256, B_*H_), 256, SMEM22>>>(tQ, tK, Qb, Kb, S,
        D_, HD_, HD_, L_,
        (long long)L_*HD_, D_, (long long)L_*HD_, D_, 8*LL2, LL2, 3, 256,
        nullptr, nullptr, 0, 0, 0, 0.0625f, Lb, nullptr);

    // PV: O = (S @ Vt^T) / l
    gemm_tc<2,256><<<dim3(D_/256, L_/256, B_*H_), 256, SMEM22>>>(tS, tVt, S, Vt, O,
        L_, L_, L_, HD_,
        8*LL2, LL2, 8LL*D_*L_, (long long)D_*L_, (long long)L_*HD_, D_, 0, 0,
        nullptr, nullptr, 0, 0, 1, 0.f, nullptr, Lb);

    // output projection + bias + residual(x)
    gemm_tc<1,256><<<dim3(D_/256, ROWS_/128, 1), 256, SMEM12>>>(tO, tWu, O, Wur, R1,
        HD_, HD_, HD_, D_, 0,0,0,0,0,0, 0, 0,
        bu, x, D_, 0, 0, 0.f, nullptr, nullptr);
    ln_kernel<<<ROWS_, 256>>>(R1, Z1, Z1r, g1, be1);

    // FFN
    gemm_tc<2,256><<<dim3(F_/256, ROWS_/256, 1), 256, SMEM22>>>(tZ1, tW1, Z1r, W1r, Hb,
        D_, D_, D_, F_, 0,0,0,0,0,0, 0, 0,
        b1, nullptr, 0, 1, 1, 0.f, nullptr, nullptr);
    gemm_tc<1,256><<<dim3(D_/256, ROWS_/128, 1), 256, SMEM12>>>(tHb, tW2, Hb, W2r, F,
        F_, F_, F_, D_, 0,0,0,0,0,0, 0, 0,
        b2, Z1, D_, 0, 0, 0.f, nullptr, nullptr);
    ln_kernel<<<ROWS_, 256>>>(F, out, nullptr, g2, be2);
}

// round 12
// speedup vs baseline: 1.4368x; 1.1517x over previous
#include <cuda_runtime.h>
#include <cuda.h>
#include <cstdint>

#define B_  8
#define L_  1024
#define D_  256
#define H_  8
#define HD_ 2048
#define F_  1024
#define ROWS_ (B_*L_)
#define EPS_ 1e-5f

#if defined(__CUDA_ARCH_FEAT_SM103_ALL) || defined(__CUDA_ARCH_FEAT_SM100_ALL)
#define TC_OK 1
#else
#define TC_OK 0
#endif

// --------------------------- scratch (device globals) ------------------------
__device__ float g_Q[(size_t)ROWS_ * HD_];
__device__ float g_K[(size_t)ROWS_ * HD_];
__device__ float g_V[(size_t)ROWS_ * HD_];
__device__ float g_Vt[(size_t)B_ * H_ * D_ * L_];
__device__ float g_S[(size_t)B_ * H_ * L_ * L_];
__device__ float g_O[(size_t)ROWS_ * HD_];
__device__ float g_R1[(size_t)ROWS_ * D_];
__device__ float g_Z1[(size_t)ROWS_ * D_];
__device__ float g_Z1r[(size_t)ROWS_ * D_];
__device__ float g_Hb[(size_t)ROWS_ * F_];
__device__ float g_F[(size_t)ROWS_ * D_];
__device__ float g_L[(size_t)B_ * H_ * L_];
__device__ float g_xr[(size_t)ROWS_ * D_];
__device__ float g_Wqr[(size_t)HD_ * D_];
__device__ float g_Wkr[(size_t)HD_ * D_];
__device__ float g_Wvr[(size_t)HD_ * D_];
__device__ float g_Wur[(size_t)D_ * HD_];
__device__ float g_W1r[(size_t)F_ * D_];
__device__ float g_W2r[(size_t)D_ * F_];

// --------------------------- common helpers ----------------------------------
__device__ __forceinline__ uint32_t f2tf(float f) {
    uint32_t u; asm("cvt.rna.tf32.f32 %0, %1;" : "=r"(u) : "f"(f)); return u;
}
__device__ __forceinline__ float f2tf_f(float f) { return __uint_as_float(f2tf(f)); }

__device__ __forceinline__ void cp16(uint32_t saddr, const void* gptr) {
    asm volatile("cp.async.cg.shared.global [%0], [%1], 16;" :: "r"(saddr), "l"(gptr));
}
__device__ __forceinline__ void cp_commit() { asm volatile("cp.async.commit_group;"); }
__device__ __forceinline__ void cp_wait1()  { asm volatile("cp.async.wait_group 1;"); }
__device__ __forceinline__ void cp_wait0()  { asm volatile("cp.async.wait_group 0;"); }

__device__ __forceinline__ void mma8(float* c, const uint32_t* a, const uint32_t* b) {
    asm volatile(
        "mma.sync.aligned.m16n8k8.row.col.f32.tf32.tf32.f32 "
        "{%0,%1,%2,%3}, {%4,%5,%6,%7}, {%8,%9}, {%0,%1,%2,%3};"
        : "+f"(c[0]), "+f"(c[1]), "+f"(c[2]), "+f"(c[3])
        : "r"(a[0]), "r"(a[1]), "r"(a[2]), "r"(a[3]), "r"(b[0]), "r"(b[1]));
}

#if TC_OK
// --------------------------- tcgen05/TMA helpers (sm_103a pass only) ---------
__device__ __forceinline__ bool elect1() {
    uint32_t p;
    asm volatile("{\n\t.reg .pred p;\n\telect.sync _|p, 0xFFFFFFFF;\n\tselp.b32 %0,1,0,p;\n\t}" : "=r"(p));
    return p != 0;
}
__device__ __forceinline__ void mbar_init(uint32_t a, uint32_t cnt) {
    asm volatile("mbarrier.init.shared.b64 [%0], %1;" :: "r"(a), "r"(cnt) : "memory");
}
__device__ __forceinline__ void mbar_wait(uint32_t a, uint32_t parity) {
    asm volatile(
        "{\n\t.reg .pred P;\n\t"
        "WL%=:\n\t"
        "mbarrier.try_wait.parity.acquire.cta.shared::cta.b64 P, [%0], %1, 0x989680;\n\t"
        "@P bra WD%=;\n\t"
        "bra WL%=;\n\t"
        "WD%=:\n\t}"
        :: "r"(a), "r"(parity) : "memory");
}
__device__ __forceinline__ void mbar_expect_tx(uint32_t a, uint32_t bytes) {
    asm volatile("mbarrier.arrive.expect_tx.shared.b64 _, [%0], %1;"
                 :: "r"(a), "r"(bytes) : "memory");
}
__device__ __forceinline__ void tma3d(uint32_t smem, const void* tm,
                                      int c0, int c1, int c2, uint32_t mbar) {
    asm volatile(
        "cp.async.bulk.tensor.3d.shared::cta.global.tile.mbarrier::complete_tx::bytes "
        "[%0], [%1, {%2, %3, %4}], [%5];"
        :: "r"(smem), "l"(tm), "r"(c0), "r"(c1), "r"(c2), "r"(mbar) : "memory");
}
__device__ __forceinline__ void tc_fence_after() {
    asm volatile("tcgen05.fence::after_thread_sync;" ::: "memory");
}
__device__ __forceinline__ void tcalloc(uint32_t smem_addr, uint32_t ncols) {
    asm volatile("tcgen05.alloc.cta_group::1.sync.aligned.shared::cta.b32 [%0], %1;"
                 :: "r"(smem_addr), "r"(ncols) : "memory");
}
__device__ __forceinline__ void tcdealloc(uint32_t tmem, uint32_t ncols) {
    asm volatile("tcgen05.dealloc.cta_group::1.sync.aligned.b32 %0, %1;" :: "r"(tmem), "r"(ncols));
}
__device__ __forceinline__ void tcrelinquish() {
    asm volatile("tcgen05.relinquish_alloc_permit.cta_group::1.sync.aligned;");
}
__device__ __forceinline__ void tc_commit(uint32_t mbar) {
    asm volatile("tcgen05.commit.cta_group::1.mbarrier::arrive::one.shared::cluster.b64 [%0];"
                 :: "r"(mbar) : "memory");
}
__device__ __forceinline__ void wait_ld() {
    asm volatile("tcgen05.wait::ld.sync.aligned;" ::: "memory");
}
__device__ __forceinline__ void mma_tf32_ss(uint32_t d, uint64_t ad, uint64_t bd,
                                            uint32_t idesc, uint32_t en) {
    asm volatile(
        "{\n\t.reg .pred p;\n\tsetp.ne.u32 p, %4, 0;\n\t"
        "tcgen05.mma.cta_group::1.kind::tf32 [%0], %1, %2, %3, {%5,%5,%5,%5}, p;\n\t}"
        :: "r"(d), "l"(ad), "l"(bd), "r"(idesc), "r"(en), "r"(0u) : "memory");
}
__device__ __forceinline__ void ldtm32(uint32_t* r, uint32_t a) {
    asm volatile(
        "tcgen05.ld.sync.aligned.32x32b.x32.b32 "
        "{%0,%1,%2,%3,%4,%5,%6,%7,%8,%9,%10,%11,%12,%13,%14,%15,"
        "%16,%17,%18,%19,%20,%21,%22,%23,%24,%25,%26,%27,%28,%29,%30,%31}, [%32];"
        : "=r"(r[0]), "=r"(r[1]), "=r"(r[2]), "=r"(r[3]),
          "=r"(r[4]), "=r"(r[5]), "=r"(r[6]), "=r"(r[7]),
          "=r"(r[8]), "=r"(r[9]), "=r"(r[10]), "=r"(r[11]),
          "=r"(r[12]), "=r"(r[13]), "=r"(r[14]), "=r"(r[15]),
          "=r"(r[16]), "=r"(r[17]), "=r"(r[18]), "=r"(r[19]),
          "=r"(r[20]), "=r"(r[21]), "=r"(r[22]), "=r"(r[23]),
          "=r"(r[24]), "=r"(r[25]), "=r"(r[26]), "=r"(r[27]),
          "=r"(r[28]), "=r"(r[29]), "=r"(r[30]), "=r"(r[31])
        : "r"(a));
}
static constexpr uint64_t DESC_BASE =
    (uint64_t(2) << 61) | (uint64_t(1) << 46) | (uint64_t(64) << 32) | (uint64_t(1) << 16);
__device__ __forceinline__ uint64_t mk_desc(uint32_t a) {
    return DESC_BASE | ((uint64_t)(a >> 4) & 0x3FFFull);
}
#endif // TC_OK

// ============================================================================
// GEMM: C = A @ B^T (K-major, tf32-prerounded), CTA tile 128 x NT, KC=32,
// 2-stage mbarrier pipeline, 2 CTAs/SM. TMA producer + warp-1 MMA issuer.
// Batched coords: zA = z>>zsh, inner offset = (z & ((1<<zsh)-1))*koMul.
// ============================================================================
template<int MH, int NT>
__global__ __launch_bounds__(256, 2)
void gemm_tc(const __grid_constant__ CUtensorMap tmA,
             const __grid_constant__ CUtensorMap tmB,
             const float* __restrict__ A, const float* __restrict__ Bm,
             float* __restrict__ C, int K, int lda, int ldb, int ldc,
             long long sA1, long long sA2, long long sB1, long long sB2,
             long long sC1, long long sC2,
             int zsh, int koMul,
             const float* __restrict__ bias, const float* __restrict__ resid, int ldres,
             int relu, int round_out, float escale,
             float* __restrict__ Lsum, const float* __restrict__ Ldiv)
{
    extern __shared__ __align__(1024) uint8_t smraw[];

    const int z = blockIdx.z;
    A  += (size_t)(z >> 3) * sA1 + (size_t)(z & 7) * sA2;
    Bm += (size_t)(z >> 3) * sB1 + (size_t)(z & 7) * sB2;
    C  += (size_t)(z >> 3) * sC1 + (size_t)(z & 7) * sC2;

    const int tid = threadIdx.x, wid = tid >> 5, lane = tid & 31;
    const int row0 = blockIdx.y * (MH * 128);
    const int col0 = blockIdx.x * NT;

#if TC_OK
    constexpr int ABYTES = MH * 16384;
    constexpr int BBYTES = (NT / 128) * 16384;
    constexpr int STGB = ABYTES + BBYTES;
    constexpr int NST = 2;
    constexpr int CTRL = NST * STGB;
    constexpr uint32_t IDESC =
        (1u << 4) | (2u << 7) | (2u << 10) | ((uint32_t)(NT / 8) << 17) | ((uint32_t)(MH * 8) << 24);

    const uint32_t smb = (uint32_t)__cvta_generic_to_shared(smraw);
    const uint32_t tptr = smb + CTRL;
    const uint32_t mbF = smb + CTRL + 8;     // full[0..1]
    const uint32_t mbE = smb + CTRL + 24;    // empty[0..1]
    const uint32_t mbD = smb + CTRL + 40;    // done

    if (wid == 0) tcalloc(tptr, MH * NT);
    if (tid == 0) {
        for (int s = 0; s < NST; ++s) { mbar_init(mbF + 8 * s, 1); mbar_init(mbE + 8 * s, 1); }
        mbar_init(mbD, 1);
    }
    __syncthreads();
    uint32_t tmem;
    asm volatile("ld.shared.b32 %0, [%1];" : "=r"(tmem) : "r"(tptr));

    const int T = K >> 5;
    const int zA = z >> zsh;
    const int ko = (z & ((1 << zsh) - 1)) * koMul;

    if (wid == 0) {
        if (elect1()) {
            // ---- TMA producer
            int eph[NST] = {1, 1};
            int s = 0;
            for (int c = 0; c < T; ++c) {
                mbar_wait(mbE + 8 * s, eph[s]); eph[s] ^= 1;
                const uint32_t bA = smb + s * STGB;
                const uint32_t fb = mbF + 8 * s;
                const int kc = ko + (c << 5);
                mbar_expect_tx(fb, STGB);
                tma3d(bA, &tmA, kc, row0, zA, fb);
                tma3d(bA + ABYTES, &tmB, kc, col0, zA, fb);
                s ^= 1;
            }
        }
    } else if (wid == 1) {
        if (elect1()) {
            // ---- MMA issuer
            int fph[NST] = {0, 0};
            int s = 0;
            for (int c = 0; c < T; ++c) {
                mbar_wait(mbF + 8 * s, fph[s]); fph[s] ^= 1;
                const uint32_t bA = smb + s * STGB, bB = bA + ABYTES;
                const uint64_t bd = mk_desc(bB);
#pragma unroll
                for (int m = 0; m < MH; ++m) {
                    const uint64_t ad = mk_desc(bA + m * 16384);
#pragma unroll
                    for (int k8 = 0; k8 < 4; ++k8)
                        mma_tf32_ss(tmem + m * NT, ad + 2 * k8, bd + 2 * k8, IDESC,
                                    (c > 0 || k8 > 0) ? 1u : 0u);
                }
                tc_commit(mbE + 8 * s);
                s ^= 1;
            }
            tc_commit(mbD);
        }
    }

    mbar_wait(mbD, 0);
    tc_fence_after();
    __syncthreads();

    // ---- vectorized epilogue: TMEM -> regs -> smem(9-f4 pitch) -> STG.128
    // MH=1: all 8 warps on acc0; warps 0-3 cols [0,NT/2), 4-7 [NT/2,NT).
    if (wid < 8) {
        const int sw = wid & 3;
        const int hsel = (MH == 2) ? (wid >> 2) : 0;
        const int cb0  = (MH == 2) ? 0 : (wid >> 2) * (NT / 64);
        const int cbN  = (MH == 2) ? (NT / 32) : (NT / 64);
        float4* wsm4 = (float4*)smraw + wid * (32 * 9);
        const int rloc = hsel * 128 + sw * 32 + lane;
        float rowsum = 0.f;
#pragma unroll 1
        for (int ci = 0; ci < cbN; ++ci) {
            const int cb = cb0 + ci;
            uint32_t rg[32];
            ldtm32(rg, tmem + hsel * NT + cb * 32);
            wait_ld();
            if (Lsum) {
#pragma unroll
                for (int j = 0; j < 32; ++j) {
                    float v = f2tf_f(__expf(__uint_as_float(rg[j]) * escale));
                    rowsum += v;
                    rg[j] = __float_as_uint(v);
                }
            }
            __syncwarp();
#pragma unroll
            for (int jq = 0; jq < 8; ++jq) {
                float4 v4 = make_float4(__uint_as_float(rg[jq * 4 + 0]),
                                        __uint_as_float(rg[jq * 4 + 1]),
                                        __uint_as_float(rg[jq * 4 + 2]),
                                        __uint_as_float(rg[jq * 4 + 3]));
                wsm4[lane * 9 + jq] = v4;
            }
            __syncwarp();
            const int cq = lane & 7;
            const int rsub = lane >> 3;
#pragma unroll 1
            for (int it = 0; it < 8; ++it) {
                const int r = it * 4 + rsub;
                float4 v = wsm4[r * 9 + cq];
                const int orow = row0 + hsel * 128 + sw * 32 + r;
                const int ocol = col0 + cb * 32 + cq * 4;
                if (bias) {
                    const float4 bv = *(const float4*)&bias[ocol];
                    v.x += bv.x; v.y += bv.y; v.z += bv.z; v.w += bv.w;
                }
                if (resid) {
                    const float4 rv = *(const float4*)&resid[(size_t)orow * ldres + ocol];
                    v.x += rv.x; v.y += rv.y; v.z += rv.z; v.w += rv.w;
                }
                if (Ldiv) {
                    const float inv = __frcp_rn(Ldiv[(size_t)z * L_ + orow]);
                    v.x *= inv; v.y *= inv; v.z *= inv; v.w *= inv;
                }
                if (relu) {
                    v.x = fmaxf(v.x, 0.f); v.y = fmaxf(v.y, 0.f);
                    v.z = fmaxf(v.z, 0.f); v.w = fmaxf(v.w, 0.f);
                }
                if (round_out) {
                    v.x = f2tf_f(v.x); v.y = f2tf_f(v.y);
                    v.z = f2tf_f(v.z); v.w = f2tf_f(v.w);
                }
                *(float4*)&C[(size_t)orow * ldc + ocol] = v;
            }
            __syncwarp();
        }
        if (Lsum) atomicAdd(&Lsum[(size_t)z * L_ + row0 + rloc], rowsum);
    }
    __syncthreads();
    if (wid == 0) { tcrelinquish(); tcdealloc(tmem, MH * NT); }

#else  // ----------------- mma.sync fallback (compute_103 pass only) ---------
    constexpr int ASTG = 128 * 36, STG2 = 2 * ASTG;
    uint32_t* sm = (uint32_t*)smraw;
    const int wm = wid & 3, wn = wid >> 2;
    const int g = lane >> 2, tg = lane & 3;
    const uint32_t smb = (uint32_t)__cvta_generic_to_shared(sm);

    for (int mh = 0; mh < MH; ++mh)
    for (int nh = 0; nh < NT / 128; ++nh) {
        const int r0 = row0 + mh * 128, c0 = col0 + nh * 128;
        float acc[2][8][4] = {};

        auto stage = [&](int st, int k0) {
#pragma unroll
            for (int i = 0; i < 4; i++) {
                const int s = tid + i * 256;
                const int r = s >> 3, kq = s & 7;
                const uint32_t baseA = smb + (uint32_t)(st * STG2) * 4u;
                const uint32_t baseB = baseA + (uint32_t)ASTG * 4u;
                cp16(baseA + (uint32_t)(r * 36 + kq * 4) * 4u, A + (size_t)(r0 + r) * lda + k0 + kq * 4);
                cp16(baseB + (uint32_t)(r * 36 + kq * 4) * 4u, Bm + (size_t)(c0 + r) * ldb + k0 + kq * 4);
            }
        };

        const int T = K >> 5;
        stage(0, 0); cp_commit();
        for (int t = 0; t < T; ++t) {
            if (t + 1 < T) { stage((t + 1) & 1, (t + 1) << 5); cp_commit(); cp_wait1(); }
            else           { cp_wait0(); }
            __syncthreads();
            const uint32_t* As = sm + (t & 1) * STG2;
            const uint32_t* Bs = As + ASTG;
#pragma unroll
            for (int ks = 0; ks < 32; ks += 8) {
                uint32_t a[2][4], b[8][2];
#pragma unroll
                for (int mf = 0; mf < 2; mf++) {
                    const int m0 = wm * 32 + mf * 16;
                    a[mf][0] = As[(m0 + g) * 36 + ks + tg];
                    a[mf][1] = As[(m0 + 8 + g) * 36 + ks + tg];
                    a[mf][2] = As[(m0 + g) * 36 + ks + 4 + tg];
                    a[mf][3] = As[(m0 + 8 + g) * 36 + ks + 4 + tg];
                }
#pragma unroll
                for (int nf = 0; nf < 8; nf++) {
                    const int n0 = wn * 64 + nf * 8;
                    b[nf][0] = Bs[(n0 + g) * 36 + ks + tg];
                    b[nf][1] = Bs[(n0 + g) * 36 + ks + 4 + tg];
                }
#pragma unroll
                for (int mf = 0; mf < 2; mf++)
#pragma unroll
                    for (int nf = 0; nf < 8; nf++)
                        mma8(acc[mf][nf], a[mf], b[nf]);
            }
            __syncthreads();
        }

        float rowsum[2][2] = {};
#pragma unroll
        for (int mf = 0; mf < 2; mf++)
#pragma unroll
            for (int nf = 0; nf < 8; nf++)
#pragma unroll
                for (int q = 0; q < 4; q++) {
                    const int rr = r0 + wm * 32 + mf * 16 + g + (q >> 1) * 8;
                    const int cc = c0 + wn * 64 + nf * 8 + 2 * tg + (q & 1);
                    float v = acc[mf][nf][q];
                    if (Lsum) { v = f2tf_f(__expf(v * escale)); rowsum[mf][q >> 1] += v; }
                    if (bias)  v += bias[cc];
                    if (resid) v += resid[(size_t)rr * ldres + cc];
                    if (Ldiv)  v *= __frcp_rn(Ldiv[(size_t)z * L_ + rr]);
                    if (relu)  v = fmaxf(v, 0.f);
                    if (round_out) v = f2tf_f(v);
                    C[(size_t)rr * ldc + cc] = v;
                }
        if (Lsum) {
#pragma unroll
            for (int mf = 0; mf < 2; mf++)
#pragma unroll
                for (int qh = 0; qh < 2; qh++) {
                    float s = rowsum[mf][qh];
                    s += __shfl_xor_sync(~0u, s, 1);
                    s += __shfl_xor_sync(~0u, s, 2);
                    if (tg == 0)
                        atomicAdd(&Lsum[(size_t)z * L_ + r0 + wm * 32 + mf * 16 + g + qh * 8], s);
                }
        }
        __syncthreads();
    }
#endif
}

// --------------------------- merged tf32 rounding pass -----------------------
__global__ void cvt_all_kernel(const float4* x, float4* xr,
                               const float4* wq, float4* wqr,
                               const float4* wk, float4* wkr,
                               const float4* wv, float4* wvr,
                               const float4* wu, float4* wur,
                               const float4* w1, float4* w1r,
                               const float4* w2, float4* w2r)
{
    const int total = 524288 + 4 * 131072 + 2 * 65536;   // 1179648 float4
    for (int i = blockIdx.x * blockDim.x + threadIdx.x; i < total; i += gridDim.x * blockDim.x) {
        const float4* in; float4* out; int j = i;
        if (j < 524288) { in = x; out = xr; }
        else if ((j -= 524288) < 131072) { in = wq; out = wqr; }
        else if ((j -= 131072) < 131072) { in = wk; out = wkr; }
        else if ((j -= 131072) < 131072) { in = wv; out = wvr; }
        else if ((j -= 131072) < 131072) { in = wu; out = wur; }
        else if ((j -= 131072) < 65536)  { in = w1; out = w1r; }
        else { j -= 65536; in = w2; out = w2r; }
        float4 v = in[j];
        v.x = f2tf_f(v.x); v.y = f2tf_f(v.y); v.z = f2tf_f(v.z); v.w = f2tf_f(v.w);
        out[j] = v;
    }
}

// --------------------------- V transpose: Vt[z][e][j] = V[b, j, h*256+e] -----
__global__ void transpose_v(const float* __restrict__ V, float* __restrict__ Vt)
{
    __shared__ float t[32][33];
    const int z = blockIdx.z, b = z >> 3, h = z & 7;
    const int j0 = blockIdx.x * 32, e0 = blockIdx.y * 32;
    const int tx = threadIdx.x, ty = threadIdx.y;
#pragma unroll
    for (int k = 0; k < 4; k++)
        t[ty + k * 8][tx] = V[(size_t)(b * L_ + j0 + ty + k * 8) * HD_ + h * D_ + e0 + tx];
    __syncthreads();
#pragma unroll
    for (int k = 0; k < 4; k++)
        Vt[(size_t)z * D_ * L_ + (size_t)(e0 + ty + k * 8) * L_ + j0 + tx] = t[tx][ty + k * 8];
}

// --------------------------- layernorm over d=256 ----------------------------
__global__ void ln_kernel(const float* __restrict__ in, float* __restrict__ out,
                          float* __restrict__ out_r,
                          const float* __restrict__ g, const float* __restrict__ be)
{
    __shared__ float r1[8], r2[8];
    const int row = blockIdx.x, t = threadIdx.x;
    const float v = in[(size_t)row * D_ + t];
    float s = v, q = v * v;
#pragma unroll
    for (int o = 16; o; o >>= 1) {
        s += __shfl_xor_sync(~0u, s, o);
        q += __shfl_xor_sync(~0u, q, o);
    }
    if ((t & 31) == 0) { r1[t >> 5] = s; r2[t >> 5] = q; }
    __syncthreads();
    float S = 0.f, Q = 0.f;
#pragma unroll
    for (int i = 0; i < 8; i++) { S += r1[i]; Q += r2[i]; }
    const float mean = S * (1.f / D_);
    const float var = Q * (1.f / D_) - mean * mean;
    const float y = (v - mean) * rsqrtf(var + EPS_) * g[t] + be[t];
    out[(size_t)row * D_ + t] = y;
    if (out_r) out_r[(size_t)row * D_ + t] = f2tf_f(y);
}

// --------------------------- host: tensormap encoding ------------------------
typedef CUresult (*EncFn)(CUtensorMap*, CUtensorMapDataType, cuuint32_t, void*,
                          const cuuint64_t*, const cuuint64_t*, const cuuint32_t*,
                          const cuuint32_t*, CUtensorMapInterleave, CUtensorMapSwizzle,
                          CUtensorMapL2promotion, CUtensorMapFloatOOBfill);

static EncFn get_enc() {
    static EncFn fn = nullptr;
    if (!fn) {
        void* p = nullptr;
        cudaDriverEntryPointQueryResult st;
        cudaGetDriverEntryPoint("cuTensorMapEncodeTiled", &p, cudaEnableDefault, &st);
        fn = (EncFn)p;
    }
    return fn;
}

static void mk3d(CUtensorMap* tm, void* ptr,
                 unsigned long long d0, unsigned long long d1, unsigned long long d2,
                 unsigned long long s1B, unsigned long long s2B,
                 unsigned b0, unsigned b1)
{
    cuuint64_t dims[3] = {d0, d1, d2};
    cuuint64_t strides[2] = {s1B, s2B};
    cuuint32_t box[3] = {b0, b1, 1};
    cuuint32_t es[3] = {1, 1, 1};
    get_enc()(tm, CU_TENSOR_MAP_DATA_TYPE_FLOAT32, 3, ptr, dims, strides, box, es,
              CU_TENSOR_MAP_INTERLEAVE_NONE, CU_TENSOR_MAP_SWIZZLE_128B,
              CU_TENSOR_MAP_L2_PROMOTION_L2_128B, CU_TENSOR_MAP_FLOAT_OOB_FILL_NONE);
}

// --------------------------- launch ------------------------------------------
extern "C" void kernel_launch(void* const* d_in, const int* in_sizes, int n_in,
                              void* d_out, int out_size)
{
    const float* x   = (const float*)d_in[0];
    const float* Wq  = (const float*)d_in[1];
    const float* Wk  = (const float*)d_in[2];
    const float* Wv  = (const float*)d_in[3];
    const float* Wu  = (const float*)d_in[4];
    const float* bu  = (const float*)d_in[5];
    const float* W1  = (const float*)d_in[6];
    const float* b1  = (const float*)d_in[7];
    const float* W2  = (const float*)d_in[8];
    const float* b2  = (const float*)d_in[9];
    const float* g1  = (const float*)d_in[10];
    const float* be1 = (const float*)d_in[11];
    const float* g2  = (const float*)d_in[12];
    const float* be2 = (const float*)d_in[13];
    float* out = (float*)d_out;

    float *Qb, *Kb, *Vb, *Vt, *S, *O, *R1, *Z1, *Z1r, *Hb, *F, *Lb;
    float *xr, *Wqr, *Wkr, *Wvr, *Wur, *W1r, *W2r;
    cudaGetSymbolAddress((void**)&Qb, g_Q);
    cudaGetSymbolAddress((void**)&Kb, g_K);
    cudaGetSymbolAddress((void**)&Vb, g_V);
    cudaGetSymbolAddress((void**)&Vt, g_Vt);
    cudaGetSymbolAddress((void**)&S,  g_S);
    cudaGetSymbolAddress((void**)&O,  g_O);
    cudaGetSymbolAddress((void**)&R1, g_R1);
    cudaGetSymbolAddress((void**)&Z1, g_Z1);
    cudaGetSymbolAddress((void**)&Z1r, g_Z1r);
    cudaGetSymbolAddress((void**)&Hb, g_Hb);
    cudaGetSymbolAddress((void**)&F,  g_F);
    cudaGetSymbolAddress((void**)&Lb, g_L);
    cudaGetSymbolAddress((void**)&xr,  g_xr);
    cudaGetSymbolAddress((void**)&Wqr, g_Wqr);
    cudaGetSymbolAddress((void**)&Wkr, g_Wkr);
    cudaGetSymbolAddress((void**)&Wvr, g_Wvr);
    cudaGetSymbolAddress((void**)&Wur, g_Wur);
    cudaGetSymbolAddress((void**)&W1r, g_W1r);
    cudaGetSymbolAddress((void**)&W2r, g_W2r);

    // ---- tensor maps (host structs, passed by value; no allocations)
    CUtensorMap tXr, tWq, tWk, tWv, tQ, tK, tS, tVt, tO, tWu, tZ1, tW1, tHb, tW2;
    const unsigned long long F4 = sizeof(float);
    // A maps: box (32, 128)
    mk3d(&tXr, xr,  D_,  ROWS_, 1, D_ * F4,  0,                 32, 128);
    mk3d(&tQ,  Qb,  HD_, L_,    B_, (unsigned long long)HD_ * F4, (unsigned long long)L_ * HD_ * F4, 32, 128);
    mk3d(&tS,  S,   L_,  L_,    B_ * H_, (unsigned long long)L_ * F4, (unsigned long long)L_ * L_ * F4, 32, 128);
    mk3d(&tO,  O,   HD_, ROWS_, 1, (unsigned long long)HD_ * F4, 0,  32, 128);
    mk3d(&tZ1, Z1r, D_,  ROWS_, 1, D_ * F4, 0,                  32, 128);
    mk3d(&tHb, Hb,  F_,  ROWS_, 1, (unsigned long long)F_ * F4, 0,  32, 128);
    // B maps: box (32, NT)
    mk3d(&tWq, Wqr, D_,  HD_,   1, D_ * F4,  0,                 32, 256);
    mk3d(&tWk, Wkr, D_,  HD_,   1, D_ * F4,  0,                 32, 256);
    mk3d(&tWv, Wvr, D_,  HD_,   1, D_ * F4,  0,                 32, 256);
    mk3d(&tK,  Kb,  HD_, L_,    B_, (unsigned long long)HD_ * F4, (unsigned long long)L_ * HD_ * F4, 32, 256);
    mk3d(&tVt, Vt,  L_,  D_,    B_ * H_, (unsigned long long)L_ * F4, (unsigned long long)D_ * L_ * F4, 32, 256);
    mk3d(&tWu, Wur, HD_, D_,    1, (unsigned long long)HD_ * F4, 0,  32, 128);
    mk3d(&tW1, W1r, D_,  F_,    1, D_ * F4, 0,                  32, 256);
    mk3d(&tW2, W2r, F_,  D_,    1, (unsigned long long)F_ * F4, 0,  32, 128);

    constexpr int SMEM256 = 2 * 49152 + 64;   // <1,256>: 98368
    constexpr int SMEM128 = 2 * 32768 + 64;   // <1,128>: 65600
    cudaFuncSetAttribute(gemm_tc<1,256>, cudaFuncAttributeMaxDynamicSharedMemorySize, SMEM256);
    cudaFuncSetAttribute(gemm_tc<1,128>, cudaFuncAttributeMaxDynamicSharedMemorySize, SMEM128);

    cvt_all_kernel<<<1184, 256>>>((const float4*)x,  (float4*)xr,
                                  (const float4*)Wq, (float4*)Wqr,
                                  (const float4*)Wk, (float4*)Wkr,
                                  (const float4*)Wv, (float4*)Wvr,
                                  (const float4*)Wu, (float4*)Wur,
                                  (const float4*)W1, (float4*)W1r,
                                  (const float4*)W2, (float4*)W2r);

    const long long LL2 = (long long)L_ * L_;

    // QKV projections: tile 128x256, grid (8, 64)
    gemm_tc<1,256><<<dim3(HD_/256, ROWS_/128, 1), 256, SMEM256>>>(tXr, tWq, xr, Wqr, Qb,
        D_, D_, D_, HD_, 0,0,0,0,0,0, 0, 0,
        nullptr, nullptr, 0, 0, 1, 0.f, nullptr, nullptr);
    gemm_tc<1,256><<<dim3(HD_/256, ROWS_/128, 1), 256, SMEM256>>>(tXr, tWk, xr, Wkr, Kb,
        D_, D_, D_, HD_, 0,0,0,0,0,0, 0, 0,
        nullptr, nullptr, 0, 0, 1, 0.f, nullptr, nullptr);
    gemm_tc<1,256><<<dim3(HD_/256, ROWS_/128, 1), 256, SMEM256>>>(tXr, tWv, xr, Wvr, Vb,
        D_, D_, D_, HD_, 0,0,0,0,0,0, 0, 0,
        nullptr, nullptr, 0, 0, 1, 0.f, nullptr, nullptr);

    transpose_v<<<dim3(L_/32, D_/32, B_*H_), dim3(32, 8)>>>(Vb, Vt);

    // scores + fused exp & row-sum
    cudaMemsetAsync(Lb, 0, (size_t)B_ * H_ * L_ * sizeof(float));
    gemm_tc<1,256><<<dim3(L_/256, L_/128, B_*H_), 256, SMEM256>>>(tQ, tK, Qb, Kb, S,
        D_, HD_, HD_, L_,
        (long long)L_*HD_, D_, (long long)L_*HD_, D_, 8*LL2, LL2, 3, 256,
        nullptr, nullptr, 0, 0, 0, 0.0625f, Lb, nullptr);

    // PV: O = (S @ Vt^T) / l
    gemm_tc<1,256><<<dim3(D_/256, L_/128, B_*H_), 256, SMEM256>>>(tS, tVt, S, Vt, O,
        L_, L_, L_, HD_,
        8*LL2, LL2, 8LL*D_*L_, (long long)D_*L_, (long long)L_*HD_, D_, 0, 0,
        nullptr, nullptr, 0, 0, 1, 0.f, nullptr, Lb);

    // output projection + bias + residual(x)
    gemm_tc<1,128><<<dim3(D_/128, ROWS_/128, 1), 256, SMEM128>>>(tO, tWu, O, Wur, R1,
        HD_, HD_, HD_, D_, 0,0,0,0,0,0, 0, 0,
        bu, x, D_, 0, 0, 0.f, nullptr, nullptr);
    ln_kernel<<<ROWS_, 256>>>(R1, Z1, Z1r, g1, be1);

    // FFN
    gemm_tc<1,256><<<dim3(F_/256, ROWS_/128, 1), 256, SMEM256>>>(tZ1, tW1, Z1r, W1r, Hb,
        D_, D_, D_, F_, 0,0,0,0,0,0, 0, 0,
        b1, nullptr, 0, 1, 1, 0.f, nullptr, nullptr);
    gemm_tc<1,128><<<dim3(D_/128, ROWS_/128, 1), 256, SMEM128>>>(tHb, tW2, Hb, W2r, F,
        F_, F_, F_, D_, 0,0,0,0,0,0, 0, 0,
        b2, Z1, D_, 0, 0, 0.f, nullptr, nullptr);
    ln_kernel<<<ROWS_, 256>>>(F, out, nullptr, g2, be2);
}

// round 13
// speedup vs baseline: 1.6792x; 1.1687x over previous
#include <cuda_runtime.h>
#include <cuda.h>
#include <cstdint>

#define B_  8
#define L_  1024
#define D_  256
#define H_  8
#define HD_ 2048
#define F_  1024
#define ROWS_ (B_*L_)
#define EPS_ 1e-5f

#if defined(__CUDA_ARCH_FEAT_SM103_ALL) || defined(__CUDA_ARCH_FEAT_SM100_ALL)
#define TC_OK 1
#else
#define TC_OK 0
#endif

// --------------------------- scratch (device globals) ------------------------
__device__ float g_Q[(size_t)ROWS_ * HD_];
__device__ float g_K[(size_t)ROWS_ * HD_];
__device__ float g_V[(size_t)ROWS_ * HD_];
__device__ float g_Vt[(size_t)B_ * H_ * D_ * L_];
__device__ float g_S[(size_t)B_ * H_ * L_ * L_];
__device__ float g_O[(size_t)ROWS_ * HD_];
__device__ float g_R1[(size_t)ROWS_ * D_];
__device__ float g_Z1[(size_t)ROWS_ * D_];
__device__ float g_Z1r[(size_t)ROWS_ * D_];
__device__ float g_Hb[(size_t)ROWS_ * F_];
__device__ float g_F[(size_t)ROWS_ * D_];
__device__ float g_L[(size_t)B_ * H_ * L_];
__device__ float g_xr[(size_t)ROWS_ * D_];
__device__ float g_Wqr[(size_t)HD_ * D_];
__device__ float g_Wkr[(size_t)HD_ * D_];
__device__ float g_Wvr[(size_t)HD_ * D_];
__device__ float g_Wur[(size_t)D_ * HD_];
__device__ float g_W1r[(size_t)F_ * D_];
__device__ float g_W2r[(size_t)D_ * F_];

// --------------------------- common helpers ----------------------------------
__device__ __forceinline__ uint32_t f2tf(float f) {
    uint32_t u; asm("cvt.rna.tf32.f32 %0, %1;" : "=r"(u) : "f"(f)); return u;
}
__device__ __forceinline__ float f2tf_f(float f) { return __uint_as_float(f2tf(f)); }

__device__ __forceinline__ void cp16(uint32_t saddr, const void* gptr) {
    asm volatile("cp.async.cg.shared.global [%0], [%1], 16;" :: "r"(saddr), "l"(gptr));
}
__device__ __forceinline__ void cp_commit() { asm volatile("cp.async.commit_group;"); }
__device__ __forceinline__ void cp_wait1()  { asm volatile("cp.async.wait_group 1;"); }
__device__ __forceinline__ void cp_wait0()  { asm volatile("cp.async.wait_group 0;"); }

__device__ __forceinline__ void mma8(float* c, const uint32_t* a, const uint32_t* b) {
    asm volatile(
        "mma.sync.aligned.m16n8k8.row.col.f32.tf32.tf32.f32 "
        "{%0,%1,%2,%3}, {%4,%5,%6,%7}, {%8,%9}, {%0,%1,%2,%3};"
        : "+f"(c[0]), "+f"(c[1]), "+f"(c[2]), "+f"(c[3])
        : "r"(a[0]), "r"(a[1]), "r"(a[2]), "r"(a[3]), "r"(b[0]), "r"(b[1]));
}

#if TC_OK
// --------------------------- tcgen05/TMA helpers (sm_103a pass only) ---------
__device__ __forceinline__ bool elect1() {
    uint32_t p;
    asm volatile("{\n\t.reg .pred p;\n\telect.sync _|p, 0xFFFFFFFF;\n\tselp.b32 %0,1,0,p;\n\t}" : "=r"(p));
    return p != 0;
}
__device__ __forceinline__ void mbar_init(uint32_t a, uint32_t cnt) {
    asm volatile("mbarrier.init.shared.b64 [%0], %1;" :: "r"(a), "r"(cnt) : "memory");
}
__device__ __forceinline__ void mbar_wait(uint32_t a, uint32_t parity) {
    asm volatile(
        "{\n\t.reg .pred P;\n\t"
        "WL%=:\n\t"
        "mbarrier.try_wait.parity.acquire.cta.shared::cta.b64 P, [%0], %1, 0x989680;\n\t"
        "@P bra WD%=;\n\t"
        "bra WL%=;\n\t"
        "WD%=:\n\t}"
        :: "r"(a), "r"(parity) : "memory");
}
__device__ __forceinline__ void mbar_expect_tx(uint32_t a, uint32_t bytes) {
    asm volatile("mbarrier.arrive.expect_tx.shared.b64 _, [%0], %1;"
                 :: "r"(a), "r"(bytes) : "memory");
}
__device__ __forceinline__ void tma3d(uint32_t smem, const void* tm,
                                      int c0, int c1, int c2, uint32_t mbar) {
    asm volatile(
        "cp.async.bulk.tensor.3d.shared::cta.global.tile.mbarrier::complete_tx::bytes "
        "[%0], [%1, {%2, %3, %4}], [%5];"
        :: "r"(smem), "l"(tm), "r"(c0), "r"(c1), "r"(c2), "r"(mbar) : "memory");
}
__device__ __forceinline__ void tc_fence_after() {
    asm volatile("tcgen05.fence::after_thread_sync;" ::: "memory");
}
__device__ __forceinline__ void tcalloc(uint32_t smem_addr, uint32_t ncols) {
    asm volatile("tcgen05.alloc.cta_group::1.sync.aligned.shared::cta.b32 [%0], %1;"
                 :: "r"(smem_addr), "r"(ncols) : "memory");
}
__device__ __forceinline__ void tcdealloc(uint32_t tmem, uint32_t ncols) {
    asm volatile("tcgen05.dealloc.cta_group::1.sync.aligned.b32 %0, %1;" :: "r"(tmem), "r"(ncols));
}
__device__ __forceinline__ void tcrelinquish() {
    asm volatile("tcgen05.relinquish_alloc_permit.cta_group::1.sync.aligned;");
}
__device__ __forceinline__ void tc_commit(uint32_t mbar) {
    asm volatile("tcgen05.commit.cta_group::1.mbarrier::arrive::one.shared::cluster.b64 [%0];"
                 :: "r"(mbar) : "memory");
}
__device__ __forceinline__ void wait_ld() {
    asm volatile("tcgen05.wait::ld.sync.aligned;" ::: "memory");
}
__device__ __forceinline__ void mma_tf32_ss(uint32_t d, uint64_t ad, uint64_t bd,
                                            uint32_t idesc, uint32_t en) {
    asm volatile(
        "{\n\t.reg .pred p;\n\tsetp.ne.u32 p, %4, 0;\n\t"
        "tcgen05.mma.cta_group::1.kind::tf32 [%0], %1, %2, %3, {%5,%5,%5,%5}, p;\n\t}"
        :: "r"(d), "l"(ad), "l"(bd), "r"(idesc), "r"(en), "r"(0u) : "memory");
}
__device__ __forceinline__ void ldtm32(uint32_t* r, uint32_t a) {
    asm volatile(
        "tcgen05.ld.sync.aligned.32x32b.x32.b32 "
        "{%0,%1,%2,%3,%4,%5,%6,%7,%8,%9,%10,%11,%12,%13,%14,%15,"
        "%16,%17,%18,%19,%20,%21,%22,%23,%24,%25,%26,%27,%28,%29,%30,%31}, [%32];"
        : "=r"(r[0]), "=r"(r[1]), "=r"(r[2]), "=r"(r[3]),
          "=r"(r[4]), "=r"(r[5]), "=r"(r[6]), "=r"(r[7]),
          "=r"(r[8]), "=r"(r[9]), "=r"(r[10]), "=r"(r[11]),
          "=r"(r[12]), "=r"(r[13]), "=r"(r[14]), "=r"(r[15]),
          "=r"(r[16]), "=r"(r[17]), "=r"(r[18]), "=r"(r[19]),
          "=r"(r[20]), "=r"(r[21]), "=r"(r[22]), "=r"(r[23]),
          "=r"(r[24]), "=r"(r[25]), "=r"(r[26]), "=r"(r[27]),
          "=r"(r[28]), "=r"(r[29]), "=r"(r[30]), "=r"(r[31])
        : "r"(a));
}
static constexpr uint64_t DESC_BASE =
    (uint64_t(2) << 61) | (uint64_t(1) << 46) | (uint64_t(64) << 32) | (uint64_t(1) << 16);
__device__ __forceinline__ uint64_t mk_desc(uint32_t a) {
    return DESC_BASE | ((uint64_t)(a >> 4) & 0x3FFFull);
}
#endif // TC_OK

// ============================================================================
// GEMM: C = A @ B^T (K-major, tf32-prerounded), CTA tile 128 x NT, KC=32,
// NST-stage mbarrier pipeline. TMA producer + warp-1 MMA issuer.
// Batched coords: zA = z>>zsh, inner offset = (z & ((1<<zsh)-1))*koMul.
// ============================================================================
template<int MH, int NT, int NST>
__global__ __launch_bounds__(256, (NT == 128) ? 2 : 1)
void gemm_tc(const __grid_constant__ CUtensorMap tmA,
             const __grid_constant__ CUtensorMap tmB,
             const float* __restrict__ A, const float* __restrict__ Bm,
             float* __restrict__ C, int K, int lda, int ldb, int ldc,
             long long sA1, long long sA2, long long sB1, long long sB2,
             long long sC1, long long sC2,
             int zsh, int koMul,
             const float* __restrict__ bias, const float* __restrict__ resid, int ldres,
             int relu, int round_out, float escale,
             float* __restrict__ Lsum, const float* __restrict__ Ldiv)
{
    extern __shared__ __align__(1024) uint8_t smraw[];

    const int z = blockIdx.z;
    A  += (size_t)(z >> 3) * sA1 + (size_t)(z & 7) * sA2;
    Bm += (size_t)(z >> 3) * sB1 + (size_t)(z & 7) * sB2;
    C  += (size_t)(z >> 3) * sC1 + (size_t)(z & 7) * sC2;

    const int tid = threadIdx.x, wid = tid >> 5, lane = tid & 31;
    const int row0 = blockIdx.y * (MH * 128);
    const int col0 = blockIdx.x * NT;

#if TC_OK
    constexpr int ABYTES = MH * 16384;
    constexpr int BBYTES = (NT / 128) * 16384;
    constexpr int STGB = ABYTES + BBYTES;
    constexpr int CTRL = NST * STGB;
    constexpr uint32_t IDESC =
        (1u << 4) | (2u << 7) | (2u << 10) | ((uint32_t)(NT / 8) << 17) | ((uint32_t)(MH * 8) << 24);

    const uint32_t smb = (uint32_t)__cvta_generic_to_shared(smraw);
    const uint32_t tptr = smb + CTRL;
    const uint32_t mbF = smb + CTRL + 8;               // full[0..NST-1]
    const uint32_t mbE = mbF + 8 * NST;                // empty[0..NST-1]
    const uint32_t mbD = mbE + 8 * NST;                // done

    if (wid == 0) tcalloc(tptr, MH * NT);
    if (tid == 0) {
        for (int s = 0; s < NST; ++s) { mbar_init(mbF + 8 * s, 1); mbar_init(mbE + 8 * s, 1); }
        mbar_init(mbD, 1);
    }
    __syncthreads();
    uint32_t tmem;
    asm volatile("ld.shared.b32 %0, [%1];" : "=r"(tmem) : "r"(tptr));

    const int T = K >> 5;
    const int zA = z >> zsh;
    const int ko = (z & ((1 << zsh) - 1)) * koMul;

    if (wid == 0) {
        if (elect1()) {
            // ---- TMA producer (runs up to NST-1 chunks ahead)
            int eph[NST];
#pragma unroll
            for (int s = 0; s < NST; ++s) eph[s] = 1;
            int s = 0;
            for (int c = 0; c < T; ++c) {
                mbar_wait(mbE + 8 * s, eph[s]); eph[s] ^= 1;
                const uint32_t bA = smb + s * STGB;
                const uint32_t fb = mbF + 8 * s;
                const int kc = ko + (c << 5);
                mbar_expect_tx(fb, STGB);
                tma3d(bA, &tmA, kc, row0, zA, fb);
                tma3d(bA + ABYTES, &tmB, kc, col0, zA, fb);
                if (++s == NST) s = 0;
            }
        }
    } else if (wid == 1) {
        if (elect1()) {
            // ---- MMA issuer
            int fph[NST];
#pragma unroll
            for (int s = 0; s < NST; ++s) fph[s] = 0;
            int s = 0;
            for (int c = 0; c < T; ++c) {
                mbar_wait(mbF + 8 * s, fph[s]); fph[s] ^= 1;
                const uint32_t bA = smb + s * STGB, bB = bA + ABYTES;
                const uint64_t bd = mk_desc(bB);
#pragma unroll
                for (int m = 0; m < MH; ++m) {
                    const uint64_t ad = mk_desc(bA + m * 16384);
#pragma unroll
                    for (int k8 = 0; k8 < 4; ++k8)
                        mma_tf32_ss(tmem + m * NT, ad + 2 * k8, bd + 2 * k8, IDESC,
                                    (c > 0 || k8 > 0) ? 1u : 0u);
                }
                tc_commit(mbE + 8 * s);
                if (++s == NST) s = 0;
            }
            tc_commit(mbD);
        }
    }

    mbar_wait(mbD, 0);
    tc_fence_after();
    __syncthreads();

    // ---- vectorized epilogue: TMEM -> regs -> smem(9-f4 pitch) -> STG.128
    // MH=1: all 8 warps on acc0; warps 0-3 cols [0,NT/2), 4-7 [NT/2,NT).
    if (wid < 8) {
        const int sw = wid & 3;
        const int hsel = (MH == 2) ? (wid >> 2) : 0;
        const int cb0  = (MH == 2) ? 0 : (wid >> 2) * (NT / 64);
        const int cbN  = (MH == 2) ? (NT / 32) : (NT / 64);
        float4* wsm4 = (float4*)smraw + wid * (32 * 9);
        const int rloc = hsel * 128 + sw * 32 + lane;
        float rowsum = 0.f;
#pragma unroll 1
        for (int ci = 0; ci < cbN; ++ci) {
            const int cb = cb0 + ci;
            uint32_t rg[32];
            ldtm32(rg, tmem + hsel * NT + cb * 32);
            wait_ld();
            if (Lsum) {
#pragma unroll
                for (int j = 0; j < 32; ++j) {
                    float v = f2tf_f(__expf(__uint_as_float(rg[j]) * escale));
                    rowsum += v;
                    rg[j] = __float_as_uint(v);
                }
            }
            __syncwarp();
#pragma unroll
            for (int jq = 0; jq < 8; ++jq) {
                float4 v4 = make_float4(__uint_as_float(rg[jq * 4 + 0]),
                                        __uint_as_float(rg[jq * 4 + 1]),
                                        __uint_as_float(rg[jq * 4 + 2]),
                                        __uint_as_float(rg[jq * 4 + 3]));
                wsm4[lane * 9 + jq] = v4;
            }
            __syncwarp();
            const int cq = lane & 7;
            const int rsub = lane >> 3;
#pragma unroll 1
            for (int it = 0; it < 8; ++it) {
                const int r = it * 4 + rsub;
                float4 v = wsm4[r * 9 + cq];
                const int orow = row0 + hsel * 128 + sw * 32 + r;
                const int ocol = col0 + cb * 32 + cq * 4;
                if (bias) {
                    const float4 bv = *(const float4*)&bias[ocol];
                    v.x += bv.x; v.y += bv.y; v.z += bv.z; v.w += bv.w;
                }
                if (resid) {
                    const float4 rv = *(const float4*)&resid[(size_t)orow * ldres + ocol];
                    v.x += rv.x; v.y += rv.y; v.z += rv.z; v.w += rv.w;
                }
                if (Ldiv) {
                    const float inv = __frcp_rn(Ldiv[(size_t)z * L_ + orow]);
                    v.x *= inv; v.y *= inv; v.z *= inv; v.w *= inv;
                }
                if (relu) {
                    v.x = fmaxf(v.x, 0.f); v.y = fmaxf(v.y, 0.f);
                    v.z = fmaxf(v.z, 0.f); v.w = fmaxf(v.w, 0.f);
                }
                if (round_out) {
                    v.x = f2tf_f(v.x); v.y = f2tf_f(v.y);
                    v.z = f2tf_f(v.z); v.w = f2tf_f(v.w);
                }
                *(float4*)&C[(size_t)orow * ldc + ocol] = v;
            }
            __syncwarp();
        }
        if (Lsum) atomicAdd(&Lsum[(size_t)z * L_ + row0 + rloc], rowsum);
    }
    __syncthreads();
    if (wid == 0) { tcrelinquish(); tcdealloc(tmem, MH * NT); }

#else  // ----------------- mma.sync fallback (compute_103 pass only) ---------
    constexpr int ASTG = 128 * 36, STG2 = 2 * ASTG;
    uint32_t* sm = (uint32_t*)smraw;
    const int wm = wid & 3, wn = wid >> 2;
    const int g = lane >> 2, tg = lane & 3;
    const uint32_t smb = (uint32_t)__cvta_generic_to_shared(sm);

    for (int mh = 0; mh < MH; ++mh)
    for (int nh = 0; nh < NT / 128; ++nh) {
        const int r0 = row0 + mh * 128, c0 = col0 + nh * 128;
        float acc[2][8][4] = {};

        auto stage = [&](int st, int k0) {
#pragma unroll
            for (int i = 0; i < 4; i++) {
                const int s = tid + i * 256;
                const int r = s >> 3, kq = s & 7;
                const uint32_t baseA = smb + (uint32_t)(st * STG2) * 4u;
                const uint32_t baseB = baseA + (uint32_t)ASTG * 4u;
                cp16(baseA + (uint32_t)(r * 36 + kq * 4) * 4u, A + (size_t)(r0 + r) * lda + k0 + kq * 4);
                cp16(baseB + (uint32_t)(r * 36 + kq * 4) * 4u, Bm + (size_t)(c0 + r) * ldb + k0 + kq * 4);
            }
        };

        const int T = K >> 5;
        stage(0, 0); cp_commit();
        for (int t = 0; t < T; ++t) {
            if (t + 1 < T) { stage((t + 1) & 1, (t + 1) << 5); cp_commit(); cp_wait1(); }
            else           { cp_wait0(); }
            __syncthreads();
            const uint32_t* As = sm + (t & 1) * STG2;
            const uint32_t* Bs = As + ASTG;
#pragma unroll
            for (int ks = 0; ks < 32; ks += 8) {
                uint32_t a[2][4], b[8][2];
#pragma unroll
                for (int mf = 0; mf < 2; mf++) {
                    const int m0 = wm * 32 + mf * 16;
                    a[mf][0] = As[(m0 + g) * 36 + ks + tg];
                    a[mf][1] = As[(m0 + 8 + g) * 36 + ks + tg];
                    a[mf][2] = As[(m0 + g) * 36 + ks + 4 + tg];
                    a[mf][3] = As[(m0 + 8 + g) * 36 + ks + 4 + tg];
                }
#pragma unroll
                for (int nf = 0; nf < 8; nf++) {
                    const int n0 = wn * 64 + nf * 8;
                    b[nf][0] = Bs[(n0 + g) * 36 + ks + tg];
                    b[nf][1] = Bs[(n0 + g) * 36 + ks + 4 + tg];
                }
#pragma unroll
                for (int mf = 0; mf < 2; mf++)
#pragma unroll
                    for (int nf = 0; nf < 8; nf++)
                        mma8(acc[mf][nf], a[mf], b[nf]);
            }
            __syncthreads();
        }

        float rowsum[2][2] = {};
#pragma unroll
        for (int mf = 0; mf < 2; mf++)
#pragma unroll
            for (int nf = 0; nf < 8; nf++)
#pragma unroll
                for (int q = 0; q < 4; q++) {
                    const int rr = r0 + wm * 32 + mf * 16 + g + (q >> 1) * 8;
                    const int cc = c0 + wn * 64 + nf * 8 + 2 * tg + (q & 1);
                    float v = acc[mf][nf][q];
                    if (Lsum) { v = f2tf_f(__expf(v * escale)); rowsum[mf][q >> 1] += v; }
                    if (bias)  v += bias[cc];
                    if (resid) v += resid[(size_t)rr * ldres + cc];
                    if (Ldiv)  v *= __frcp_rn(Ldiv[(size_t)z * L_ + rr]);
                    if (relu)  v = fmaxf(v, 0.f);
                    if (round_out) v = f2tf_f(v);
                    C[(size_t)rr * ldc + cc] = v;
                }
        if (Lsum) {
#pragma unroll
            for (int mf = 0; mf < 2; mf++)
#pragma unroll
                for (int qh = 0; qh < 2; qh++) {
                    float s = rowsum[mf][qh];
                    s += __shfl_xor_sync(~0u, s, 1);
                    s += __shfl_xor_sync(~0u, s, 2);
                    if (tg == 0)
                        atomicAdd(&Lsum[(size_t)z * L_ + r0 + wm * 32 + mf * 16 + g + qh * 8], s);
                }
        }
        __syncthreads();
    }
#endif
}

// --------------------------- merged tf32 rounding pass -----------------------
__global__ void cvt_all_kernel(const float4* x, float4* xr,
                               const float4* wq, float4* wqr,
                               const float4* wk, float4* wkr,
                               const float4* wv, float4* wvr,
                               const float4* wu, float4* wur,
                               const float4* w1, float4* w1r,
                               const float4* w2, float4* w2r)
{
    const int total = 524288 + 4 * 131072 + 2 * 65536;   // 1179648 float4
    for (int i = blockIdx.x * blockDim.x + threadIdx.x; i < total; i += gridDim.x * blockDim.x) {
        const float4* in; float4* out; int j = i;
        if (j < 524288) { in = x; out = xr; }
        else if ((j -= 524288) < 131072) { in = wq; out = wqr; }
        else if ((j -= 131072) < 131072) { in = wk; out = wkr; }
        else if ((j -= 131072) < 131072) { in = wv; out = wvr; }
        else if ((j -= 131072) < 131072) { in = wu; out = wur; }
        else if ((j -= 131072) < 65536)  { in = w1; out = w1r; }
        else { j -= 65536; in = w2; out = w2r; }
        float4 v = in[j];
        v.x = f2tf_f(v.x); v.y = f2tf_f(v.y); v.z = f2tf_f(v.z); v.w = f2tf_f(v.w);
        out[j] = v;
    }
}

// --------------------------- V transpose: Vt[z][e][j] = V[b, j, h*256+e] -----
__global__ void transpose_v(const float* __restrict__ V, float* __restrict__ Vt)
{
    __shared__ float t[32][33];
    const int z = blockIdx.z, b = z >> 3, h = z & 7;
    const int j0 = blockIdx.x * 32, e0 = blockIdx.y * 32;
    const int tx = threadIdx.x, ty = threadIdx.y;
#pragma unroll
    for (int k = 0; k < 4; k++)
        t[ty + k * 8][tx] = V[(size_t)(b * L_ + j0 + ty + k * 8) * HD_ + h * D_ + e0 + tx];
    __syncthreads();
#pragma unroll
    for (int k = 0; k < 4; k++)
        Vt[(size_t)z * D_ * L_ + (size_t)(e0 + ty + k * 8) * L_ + j0 + tx] = t[tx][ty + k * 8];
}

// --------------------------- layernorm over d=256 ----------------------------
__global__ void ln_kernel(const float* __restrict__ in, float* __restrict__ out,
                          float* __restrict__ out_r,
                          const float* __restrict__ g, const float* __restrict__ be)
{
    __shared__ float r1[8], r2[8];
    const int row = blockIdx.x, t = threadIdx.x;
    const float v = in[(size_t)row * D_ + t];
    float s = v, q = v * v;
#pragma unroll
    for (int o = 16; o; o >>= 1) {
        s += __shfl_xor_sync(~0u, s, o);
        q += __shfl_xor_sync(~0u, q, o);
    }
    if ((t & 31) == 0) { r1[t >> 5] = s; r2[t >> 5] = q; }
    __syncthreads();
    float S = 0.f, Q = 0.f;
#pragma unroll
    for (int i = 0; i < 8; i++) { S += r1[i]; Q += r2[i]; }
    const float mean = S * (1.f / D_);
    const float var = Q * (1.f / D_) - mean * mean;
    const float y = (v - mean) * rsqrtf(var + EPS_) * g[t] + be[t];
    out[(size_t)row * D_ + t] = y;
    if (out_r) out_r[(size_t)row * D_ + t] = f2tf_f(y);
}

// --------------------------- host: tensormap encoding ------------------------
typedef CUresult (*EncFn)(CUtensorMap*, CUtensorMapDataType, cuuint32_t, void*,
                          const cuuint64_t*, const cuuint64_t*, const cuuint32_t*,
                          const cuuint32_t*, CUtensorMapInterleave, CUtensorMapSwizzle,
                          CUtensorMapL2promotion, CUtensorMapFloatOOBfill);

static EncFn get_enc() {
    static EncFn fn = nullptr;
    if (!fn) {
        void* p = nullptr;
        cudaDriverEntryPointQueryResult st;
        cudaGetDriverEntryPoint("cuTensorMapEncodeTiled", &p, cudaEnableDefault, &st);
        fn = (EncFn)p;
    }
    return fn;
}

static void mk3d(CUtensorMap* tm, void* ptr,
                 unsigned long long d0, unsigned long long d1, unsigned long long d2,
                 unsigned long long s1B, unsigned long long s2B,
                 unsigned b0, unsigned b1)
{
    cuuint64_t dims[3] = {d0, d1, d2};
    cuuint64_t strides[2] = {s1B, s2B};
    cuuint32_t box[3] = {b0, b1, 1};
    cuuint32_t es[3] = {1, 1, 1};
    get_enc()(tm, CU_TENSOR_MAP_DATA_TYPE_FLOAT32, 3, ptr, dims, strides, box, es,
              CU_TENSOR_MAP_INTERLEAVE_NONE, CU_TENSOR_MAP_SWIZZLE_128B,
              CU_TENSOR_MAP_L2_PROMOTION_L2_128B, CU_TENSOR_MAP_FLOAT_OOB_FILL_NONE);
}

// --------------------------- launch ------------------------------------------
extern "C" void kernel_launch(void* const* d_in, const int* in_sizes, int n_in,
                              void* d_out, int out_size)
{
    const float* x   = (const float*)d_in[0];
    const float* Wq  = (const float*)d_in[1];
    const float* Wk  = (const float*)d_in[2];
    const float* Wv  = (const float*)d_in[3];
    const float* Wu  = (const float*)d_in[4];
    const float* bu  = (const float*)d_in[5];
    const float* W1  = (const float*)d_in[6];
    const float* b1  = (const float*)d_in[7];
    const float* W2  = (const float*)d_in[8];
    const float* b2  = (const float*)d_in[9];
    const float* g1  = (const float*)d_in[10];
    const float* be1 = (const float*)d_in[11];
    const float* g2  = (const float*)d_in[12];
    const float* be2 = (const float*)d_in[13];
    float* out = (float*)d_out;

    float *Qb, *Kb, *Vb, *Vt, *S, *O, *R1, *Z1, *Z1r, *Hb, *F, *Lb;
    float *xr, *Wqr, *Wkr, *Wvr, *Wur, *W1r, *W2r;
    cudaGetSymbolAddress((void**)&Qb, g_Q);
    cudaGetSymbolAddress((void**)&Kb, g_K);
    cudaGetSymbolAddress((void**)&Vb, g_V);
    cudaGetSymbolAddress((void**)&Vt, g_Vt);
    cudaGetSymbolAddress((void**)&S,  g_S);
    cudaGetSymbolAddress((void**)&O,  g_O);
    cudaGetSymbolAddress((void**)&R1, g_R1);
    cudaGetSymbolAddress((void**)&Z1, g_Z1);
    cudaGetSymbolAddress((void**)&Z1r, g_Z1r);
    cudaGetSymbolAddress((void**)&Hb, g_Hb);
    cudaGetSymbolAddress((void**)&F,  g_F);
    cudaGetSymbolAddress((void**)&Lb, g_L);
    cudaGetSymbolAddress((void**)&xr,  g_xr);
    cudaGetSymbolAddress((void**)&Wqr, g_Wqr);
    cudaGetSymbolAddress((void**)&Wkr, g_Wkr);
    cudaGetSymbolAddress((void**)&Wvr, g_Wvr);
    cudaGetSymbolAddress((void**)&Wur, g_Wur);
    cudaGetSymbolAddress((void**)&W1r, g_W1r);
    cudaGetSymbolAddress((void**)&W2r, g_W2r);

    // ---- tensor maps (host structs, passed by value; no allocations)
    CUtensorMap tXr, tWq, tWk, tWv, tQ, tK, tS, tVt, tO, tWu, tZ1, tW1, tHb, tW2;
    const unsigned long long F4 = sizeof(float);
    // A maps: box (32, 128)
    mk3d(&tXr, xr,  D_,  ROWS_, 1, D_ * F4,  0,                 32, 128);
    mk3d(&tQ,  Qb,  HD_, L_,    B_, (unsigned long long)HD_ * F4, (unsigned long long)L_ * HD_ * F4, 32, 128);
    mk3d(&tS,  S,   L_,  L_,    B_ * H_, (unsigned long long)L_ * F4, (unsigned long long)L_ * L_ * F4, 32, 128);
    mk3d(&tO,  O,   HD_, ROWS_, 1, (unsigned long long)HD_ * F4, 0,  32, 128);
    mk3d(&tZ1, Z1r, D_,  ROWS_, 1, D_ * F4, 0,                  32, 128);
    mk3d(&tHb, Hb,  F_,  ROWS_, 1, (unsigned long long)F_ * F4, 0,  32, 128);
    // B maps: box (32, NT)
    mk3d(&tWq, Wqr, D_,  HD_,   1, D_ * F4,  0,                 32, 256);
    mk3d(&tWk, Wkr, D_,  HD_,   1, D_ * F4,  0,                 32, 256);
    mk3d(&tWv, Wvr, D_,  HD_,   1, D_ * F4,  0,                 32, 256);
    mk3d(&tK,  Kb,  HD_, L_,    B_, (unsigned long long)HD_ * F4, (unsigned long long)L_ * HD_ * F4, 32, 256);
    mk3d(&tVt, Vt,  L_,  D_,    B_ * H_, (unsigned long long)L_ * F4, (unsigned long long)D_ * L_ * F4, 32, 256);
    mk3d(&tWu, Wur, HD_, D_,    1, (unsigned long long)HD_ * F4, 0,  32, 128);
    mk3d(&tW1, W1r, D_,  F_,    1, D_ * F4, 0,                  32, 256);
    mk3d(&tW2, W2r, F_,  D_,    1, (unsigned long long)F_ * F4, 0,  32, 128);

    constexpr int SMEM256 = 4 * 49152 + 80;   // <1,256,4>: 196688
    constexpr int SMEM128 = 3 * 32768 + 72;   // <1,128,3>: 98376
    cudaFuncSetAttribute(gemm_tc<1,256,4>, cudaFuncAttributeMaxDynamicSharedMemorySize, SMEM256);
    cudaFuncSetAttribute(gemm_tc<1,128,3>, cudaFuncAttributeMaxDynamicSharedMemorySize, SMEM128);

    cvt_all_kernel<<<1184, 256>>>((const float4*)x,  (float4*)xr,
                                  (const float4*)Wq, (float4*)Wqr,
                                  (const float4*)Wk, (float4*)Wkr,
                                  (const float4*)Wv, (float4*)Wvr,
                                  (const float4*)Wu, (float4*)Wur,
                                  (const float4*)W1, (float4*)W1r,
                                  (const float4*)W2, (float4*)W2r);

    const long long LL2 = (long long)L_ * L_;

    // QKV projections: tile 128x256
    gemm_tc<1,256,4><<<dim3(HD_/256, ROWS_/128, 1), 256, SMEM256>>>(tXr, tWq, xr, Wqr, Qb,
        D_, D_, D_, HD_, 0,0,0,0,0,0, 0, 0,
        nullptr, nullptr, 0, 0, 1, 0.f, nullptr, nullptr);
    gemm_tc<1,256,4><<<dim3(HD_/256, ROWS_/128, 1), 256, SMEM256>>>(tXr, tWk, xr, Wkr, Kb,
        D_, D_, D_, HD_, 0,0,0,0,0,0, 0, 0,
        nullptr, nullptr, 0, 0, 1, 0.f, nullptr, nullptr);
    gemm_tc<1,256,4><<<dim3(HD_/256, ROWS_/128, 1), 256, SMEM256>>>(tXr, tWv, xr, Wvr, Vb,
        D_, D_, D_, HD_, 0,0,0,0,0,0, 0, 0,
        nullptr, nullptr, 0, 0, 1, 0.f, nullptr, nullptr);

    transpose_v<<<dim3(L_/32, D_/32, B_*H_), dim3(32, 8)>>>(Vb, Vt);

    // scores + fused exp & row-sum
    cudaMemsetAsync(Lb, 0, (size_t)B_ * H_ * L_ * sizeof(float));
    gemm_tc<1,256,4><<<dim3(L_/256, L_/128, B_*H_), 256, SMEM256>>>(tQ, tK, Qb, Kb, S,
        D_, HD_, HD_, L_,
        (long long)L_*HD_, D_, (long long)L_*HD_, D_, 8*LL2, LL2, 3, 256,
        nullptr, nullptr, 0, 0, 0, 0.0625f, Lb, nullptr);

    // PV: O = (S @ Vt^T) / l
    gemm_tc<1,256,4><<<dim3(D_/256, L_/128, B_*H_), 256, SMEM256>>>(tS, tVt, S, Vt, O,
        L_, L_, L_, HD_,
        8*LL2, LL2, 8LL*D_*L_, (long long)D_*L_, (long long)L_*HD_, D_, 0, 0,
        nullptr, nullptr, 0, 0, 1, 0.f, nullptr, Lb);

    // output projection + bias + residual(x)
    gemm_tc<1,128,3><<<dim3(D_/128, ROWS_/128, 1), 256, SMEM128>>>(tO, tWu, O, Wur, R1,
        HD_, HD_, HD_, D_, 0,0,0,0,0,0, 0, 0,
        bu, x, D_, 0, 0, 0.f, nullptr, nullptr);
    ln_kernel<<<ROWS_, 256>>>(R1, Z1, Z1r, g1, be1);

    // FFN
    gemm_tc<1,256,4><<<dim3(F_/256, ROWS_/128, 1), 256, SMEM256>>>(tZ1, tW1, Z1r, W1r, Hb,
        D_, D_, D_, F_, 0,0,0,0,0,0, 0, 0,
        b1, nullptr, 0, 1, 1, 0.f, nullptr, nullptr);
    gemm_tc<1,128,3><<<dim3(D_/128, ROWS_/128, 1), 256, SMEM128>>>(tHb, tW2, Hb, W2r, F,
        F_, F_, F_, D_, 0,0,0,0,0,0, 0, 0,
        b2, Z1, D_, 0, 0, 0.f, nullptr, nullptr);
    ln_kernel<<<ROWS_, 256>>>(F, out, nullptr, g2, be2);
}

// round 14
// speedup vs baseline: 2.1986x; 1.3093x over previous
#include <cuda_runtime.h>
#include <cuda.h>
#include <cstdint>

#define B_  8
#define L_  1024
#define D_  256
#define H_  8
#define HD_ 2048
#define QKVW_ 6144          // 3*HD_
#define F_  1024
#define ROWS_ (B_*L_)
#define EPS_ 1e-5f

#if defined(__CUDA_ARCH_FEAT_SM103_ALL) || defined(__CUDA_ARCH_FEAT_SM100_ALL)
#define TC_OK 1
#else
#define TC_OK 0
#endif

// --------------------------- scratch (device globals) ------------------------
__device__ float g_QKV[(size_t)ROWS_ * QKVW_];   // fused QKV output [row, 3*HD]
__device__ float g_Vt[(size_t)B_ * H_ * D_ * L_];
__device__ float g_S[(size_t)B_ * H_ * L_ * L_];
__device__ float g_O[(size_t)ROWS_ * HD_];
__device__ float g_R1[(size_t)ROWS_ * D_];
__device__ float g_Z1[(size_t)ROWS_ * D_];
__device__ float g_Z1r[(size_t)ROWS_ * D_];
__device__ float g_Hb[(size_t)ROWS_ * F_];
__device__ float g_F[(size_t)ROWS_ * D_];
__device__ float g_L[(size_t)B_ * H_ * L_];
__device__ float g_xr[(size_t)ROWS_ * D_];
__device__ float g_Wqkvr[(size_t)QKVW_ * D_];    // concat rounded Wq|Wk|Wv
__device__ float g_Wur[(size_t)D_ * HD_];
__device__ float g_W1r[(size_t)F_ * D_];
__device__ float g_W2r[(size_t)D_ * F_];

// --------------------------- common helpers ----------------------------------
__device__ __forceinline__ uint32_t f2tf(float f) {
    uint32_t u; asm("cvt.rna.tf32.f32 %0, %1;" : "=r"(u) : "f"(f)); return u;
}
__device__ __forceinline__ float f2tf_f(float f) { return __uint_as_float(f2tf(f)); }

__device__ __forceinline__ void cp16(uint32_t saddr, const void* gptr) {
    asm volatile("cp.async.cg.shared.global [%0], [%1], 16;" :: "r"(saddr), "l"(gptr));
}
__device__ __forceinline__ void cp_commit() { asm volatile("cp.async.commit_group;"); }
__device__ __forceinline__ void cp_wait1()  { asm volatile("cp.async.wait_group 1;"); }
__device__ __forceinline__ void cp_wait0()  { asm volatile("cp.async.wait_group 0;"); }

__device__ __forceinline__ void mma8(float* c, const uint32_t* a, const uint32_t* b) {
    asm volatile(
        "mma.sync.aligned.m16n8k8.row.col.f32.tf32.tf32.f32 "
        "{%0,%1,%2,%3}, {%4,%5,%6,%7}, {%8,%9}, {%0,%1,%2,%3};"
        : "+f"(c[0]), "+f"(c[1]), "+f"(c[2]), "+f"(c[3])
        : "r"(a[0]), "r"(a[1]), "r"(a[2]), "r"(a[3]), "r"(b[0]), "r"(b[1]));
}

#if TC_OK
// --------------------------- tcgen05/TMA helpers (sm_103a pass only) ---------
__device__ __forceinline__ bool elect1() {
    uint32_t p;
    asm volatile("{\n\t.reg .pred p;\n\telect.sync _|p, 0xFFFFFFFF;\n\tselp.b32 %0,1,0,p;\n\t}" : "=r"(p));
    return p != 0;
}
__device__ __forceinline__ void mbar_init(uint32_t a, uint32_t cnt) {
    asm volatile("mbarrier.init.shared.b64 [%0], %1;" :: "r"(a), "r"(cnt) : "memory");
}
__device__ __forceinline__ void mbar_wait(uint32_t a, uint32_t parity) {
    asm volatile(
        "{\n\t.reg .pred P;\n\t"
        "WL%=:\n\t"
        "mbarrier.try_wait.parity.acquire.cta.shared::cta.b64 P, [%0], %1, 0x989680;\n\t"
        "@P bra WD%=;\n\t"
        "bra WL%=;\n\t"
        "WD%=:\n\t}"
        :: "r"(a), "r"(parity) : "memory");
}
__device__ __forceinline__ void mbar_arrive(uint32_t a) {
    asm volatile("mbarrier.arrive.shared.b64 _, [%0];" :: "r"(a) : "memory");
}
__device__ __forceinline__ void mbar_expect_tx(uint32_t a, uint32_t bytes) {
    asm volatile("mbarrier.arrive.expect_tx.shared.b64 _, [%0], %1;"
                 :: "r"(a), "r"(bytes) : "memory");
}
__device__ __forceinline__ void tma3d(uint32_t smem, const void* tm,
                                      int c0, int c1, int c2, uint32_t mbar) {
    asm volatile(
        "cp.async.bulk.tensor.3d.shared::cta.global.tile.mbarrier::complete_tx::bytes "
        "[%0], [%1, {%2, %3, %4}], [%5];"
        :: "r"(smem), "l"(tm), "r"(c0), "r"(c1), "r"(c2), "r"(mbar) : "memory");
}
__device__ __forceinline__ void tc_fence_after() {
    asm volatile("tcgen05.fence::after_thread_sync;" ::: "memory");
}
__device__ __forceinline__ void tcalloc(uint32_t smem_addr, uint32_t ncols) {
    asm volatile("tcgen05.alloc.cta_group::1.sync.aligned.shared::cta.b32 [%0], %1;"
                 :: "r"(smem_addr), "r"(ncols) : "memory");
}
__device__ __forceinline__ void tcdealloc(uint32_t tmem, uint32_t ncols) {
    asm volatile("tcgen05.dealloc.cta_group::1.sync.aligned.b32 %0, %1;" :: "r"(tmem), "r"(ncols));
}
__device__ __forceinline__ void tcrelinquish() {
    asm volatile("tcgen05.relinquish_alloc_permit.cta_group::1.sync.aligned;");
}
__device__ __forceinline__ void tc_commit(uint32_t mbar) {
    asm volatile("tcgen05.commit.cta_group::1.mbarrier::arrive::one.shared::cluster.b64 [%0];"
                 :: "r"(mbar) : "memory");
}
__device__ __forceinline__ void wait_ld() {
    asm volatile("tcgen05.wait::ld.sync.aligned;" ::: "memory");
}
__device__ __forceinline__ void mma_tf32_ss(uint32_t d, uint64_t ad, uint64_t bd,
                                            uint32_t idesc, uint32_t en) {
    asm volatile(
        "{\n\t.reg .pred p;\n\tsetp.ne.u32 p, %4, 0;\n\t"
        "tcgen05.mma.cta_group::1.kind::tf32 [%0], %1, %2, %3, {%5,%5,%5,%5}, p;\n\t}"
        :: "r"(d), "l"(ad), "l"(bd), "r"(idesc), "r"(en), "r"(0u) : "memory");
}
__device__ __forceinline__ void ldtm32(uint32_t* r, uint32_t a) {
    asm volatile(
        "tcgen05.ld.sync.aligned.32x32b.x32.b32 "
        "{%0,%1,%2,%3,%4,%5,%6,%7,%8,%9,%10,%11,%12,%13,%14,%15,"
        "%16,%17,%18,%19,%20,%21,%22,%23,%24,%25,%26,%27,%28,%29,%30,%31}, [%32];"
        : "=r"(r[0]), "=r"(r[1]), "=r"(r[2]), "=r"(r[3]),
          "=r"(r[4]), "=r"(r[5]), "=r"(r[6]), "=r"(r[7]),
          "=r"(r[8]), "=r"(r[9]), "=r"(r[10]), "=r"(r[11]),
          "=r"(r[12]), "=r"(r[13]), "=r"(r[14]), "=r"(r[15]),
          "=r"(r[16]), "=r"(r[17]), "=r"(r[18]), "=r"(r[19]),
          "=r"(r[20]), "=r"(r[21]), "=r"(r[22]), "=r"(r[23]),
          "=r"(r[24]), "=r"(r[25]), "=r"(r[26]), "=r"(r[27]),
          "=r"(r[28]), "=r"(r[29]), "=r"(r[30]), "=r"(r[31])
        : "r"(a));
}
static constexpr uint64_t DESC_BASE =
    (uint64_t(2) << 61) | (uint64_t(1) << 46) | (uint64_t(64) << 32) | (uint64_t(1) << 16);
__device__ __forceinline__ uint64_t mk_desc(uint32_t a) {
    return DESC_BASE | ((uint64_t)(a >> 4) & 0x3FFFull);
}
#endif // TC_OK

// ============================================================================
// Persistent GEMM: C = A @ B^T (K-major, tf32-prerounded), tile 128 x NT,
// KC=32, NST-stage TMA pipeline, DOUBLE-BUFFERED TMEM accumulators.
// 320 threads: w0 = TMA producer, w1 = MMA issuer, w2-9 = epilogue.
// Tile t -> tz = t/gxy, ty = (t%gxy)/gx, tx = (t%gxy)%gx.
// ============================================================================
template<int NT, int NST>
__global__ __launch_bounds__(320, 1)
void gemm_tc(const __grid_constant__ CUtensorMap tmA,
             const __grid_constant__ CUtensorMap tmB,
             const float* __restrict__ A, const float* __restrict__ Bm,
             float* __restrict__ C, int K, int lda, int ldb, int ldc,
             long long sA1, long long sA2, long long sC1, long long sC2,
             int ntiles, int gx, int gxy, int zsh, int koMul,
             const float* __restrict__ bias, const float* __restrict__ resid, int ldres,
             int relu, int round_out, float escale,
             float* __restrict__ Lsum, const float* __restrict__ Ldiv)
{
    extern __shared__ __align__(1024) uint8_t smraw[];

    const int tid = threadIdx.x, wid = tid >> 5, lane = tid & 31;
    const int nCTA = gridDim.x, bx = blockIdx.x;
    const int T = K >> 5;

#if TC_OK
    constexpr int ABYTES = 16384;
    constexpr int BBYTES = NT * 128;
    constexpr int STGB = ABYTES + BBYTES;
    constexpr int EPIOFF = NST * STGB;                 // epilogue scratch (8 warps)
    constexpr int CTRL = EPIOFF + 8 * 32 * 9 * 16;
    constexpr uint32_t IDESC =
        (1u << 4) | (2u << 7) | (2u << 10) | ((uint32_t)(NT / 8) << 17) | (8u << 24);

    const uint32_t smb  = (uint32_t)__cvta_generic_to_shared(smraw);
    const uint32_t tptr = smb + CTRL;
    const uint32_t mbF  = tptr + 8;                    // full[NST]
    const uint32_t mbE  = mbF + 8 * NST;               // empty[NST]
    const uint32_t mbD  = mbE + 8 * NST;               // done[2]
    const uint32_t mbR  = mbD + 16;                    // free[2]

    if (wid == 0) tcalloc(tptr, 512);
    if (tid == 0) {
        for (int s = 0; s < NST; ++s) { mbar_init(mbF + 8 * s, 1); mbar_init(mbE + 8 * s, 1); }
        mbar_init(mbD, 1);     mbar_init(mbD + 8, 1);
        mbar_init(mbR, 8);     mbar_init(mbR + 8, 8);
    }
    __syncthreads();
    uint32_t tmem;
    asm volatile("ld.shared.b32 %0, [%1];" : "=r"(tmem) : "r"(tptr));

    if (wid == 0) {
        if (elect1()) {
            // -------- TMA producer: streams continuously across tiles --------
            int eph[NST];
#pragma unroll
            for (int s = 0; s < NST; ++s) eph[s] = 1;
            int s = 0;
            for (int t = bx; t < ntiles; t += nCTA) {
                const int tz = t / gxy, rem = t - tz * gxy;
                const int ty = rem / gx, tx = rem - ty * gx;
                const int row0 = ty * 128, col0 = tx * NT;
                const int zA = tz >> zsh;
                const int ko = (tz & ((1 << zsh) - 1)) * koMul;
                for (int c = 0; c < T; ++c) {
                    mbar_wait(mbE + 8 * s, eph[s]); eph[s] ^= 1;
                    const uint32_t bA = smb + s * STGB;
                    const uint32_t fb = mbF + 8 * s;
                    const int kc = ko + (c << 5);
                    mbar_expect_tx(fb, STGB);
                    tma3d(bA, &tmA, kc, row0, zA, fb);
                    tma3d(bA + ABYTES, &tmB, kc, col0, zA, fb);
                    if (++s == NST) s = 0;
                }
            }
        }
    } else if (wid == 1) {
        if (elect1()) {
            // -------- MMA issuer: acc = tile-parity, waits free[p] ----------
            int fph[NST];
#pragma unroll
            for (int s = 0; s < NST; ++s) fph[s] = 0;
            int phF[2] = {1, 1};
            int s = 0, pk = 0;
            for (int t = bx; t < ntiles; t += nCTA) {
                const int p = pk & 1;
                mbar_wait(mbR + 8 * p, phF[p]); phF[p] ^= 1;
                const uint32_t dacc = tmem + p * NT;
                for (int c = 0; c < T; ++c) {
                    mbar_wait(mbF + 8 * s, fph[s]); fph[s] ^= 1;
                    const uint32_t bA = smb + s * STGB, bB = bA + ABYTES;
                    const uint64_t ad = mk_desc(bA), bd = mk_desc(bB);
#pragma unroll
                    for (int k8 = 0; k8 < 4; ++k8)
                        mma_tf32_ss(dacc, ad + 2 * k8, bd + 2 * k8, IDESC,
                                    (c > 0 || k8 > 0) ? 1u : 0u);
                    tc_commit(mbE + 8 * s);
                    if (++s == NST) s = 0;
                }
                tc_commit(mbD + 8 * p);
                ++pk;
            }
        }
    } else {
        // -------- epilogue warps 2..9: drain acc[(pk)&1] per tile -----------
        const int ew = wid - 2;                 // 0..7
        const int sub = wid & 3;                // TMEM subpartition rows
        const int colhalf = ew >> 2;
        const int cbN = NT / 64;                // col blocks per warp
        float4* wsm4 = (float4*)(smraw + EPIOFF) + ew * (32 * 9);
        int phD[2] = {0, 0};
        int pk = 0;
        for (int t = bx; t < ntiles; t += nCTA) {
            const int tz = t / gxy, rem = t - tz * gxy;
            const int ty = rem / gx, tx = rem - ty * gx;
            const int row0 = ty * 128, col0 = tx * NT;
            float* Cz = C + (size_t)(tz >> 3) * sC1 + (size_t)(tz & 7) * sC2;
            const int p = pk & 1;
            mbar_wait(mbD + 8 * p, phD[p]); phD[p] ^= 1;
            tc_fence_after();

            float rowsum = 0.f;
#pragma unroll 1
            for (int ci = 0; ci < cbN; ++ci) {
                const int cb = colhalf * cbN + ci;
                uint32_t rg[32];
                ldtm32(rg, tmem + p * NT + cb * 32);
                wait_ld();
                if (Lsum) {
#pragma unroll
                    for (int j = 0; j < 32; ++j) {
                        float v = f2tf_f(__expf(__uint_as_float(rg[j]) * escale));
                        rowsum += v;
                        rg[j] = __float_as_uint(v);
                    }
                }
                __syncwarp();
#pragma unroll
                for (int jq = 0; jq < 8; ++jq)
                    wsm4[lane * 9 + jq] = make_float4(__uint_as_float(rg[jq * 4 + 0]),
                                                      __uint_as_float(rg[jq * 4 + 1]),
                                                      __uint_as_float(rg[jq * 4 + 2]),
                                                      __uint_as_float(rg[jq * 4 + 3]));
                __syncwarp();
                const int cq = lane & 7, rsub = lane >> 3;
#pragma unroll 1
                for (int it = 0; it < 8; ++it) {
                    const int r = it * 4 + rsub;
                    float4 v = wsm4[r * 9 + cq];
                    const int orow = row0 + sub * 32 + r;
                    const int ocol = col0 + cb * 32 + cq * 4;
                    if (bias) {
                        const float4 bv = *(const float4*)&bias[ocol];
                        v.x += bv.x; v.y += bv.y; v.z += bv.z; v.w += bv.w;
                    }
                    if (resid) {
                        const float4 rv = *(const float4*)&resid[(size_t)orow * ldres + ocol];
                        v.x += rv.x; v.y += rv.y; v.z += rv.z; v.w += rv.w;
                    }
                    if (Ldiv) {
                        const float inv = __frcp_rn(Ldiv[(size_t)tz * L_ + orow]);
                        v.x *= inv; v.y *= inv; v.z *= inv; v.w *= inv;
                    }
                    if (relu) {
                        v.x = fmaxf(v.x, 0.f); v.y = fmaxf(v.y, 0.f);
                        v.z = fmaxf(v.z, 0.f); v.w = fmaxf(v.w, 0.f);
                    }
                    if (round_out) {
                        v.x = f2tf_f(v.x); v.y = f2tf_f(v.y);
                        v.z = f2tf_f(v.z); v.w = f2tf_f(v.w);
                    }
                    *(float4*)&Cz[(size_t)orow * ldc + ocol] = v;
                }
                __syncwarp();
            }
            if (Lsum) atomicAdd(&Lsum[(size_t)tz * L_ + row0 + sub * 32 + lane], rowsum);
            __syncwarp();
            if (lane == 0) mbar_arrive(mbR + 8 * p);
            ++pk;
        }
    }

    __syncthreads();
    if (wid == 0) { tcrelinquish(); tcdealloc(tmem, 512); }

#else  // ----------------- mma.sync fallback (compute_103 pass only) ---------
    constexpr int ASTG = 128 * 36, STG2 = 2 * ASTG;
    uint32_t* sm = (uint32_t*)smraw;
    const int wm = wid & 3, wn = wid >> 2;
    const int g = lane >> 2, tg = lane & 3;
    const uint32_t smb = (uint32_t)__cvta_generic_to_shared(sm);

    for (int t = bx; t < ntiles; t += nCTA) {
        const int tz = t / gxy, rem = t - tz * gxy;
        const int ty = rem / gx, txx = rem - ty * gx;
        const float* Az = A + (size_t)(tz >> 3) * sA1 + (size_t)(tz & 7) * sA2;
        const float* Bz = Bm + (size_t)(tz >> 3) * sA1 * 0;   // B offsets folded below
        // recompute B base like A (B shares z folding via tensormap in TC path):
        // for fallback, derive from koMul/zsh semantics: B rows offset = col dim only.
        float* Cz = C + (size_t)(tz >> 3) * sC1 + (size_t)(tz & 7) * sC2;
        const int r0 = ty * 128;
        const int koff = (tz & ((1 << zsh) - 1)) * koMul;
        const long long zrowA = (long long)(tz >> zsh) * ((zsh || koMul) ? 0 : 0);
        (void)zrowA; (void)Bz;

        for (int nh = 0; nh < NT / 128; ++nh) {
            const int c0 = txx * NT + nh * 128;
            float acc[2][8][4] = {};
            const float* Ab = A + (size_t)(tz >> zsh) * ((zsh == 3) ? (long long)L_ * lda : ((gxy < ntiles) ? (long long)0 : 0));
            // General fallback addressing: use sA1/sA2 for A, and B via ldb with same z-fold.
            Ab = A + (size_t)(tz >> 3) * sA1 + (size_t)(tz & 7) * sA2;
            const float* Bb = Bm + ((zsh == 3) ? ((size_t)(tz >> 3) * (size_t)L_ * ldb + (size_t)(tz & 7) * D_)
                                               : ((gxy * 1 < ntiles || true) ? (size_t)((sC1 != 0 && zsh == 0 && koMul == 0 && gxy != ntiles) ? (size_t)tz * (size_t)D_ * (size_t)L_ : 0) : 0));

            auto stage = [&](int st, int k0) {
                for (int s2 = tid; s2 < 1024; s2 += 320) {
                    const int r = s2 >> 3, kq = s2 & 7;
                    const uint32_t baseA = smb + (uint32_t)(st * STG2) * 4u;
                    const uint32_t baseB = baseA + (uint32_t)ASTG * 4u;
                    cp16(baseA + (uint32_t)(r * 36 + kq * 4) * 4u,
                         Ab + (size_t)(r0 + r) * lda + koff + k0 + kq * 4);
                    cp16(baseB + (uint32_t)(r * 36 + kq * 4) * 4u,
                         Bb + (size_t)(c0 + r) * ldb + koff + k0 + kq * 4);
                }
            };

            stage(0, 0); cp_commit();
            for (int tt = 0; tt < T; ++tt) {
                if (tt + 1 < T) { stage((tt + 1) & 1, (tt + 1) << 5); cp_commit(); cp_wait1(); }
                else            { cp_wait0(); }
                __syncthreads();
                if (wid < 8) {
                    const uint32_t* As = sm + (tt & 1) * STG2;
                    const uint32_t* Bs = As + ASTG;
#pragma unroll
                    for (int ks = 0; ks < 32; ks += 8) {
                        uint32_t a[2][4], b[8][2];
#pragma unroll
                        for (int mf = 0; mf < 2; mf++) {
                            const int m0 = wm * 32 + mf * 16;
                            a[mf][0] = As[(m0 + g) * 36 + ks + tg];
                            a[mf][1] = As[(m0 + 8 + g) * 36 + ks + tg];
                            a[mf][2] = As[(m0 + g) * 36 + ks + 4 + tg];
                            a[mf][3] = As[(m0 + 8 + g) * 36 + ks + 4 + tg];
                        }
#pragma unroll
                        for (int nf = 0; nf < 8; nf++) {
                            const int n0 = wn * 64 + nf * 8;
                            b[nf][0] = Bs[(n0 + g) * 36 + ks + tg];
                            b[nf][1] = Bs[(n0 + g) * 36 + ks + 4 + tg];
                        }
#pragma unroll
                        for (int mf = 0; mf < 2; mf++)
#pragma unroll
                            for (int nf = 0; nf < 8; nf++)
                                mma8(acc[mf][nf], a[mf], b[nf]);
                    }
                }
                __syncthreads();
            }

            if (wid < 8) {
                float rowsum[2][2] = {};
#pragma unroll
                for (int mf = 0; mf < 2; mf++)
#pragma unroll
                    for (int nf = 0; nf < 8; nf++)
#pragma unroll
                        for (int q = 0; q < 4; q++) {
                            const int rr = r0 + wm * 32 + mf * 16 + g + (q >> 1) * 8;
                            const int cc = c0 + wn * 64 + nf * 8 + 2 * tg + (q & 1);
                            float v = acc[mf][nf][q];
                            if (Lsum) { v = f2tf_f(__expf(v * escale)); rowsum[mf][q >> 1] += v; }
                            if (bias)  v += bias[cc];
                            if (resid) v += resid[(size_t)rr * ldres + cc];
                            if (Ldiv)  v *= __frcp_rn(Ldiv[(size_t)tz * L_ + rr]);
                            if (relu)  v = fmaxf(v, 0.f);
                            if (round_out) v = f2tf_f(v);
                            Cz[(size_t)rr * ldc + cc] = v;
                        }
                if (Lsum) {
#pragma unroll
                    for (int mf = 0; mf < 2; mf++)
#pragma unroll
                        for (int qh = 0; qh < 2; qh++) {
                            float sv = rowsum[mf][qh];
                            sv += __shfl_xor_sync(~0u, sv, 1);
                            sv += __shfl_xor_sync(~0u, sv, 2);
                            if (tg == 0)
                                atomicAdd(&Lsum[(size_t)tz * L_ + r0 + wm * 32 + mf * 16 + g + qh * 8], sv);
                        }
                }
            }
            __syncthreads();
        }
    }
#endif
}

// --------------------------- merged tf32 rounding pass -----------------------
__global__ void cvt_all_kernel(const float4* x, float4* xr,
                               const float4* wq, const float4* wk, const float4* wv,
                               float4* wqkv,
                               const float4* wu, float4* wur,
                               const float4* w1, float4* w1r,
                               const float4* w2, float4* w2r)
{
    const int WSEG = HD_ * D_ / 4;    // 131072
    const int total = 524288 + 3 * WSEG + WSEG + 2 * 65536;
    for (int i = blockIdx.x * blockDim.x + threadIdx.x; i < total; i += gridDim.x * blockDim.x) {
        const float4* in; float4* out; int j = i;
        if (j < 524288) { in = x; out = xr; }
        else if ((j -= 524288) < WSEG) { in = wq; out = wqkv; }
        else if ((j -= WSEG) < WSEG)   { in = wk; out = wqkv + WSEG; }
        else if ((j -= WSEG) < WSEG)   { in = wv; out = wqkv + 2 * WSEG; }
        else if ((j -= WSEG) < WSEG)   { in = wu; out = wur; }
        else if ((j -= WSEG) < 65536)  { in = w1; out = w1r; }
        else { j -= 65536; in = w2; out = w2r; }
        float4 v = in[j];
        v.x = f2tf_f(v.x); v.y = f2tf_f(v.y); v.z = f2tf_f(v.z); v.w = f2tf_f(v.w);
        out[j] = v;
    }
}

// ---------------- V transpose: Vt[z][e][j] = QKV[b*L+j][4096 + h*256 + e] ----
__global__ void transpose_v(const float* __restrict__ QKV, float* __restrict__ Vt)
{
    __shared__ float t[32][33];
    const int z = blockIdx.z, b = z >> 3, h = z & 7;
    const int j0 = blockIdx.x * 32, e0 = blockIdx.y * 32;
    const int tx = threadIdx.x, ty = threadIdx.y;
#pragma unroll
    for (int k = 0; k < 4; k++)
        t[ty + k * 8][tx] = QKV[(size_t)(b * L_ + j0 + ty + k * 8) * QKVW_ + 2 * HD_ + h * D_ + e0 + tx];
    __syncthreads();
#pragma unroll
    for (int k = 0; k < 4; k++)
        Vt[(size_t)z * D_ * L_ + (size_t)(e0 + ty + k * 8) * L_ + j0 + tx] = t[tx][ty + k * 8];
}

// --------------------------- layernorm over d=256 ----------------------------
__global__ void ln_kernel(const float* __restrict__ in, float* __restrict__ out,
                          float* __restrict__ out_r,
                          const float* __restrict__ g, const float* __restrict__ be)
{
    __shared__ float r1[8], r2[8];
    const int row = blockIdx.x, t = threadIdx.x;
    const float v = in[(size_t)row * D_ + t];
    float s = v, q = v * v;
#pragma unroll
    for (int o = 16; o; o >>= 1) {
        s += __shfl_xor_sync(~0u, s, o);
        q += __shfl_xor_sync(~0u, q, o);
    }
    if ((t & 31) == 0) { r1[t >> 5] = s; r2[t >> 5] = q; }
    __syncthreads();
    float S = 0.f, Q = 0.f;
#pragma unroll
    for (int i = 0; i < 8; i++) { S += r1[i]; Q += r2[i]; }
    const float mean = S * (1.f / D_);
    const float var = Q * (1.f / D_) - mean * mean;
    const float y = (v - mean) * rsqrtf(var + EPS_) * g[t] + be[t];
    out[(size_t)row * D_ + t] = y;
    if (out_r) out_r[(size_t)row * D_ + t] = f2tf_f(y);
}

// --------------------------- host: tensormap encoding ------------------------
typedef CUresult (*EncFn)(CUtensorMap*, CUtensorMapDataType, cuuint32_t, void*,
                          const cuuint64_t*, const cuuint64_t*, const cuuint32_t*,
                          const cuuint32_t*, CUtensorMapInterleave, CUtensorMapSwizzle,
                          CUtensorMapL2promotion, CUtensorMapFloatOOBfill);

static EncFn get_enc() {
    static EncFn fn = nullptr;
    if (!fn) {
        void* p = nullptr;
        cudaDriverEntryPointQueryResult st;
        cudaGetDriverEntryPoint("cuTensorMapEncodeTiled", &p, cudaEnableDefault, &st);
        fn = (EncFn)p;
    }
    return fn;
}

static void mk3d(CUtensorMap* tm, void* ptr,
                 unsigned long long d0, unsigned long long d1, unsigned long long d2,
                 unsigned long long s1B, unsigned long long s2B,
                 unsigned b0, unsigned b1)
{
    cuuint64_t dims[3] = {d0, d1, d2};
    cuuint64_t strides[2] = {s1B, s2B};
    cuuint32_t box[3] = {b0, b1, 1};
    cuuint32_t es[3] = {1, 1, 1};
    get_enc()(tm, CU_TENSOR_MAP_DATA_TYPE_FLOAT32, 3, ptr, dims, strides, box, es,
              CU_TENSOR_MAP_INTERLEAVE_NONE, CU_TENSOR_MAP_SWIZZLE_128B,
              CU_TENSOR_MAP_L2_PROMOTION_L2_128B, CU_TENSOR_MAP_FLOAT_OOB_FILL_NONE);
}

static inline int ncta(int ntiles) { return ntiles < 148 ? ntiles : 148; }

// --------------------------- launch ------------------------------------------
extern "C" void kernel_launch(void* const* d_in, const int* in_sizes, int n_in,
                              void* d_out, int out_size)
{
    const float* x   = (const float*)d_in[0];
    const float* Wq  = (const float*)d_in[1];
    const float* Wk  = (const float*)d_in[2];
    const float* Wv  = (const float*)d_in[3];
    const float* Wu  = (const float*)d_in[4];
    const float* bu  = (const float*)d_in[5];
    const float* W1  = (const float*)d_in[6];
    const float* b1  = (const float*)d_in[7];
    const float* W2  = (const float*)d_in[8];
    const float* b2  = (const float*)d_in[9];
    const float* g1  = (const float*)d_in[10];
    const float* be1 = (const float*)d_in[11];
    const float* g2  = (const float*)d_in[12];
    const float* be2 = (const float*)d_in[13];
    float* out = (float*)d_out;

    float *QKV, *Vt, *S, *O, *R1, *Z1, *Z1r, *Hb, *F, *Lb;
    float *xr, *Wqkvr, *Wur, *W1r, *W2r;
    cudaGetSymbolAddress((void**)&QKV, g_QKV);
    cudaGetSymbolAddress((void**)&Vt, g_Vt);
    cudaGetSymbolAddress((void**)&S,  g_S);
    cudaGetSymbolAddress((void**)&O,  g_O);
    cudaGetSymbolAddress((void**)&R1, g_R1);
    cudaGetSymbolAddress((void**)&Z1, g_Z1);
    cudaGetSymbolAddress((void**)&Z1r, g_Z1r);
    cudaGetSymbolAddress((void**)&Hb, g_Hb);
    cudaGetSymbolAddress((void**)&F,  g_F);
    cudaGetSymbolAddress((void**)&Lb, g_L);
    cudaGetSymbolAddress((void**)&xr,  g_xr);
    cudaGetSymbolAddress((void**)&Wqkvr, g_Wqkvr);
    cudaGetSymbolAddress((void**)&Wur, g_Wur);
    cudaGetSymbolAddress((void**)&W1r, g_W1r);
    cudaGetSymbolAddress((void**)&W2r, g_W2r);

    // ---- tensor maps
    CUtensorMap tXr, tWqkv, tQ, tK, tS, tVt, tO, tWu, tZ1, tW1, tHb, tW2;
    const unsigned long long F4 = sizeof(float);
    mk3d(&tXr,  xr,   D_,   ROWS_, 1,  D_ * F4, 0, 32, 128);
    mk3d(&tWqkv, Wqkvr, D_, QKVW_, 1,  D_ * F4, 0, 32, 256);
    mk3d(&tQ,  QKV,        HD_, L_, B_, (unsigned long long)QKVW_ * F4,
         (unsigned long long)L_ * QKVW_ * F4, 32, 128);
    mk3d(&tK,  QKV + HD_,  HD_, L_, B_, (unsigned long long)QKVW_ * F4,
         (unsigned long long)L_ * QKVW_ * F4, 32, 256);
    mk3d(&tS,  S,  L_, L_, B_ * H_, (unsigned long long)L_ * F4,
         (unsigned long long)L_ * L_ * F4, 32, 128);
    mk3d(&tVt, Vt, L_, D_, B_ * H_, (unsigned long long)L_ * F4,
         (unsigned long long)D_ * L_ * F4, 32, 256);
    mk3d(&tO,  O,   HD_, ROWS_, 1, (unsigned long long)HD_ * F4, 0, 32, 128);
    mk3d(&tWu, Wur, HD_, D_,    1, (unsigned long long)HD_ * F4, 0, 32, 128);
    mk3d(&tZ1, Z1r, D_,  ROWS_, 1, D_ * F4, 0, 32, 128);
    mk3d(&tW1, W1r, D_,  F_,    1, D_ * F4, 0, 32, 256);
    mk3d(&tHb, Hb,  F_,  ROWS_, 1, (unsigned long long)F_ * F4, 0, 32, 128);
    mk3d(&tW2, W2r, F_,  D_,    1, (unsigned long long)F_ * F4, 0, 32, 128);

    constexpr int SM256 = 3 * 49152 + 8 * 32 * 9 * 16 + 128;   // <256,3>
    constexpr int SM128 = 4 * 32768 + 8 * 32 * 9 * 16 + 128;   // <128,4>
    cudaFuncSetAttribute(gemm_tc<256,3>, cudaFuncAttributeMaxDynamicSharedMemorySize, SM256);
    cudaFuncSetAttribute(gemm_tc<128,4>, cudaFuncAttributeMaxDynamicSharedMemorySize, SM128);

    cvt_all_kernel<<<1184, 256>>>((const float4*)x, (float4*)xr,
                                  (const float4*)Wq, (const float4*)Wk, (const float4*)Wv,
                                  (float4*)Wqkvr,
                                  (const float4*)Wu, (float4*)Wur,
                                  (const float4*)W1, (float4*)W1r,
                                  (const float4*)W2, (float4*)W2r);

    const long long LL2 = (long long)L_ * L_;

    // fused QKV: [8192,256] @ [6144,256]^T -> QKV [8192,6144] (rounded)
    gemm_tc<256,3><<<ncta(1536), 320, SM256>>>(tXr, tWqkv, xr, Wqkvr, QKV,
        D_, D_, D_, QKVW_, 0, 0, 0, 0,
        1536, QKVW_/256, 1536, 0, 0,
        nullptr, nullptr, 0, 0, 1, 0.f, nullptr, nullptr);

    transpose_v<<<dim3(L_/32, D_/32, B_*H_), dim3(32, 8)>>>(QKV, Vt);

    // scores + fused exp & row-sum: S = exp(Q@K^T/16), Lb = row sums
    cudaMemsetAsync(Lb, 0, (size_t)B_ * H_ * L_ * sizeof(float));
    gemm_tc<256,3><<<148, 320, SM256>>>(tQ, tK, QKV, QKV + HD_, S,
        D_, QKVW_, QKVW_, L_, (long long)L_ * QKVW_, D_, 8 * LL2, LL2,
        2048, L_/256, 32, 3, 256,
        nullptr, nullptr, 0, 0, 0, 0.0625f, Lb, nullptr);

    // PV: O = (S @ Vt^T) / rowsum  (rounded)
    gemm_tc<256,3><<<148, 320, SM256>>>(tS, tVt, S, Vt, O,
        L_, L_, L_, HD_, (long long)L_ * HD_, D_, (long long)L_ * HD_, D_,
        512, 1, 8, 0, 0,
        nullptr, nullptr, 0, 0, 1, 0.f, nullptr, Lb);

    // output projection + bias + residual(x)
    gemm_tc<128,4><<<ncta(128), 320, SM128>>>(tO, tWu, O, Wur, R1,
        HD_, HD_, HD_, D_, 0, 0, 0, 0,
        128, D_/128, 128, 0, 0,
        bu, x, D_, 0, 0, 0.f, nullptr, nullptr);
    ln_kernel<<<ROWS_, 256>>>(R1, Z1, Z1r, g1, be1);

    // FFN
    gemm_tc<256,3><<<ncta(256), 320, SM256>>>(tZ1, tW1, Z1r, W1r, Hb,
        D_, D_, D_, F_, 0, 0, 0, 0,
        256, F_/256, 256, 0, 0,
        b1, nullptr, 0, 1, 1, 0.f, nullptr, nullptr);
    gemm_tc<128,4><<<ncta(128), 320, SM128>>>(tHb, tW2, Hb, W2r, F,
        F_, F_, F_, D_, 0, 0, 0, 0,
        128, D_/128, 128, 0, 0,
        b2, Z1, D_, 0, 0, 0.f, nullptr, nullptr);
    ln_kernel<<<ROWS_, 256>>>(F, out, nullptr, g2, be2);
}

// round 15
// speedup vs baseline: 2.7812x; 1.2650x over previous
#include <cuda_runtime.h>
#include <cuda.h>
#include <cuda_bf16.h>
#include <cstdint>

#define B_  8
#define L_  1024
#define D_  256
#define H_  8
#define HD_ 2048
#define QKVW_ 6144
#define F_  1024
#define ROWS_ (B_*L_)
#define EPS_ 1e-5f

#if defined(__CUDA_ARCH_FEAT_SM103_ALL) || defined(__CUDA_ARCH_FEAT_SM100_ALL)
#define TC_OK 1
#else
#define TC_OK 0
#endif

// --------------------------- scratch (device globals) ------------------------
__device__ __nv_bfloat16 g_QKVh[(size_t)ROWS_ * QKVW_];   // bf16 QKV [row, 3*HD]
__device__ __nv_bfloat16 g_Vth[(size_t)B_ * H_ * D_ * L_]; // bf16 Vt [z][e][j]
__device__ __nv_bfloat16 g_Sh[(size_t)B_ * H_ * L_ * L_];  // bf16 probs
__device__ float g_O[(size_t)ROWS_ * HD_];
__device__ float g_R1[(size_t)ROWS_ * D_];
__device__ float g_Z1[(size_t)ROWS_ * D_];
__device__ float g_Z1r[(size_t)ROWS_ * D_];
__device__ float g_Hb[(size_t)ROWS_ * F_];
__device__ float g_F[(size_t)ROWS_ * D_];
__device__ float g_L[(size_t)B_ * H_ * L_];
__device__ float g_xr[(size_t)ROWS_ * D_];
__device__ float g_Wqkvr[(size_t)QKVW_ * D_];
__device__ float g_Wur[(size_t)D_ * HD_];
__device__ float g_W1r[(size_t)F_ * D_];
__device__ float g_W2r[(size_t)D_ * F_];

// --------------------------- common helpers ----------------------------------
__device__ __forceinline__ uint32_t f2tf(float f) {
    uint32_t u; asm("cvt.rna.tf32.f32 %0, %1;" : "=r"(u) : "f"(f)); return u;
}
__device__ __forceinline__ float f2tf_f(float f) { return __uint_as_float(f2tf(f)); }
__device__ __forceinline__ float bf16r(float f) {
    return __bfloat162float(__float2bfloat16(f));
}

#if TC_OK
// --------------------------- tcgen05/TMA helpers (sm_103a pass only) ---------
__device__ __forceinline__ bool elect1() {
    uint32_t p;
    asm volatile("{\n\t.reg .pred p;\n\telect.sync _|p, 0xFFFFFFFF;\n\tselp.b32 %0,1,0,p;\n\t}" : "=r"(p));
    return p != 0;
}
__device__ __forceinline__ void mbar_init(uint32_t a, uint32_t cnt) {
    asm volatile("mbarrier.init.shared.b64 [%0], %1;" :: "r"(a), "r"(cnt) : "memory");
}
__device__ __forceinline__ void mbar_wait(uint32_t a, uint32_t parity) {
    asm volatile(
        "{\n\t.reg .pred P;\n\t"
        "WL%=:\n\t"
        "mbarrier.try_wait.parity.acquire.cta.shared::cta.b64 P, [%0], %1, 0x989680;\n\t"
        "@P bra WD%=;\n\t"
        "bra WL%=;\n\t"
        "WD%=:\n\t}"
        :: "r"(a), "r"(parity) : "memory");
}
__device__ __forceinline__ void mbar_arrive(uint32_t a) {
    asm volatile("mbarrier.arrive.shared.b64 _, [%0];" :: "r"(a) : "memory");
}
__device__ __forceinline__ void mbar_expect_tx(uint32_t a, uint32_t bytes) {
    asm volatile("mbarrier.arrive.expect_tx.shared.b64 _, [%0], %1;"
                 :: "r"(a), "r"(bytes) : "memory");
}
__device__ __forceinline__ void tma3d(uint32_t smem, const void* tm,
                                      int c0, int c1, int c2, uint32_t mbar) {
    asm volatile(
        "cp.async.bulk.tensor.3d.shared::cta.global.tile.mbarrier::complete_tx::bytes "
        "[%0], [%1, {%2, %3, %4}], [%5];"
        :: "r"(smem), "l"(tm), "r"(c0), "r"(c1), "r"(c2), "r"(mbar) : "memory");
}
__device__ __forceinline__ void tc_fence_after() {
    asm volatile("tcgen05.fence::after_thread_sync;" ::: "memory");
}
__device__ __forceinline__ void tcalloc(uint32_t smem_addr, uint32_t ncols) {
    asm volatile("tcgen05.alloc.cta_group::1.sync.aligned.shared::cta.b32 [%0], %1;"
                 :: "r"(smem_addr), "r"(ncols) : "memory");
}
__device__ __forceinline__ void tcdealloc(uint32_t tmem, uint32_t ncols) {
    asm volatile("tcgen05.dealloc.cta_group::1.sync.aligned.b32 %0, %1;" :: "r"(tmem), "r"(ncols));
}
__device__ __forceinline__ void tcrelinquish() {
    asm volatile("tcgen05.relinquish_alloc_permit.cta_group::1.sync.aligned;");
}
__device__ __forceinline__ void tc_commit(uint32_t mbar) {
    asm volatile("tcgen05.commit.cta_group::1.mbarrier::arrive::one.shared::cluster.b64 [%0];"
                 :: "r"(mbar) : "memory");
}
__device__ __forceinline__ void wait_ld() {
    asm volatile("tcgen05.wait::ld.sync.aligned;" ::: "memory");
}
__device__ __forceinline__ void mma_tf32_ss(uint32_t d, uint64_t ad, uint64_t bd,
                                            uint32_t idesc, uint32_t en) {
    asm volatile(
        "{\n\t.reg .pred p;\n\tsetp.ne.u32 p, %4, 0;\n\t"
        "tcgen05.mma.cta_group::1.kind::tf32 [%0], %1, %2, %3, {%5,%5,%5,%5}, p;\n\t}"
        :: "r"(d), "l"(ad), "l"(bd), "r"(idesc), "r"(en), "r"(0u) : "memory");
}
__device__ __forceinline__ void mma_f16_ss(uint32_t d, uint64_t ad, uint64_t bd,
                                           uint32_t idesc, uint32_t en) {
    asm volatile(
        "{\n\t.reg .pred p;\n\tsetp.ne.u32 p, %4, 0;\n\t"
        "tcgen05.mma.cta_group::1.kind::f16 [%0], %1, %2, %3, {%5,%5,%5,%5}, p;\n\t}"
        :: "r"(d), "l"(ad), "l"(bd), "r"(idesc), "r"(en), "r"(0u) : "memory");
}
__device__ __forceinline__ void ldtm32(uint32_t* r, uint32_t a) {
    asm volatile(
        "tcgen05.ld.sync.aligned.32x32b.x32.b32 "
        "{%0,%1,%2,%3,%4,%5,%6,%7,%8,%9,%10,%11,%12,%13,%14,%15,"
        "%16,%17,%18,%19,%20,%21,%22,%23,%24,%25,%26,%27,%28,%29,%30,%31}, [%32];"
        : "=r"(r[0]), "=r"(r[1]), "=r"(r[2]), "=r"(r[3]),
          "=r"(r[4]), "=r"(r[5]), "=r"(r[6]), "=r"(r[7]),
          "=r"(r[8]), "=r"(r[9]), "=r"(r[10]), "=r"(r[11]),
          "=r"(r[12]), "=r"(r[13]), "=r"(r[14]), "=r"(r[15]),
          "=r"(r[16]), "=r"(r[17]), "=r"(r[18]), "=r"(r[19]),
          "=r"(r[20]), "=r"(r[21]), "=r"(r[22]), "=r"(r[23]),
          "=r"(r[24]), "=r"(r[25]), "=r"(r[26]), "=r"(r[27]),
          "=r"(r[28]), "=r"(r[29]), "=r"(r[30]), "=r"(r[31])
        : "r"(a));
}
static constexpr uint64_t DESC_BASE =
    (uint64_t(2) << 61) | (uint64_t(1) << 46) | (uint64_t(64) << 32) | (uint64_t(1) << 16);
__device__ __forceinline__ uint64_t mk_desc(uint32_t a) {
    return DESC_BASE | ((uint64_t)(a >> 4) & 0x3FFFull);
}
#endif // TC_OK

// ============================================================================
// Persistent GEMM: C = A @ B^T, tile 128 x NT, 128B K-chunks, NST-stage TMA
// pipeline, double-buffered TMEM accumulators. EB = element bytes of A/B
// (4 = tf32, 2 = bf16/kind::f16). OBF = write bf16 output.
// 320 threads: w0 TMA producer, w1 MMA issuer, w2-9 epilogue.
// Tile t -> tz = t/gxy, ty = (t%gxy)/gx, tx = (t%gxy)%gx.
// ============================================================================
template<int NT, int NST, int EB, int OBF>
__global__ __launch_bounds__(320, 1)
void gemm_tc(const __grid_constant__ CUtensorMap tmA,
             const __grid_constant__ CUtensorMap tmB,
             void* __restrict__ Cv, int K, int ldc,
             long long sC1, long long sC2,
             int ntiles, int gx, int gxy, int zsh, int koMul,
             const float* __restrict__ bias, const float* __restrict__ resid, int ldres,
             int relu, int round_out, float escale,
             float* __restrict__ Lsum, const float* __restrict__ Ldiv)
{
    extern __shared__ __align__(1024) uint8_t smraw[];

    const int tid = threadIdx.x, wid = tid >> 5, lane = tid & 31;
    const int nCTA = gridDim.x, bx = blockIdx.x;
    const int KCE = 128 / EB;                  // K elems per chunk
    const int T = K / KCE;

#if TC_OK
    constexpr int ABYTES = 16384;
    constexpr int BBYTES = NT * 128;
    constexpr int STGB = ABYTES + BBYTES;
    constexpr int EPIOFF = NST * STGB;
    constexpr int CTRL = EPIOFF + 8 * 32 * 9 * 16;
    constexpr uint32_t TYC = (EB == 4) ? 2u : 1u;
    constexpr uint32_t IDESC =
        (1u << 4) | (TYC << 7) | (TYC << 10) | ((uint32_t)(NT / 8) << 17) | (8u << 24);

    const uint32_t smb  = (uint32_t)__cvta_generic_to_shared(smraw);
    const uint32_t tptr = smb + CTRL;
    const uint32_t mbF  = tptr + 8;
    const uint32_t mbE  = mbF + 8 * NST;
    const uint32_t mbD  = mbE + 8 * NST;
    const uint32_t mbR  = mbD + 16;

    if (wid == 0) tcalloc(tptr, 512);
    if (tid == 0) {
        for (int s = 0; s < NST; ++s) { mbar_init(mbF + 8 * s, 1); mbar_init(mbE + 8 * s, 1); }
        mbar_init(mbD, 1);     mbar_init(mbD + 8, 1);
        mbar_init(mbR, 8);     mbar_init(mbR + 8, 8);
    }
    __syncthreads();
    uint32_t tmem;
    asm volatile("ld.shared.b32 %0, [%1];" : "=r"(tmem) : "r"(tptr));

    if (wid == 0) {
        if (elect1()) {
            int eph[NST];
#pragma unroll
            for (int s = 0; s < NST; ++s) eph[s] = 1;
            int s = 0;
            for (int t = bx; t < ntiles; t += nCTA) {
                const int tz = t / gxy, rem = t - tz * gxy;
                const int ty = rem / gx, tx = rem - ty * gx;
                const int row0 = ty * 128, col0 = tx * NT;
                const int zA = tz >> zsh;
                const int ko = (tz & ((1 << zsh) - 1)) * koMul;
                for (int c = 0; c < T; ++c) {
                    mbar_wait(mbE + 8 * s, eph[s]); eph[s] ^= 1;
                    const uint32_t bA = smb + s * STGB;
                    const uint32_t fb = mbF + 8 * s;
                    const int kc = ko + c * KCE;
                    mbar_expect_tx(fb, STGB);
                    tma3d(bA, &tmA, kc, row0, zA, fb);
                    tma3d(bA + ABYTES, &tmB, kc, col0, zA, fb);
                    if (++s == NST) s = 0;
                }
            }
        }
    } else if (wid == 1) {
        if (elect1()) {
            int fph[NST];
#pragma unroll
            for (int s = 0; s < NST; ++s) fph[s] = 0;
            int phF[2] = {1, 1};
            int s = 0, pk = 0;
            for (int t = bx; t < ntiles; t += nCTA) {
                const int p = pk & 1;
                mbar_wait(mbR + 8 * p, phF[p]); phF[p] ^= 1;
                const uint32_t dacc = tmem + p * NT;
                for (int c = 0; c < T; ++c) {
                    mbar_wait(mbF + 8 * s, fph[s]); fph[s] ^= 1;
                    const uint32_t bA = smb + s * STGB, bB = bA + ABYTES;
                    const uint64_t ad = mk_desc(bA), bd = mk_desc(bB);
#pragma unroll
                    for (int k8 = 0; k8 < 4; ++k8) {
                        const uint32_t en = (c > 0 || k8 > 0) ? 1u : 0u;
                        if (EB == 4) mma_tf32_ss(dacc, ad + 2 * k8, bd + 2 * k8, IDESC, en);
                        else         mma_f16_ss (dacc, ad + 2 * k8, bd + 2 * k8, IDESC, en);
                    }
                    tc_commit(mbE + 8 * s);
                    if (++s == NST) s = 0;
                }
                tc_commit(mbD + 8 * p);
                ++pk;
            }
        }
    } else {
        const int ew = wid - 2;
        const int sub = wid & 3;
        const int colhalf = ew >> 2;
        const int cbN = NT / 64;
        float4* wsm4 = (float4*)(smraw + EPIOFF) + ew * (32 * 9);
        int phD[2] = {0, 0};
        int pk = 0;
        for (int t = bx; t < ntiles; t += nCTA) {
            const int tz = t / gxy, rem = t - tz * gxy;
            const int ty = rem / gx, tx = rem - ty * gx;
            const int row0 = ty * 128, col0 = tx * NT;
            const size_t coff = (size_t)(tz >> 3) * sC1 + (size_t)(tz & 7) * sC2;
            const int p = pk & 1;
            mbar_wait(mbD + 8 * p, phD[p]); phD[p] ^= 1;
            tc_fence_after();

            float rowsum = 0.f;
#pragma unroll 1
            for (int ci = 0; ci < cbN; ++ci) {
                const int cb = colhalf * cbN + ci;
                uint32_t rg[32];
                ldtm32(rg, tmem + p * NT + cb * 32);
                wait_ld();
                if (Lsum) {
#pragma unroll
                    for (int j = 0; j < 32; ++j) {
                        float v = bf16r(__expf(__uint_as_float(rg[j]) * escale));
                        rowsum += v;
                        rg[j] = __float_as_uint(v);
                    }
                }
                __syncwarp();
#pragma unroll
                for (int jq = 0; jq < 8; ++jq)
                    wsm4[lane * 9 + jq] = make_float4(__uint_as_float(rg[jq * 4 + 0]),
                                                      __uint_as_float(rg[jq * 4 + 1]),
                                                      __uint_as_float(rg[jq * 4 + 2]),
                                                      __uint_as_float(rg[jq * 4 + 3]));
                __syncwarp();
                const int cq = lane & 7, rsub = lane >> 3;
#pragma unroll 1
                for (int it = 0; it < 8; ++it) {
                    const int r = it * 4 + rsub;
                    float4 v = wsm4[r * 9 + cq];
                    const int orow = row0 + sub * 32 + r;
                    const int ocol = col0 + cb * 32 + cq * 4;
                    if (bias) {
                        const float4 bv = *(const float4*)&bias[ocol];
                        v.x += bv.x; v.y += bv.y; v.z += bv.z; v.w += bv.w;
                    }
                    if (resid) {
                        const float4 rv = *(const float4*)&resid[(size_t)orow * ldres + ocol];
                        v.x += rv.x; v.y += rv.y; v.z += rv.z; v.w += rv.w;
                    }
                    if (Ldiv) {
                        const float inv = __frcp_rn(Ldiv[(size_t)tz * L_ + orow]);
                        v.x *= inv; v.y *= inv; v.z *= inv; v.w *= inv;
                    }
                    if (relu) {
                        v.x = fmaxf(v.x, 0.f); v.y = fmaxf(v.y, 0.f);
                        v.z = fmaxf(v.z, 0.f); v.w = fmaxf(v.w, 0.f);
                    }
                    if (round_out) {
                        v.x = f2tf_f(v.x); v.y = f2tf_f(v.y);
                        v.z = f2tf_f(v.z); v.w = f2tf_f(v.w);
                    }
                    if (OBF) {
                        __nv_bfloat16* Ch = (__nv_bfloat16*)Cv + coff;
                        __nv_bfloat162 p0 = __floats2bfloat162_rn(v.x, v.y);
                        __nv_bfloat162 p1 = __floats2bfloat162_rn(v.z, v.w);
                        uint2 u = make_uint2(*(uint32_t*)&p0, *(uint32_t*)&p1);
                        *(uint2*)&Ch[(size_t)orow * ldc + ocol] = u;
                    } else {
                        float* Cf = (float*)Cv + coff;
                        *(float4*)&Cf[(size_t)orow * ldc + ocol] = v;
                    }
                }
                __syncwarp();
            }
            if (Lsum) atomicAdd(&Lsum[(size_t)tz * L_ + row0 + sub * 32 + lane], rowsum);
            __syncwarp();
            if (lane == 0) mbar_arrive(mbR + 8 * p);
            ++pk;
        }
    }

    __syncthreads();
    if (wid == 0) { tcrelinquish(); tcdealloc(tmem, 512); }
#else
    // compile-only stub for the compute_103 PTX pass (runtime uses sm_103a cubin)
    (void)Cv; (void)K; (void)ldc; (void)sC1; (void)sC2; (void)ntiles; (void)gx;
    (void)gxy; (void)zsh; (void)koMul; (void)bias; (void)resid; (void)ldres;
    (void)relu; (void)round_out; (void)escale; (void)Lsum; (void)Ldiv;
    (void)T; (void)KCE; (void)nCTA; (void)bx; (void)lane; (void)wid;
#endif
}

// --------------------------- merged tf32 rounding pass -----------------------
__global__ void cvt_all_kernel(const float4* x, float4* xr,
                               const float4* wq, const float4* wk, const float4* wv,
                               float4* wqkv,
                               const float4* wu, float4* wur,
                               const float4* w1, float4* w1r,
                               const float4* w2, float4* w2r)
{
    const int WSEG = HD_ * D_ / 4;
    const int total = 524288 + 4 * WSEG + 2 * 65536;
    for (int i = blockIdx.x * blockDim.x + threadIdx.x; i < total; i += gridDim.x * blockDim.x) {
        const float4* in; float4* out; int j = i;
        if (j < 524288) { in = x; out = xr; }
        else if ((j -= 524288) < WSEG) { in = wq; out = wqkv; }
        else if ((j -= WSEG) < WSEG)   { in = wk; out = wqkv + WSEG; }
        else if ((j -= WSEG) < WSEG)   { in = wv; out = wqkv + 2 * WSEG; }
        else if ((j -= WSEG) < WSEG)   { in = wu; out = wur; }
        else if ((j -= WSEG) < 65536)  { in = w1; out = w1r; }
        else { j -= 65536; in = w2; out = w2r; }
        float4 v = in[j];
        v.x = f2tf_f(v.x); v.y = f2tf_f(v.y); v.z = f2tf_f(v.z); v.w = f2tf_f(v.w);
        out[j] = v;
    }
}

// -------- V transpose (bf16): Vt[z][e][j] = QKV[b*L+j][2*HD + h*256 + e] -----
__global__ void transpose_v(const __nv_bfloat16* __restrict__ QKV,
                            __nv_bfloat16* __restrict__ Vt)
{
    __shared__ __nv_bfloat16 t[32][33];
    const int z = blockIdx.z, b = z >> 3, h = z & 7;
    const int j0 = blockIdx.x * 32, e0 = blockIdx.y * 32;
    const int tx = threadIdx.x, ty = threadIdx.y;
#pragma unroll
    for (int k = 0; k < 4; k++)
        t[ty + k * 8][tx] = QKV[(size_t)(b * L_ + j0 + ty + k * 8) * QKVW_ + 2 * HD_ + h * D_ + e0 + tx];
    __syncthreads();
#pragma unroll
    for (int k = 0; k < 4; k++)
        Vt[(size_t)z * D_ * L_ + (size_t)(e0 + ty + k * 8) * L_ + j0 + tx] = t[tx][ty + k * 8];
}

// --------------------------- layernorm over d=256 ----------------------------
__global__ void ln_kernel(const float* __restrict__ in, float* __restrict__ out,
                          float* __restrict__ out_r,
                          const float* __restrict__ g, const float* __restrict__ be)
{
    __shared__ float r1[8], r2[8];
    const int row = blockIdx.x, t = threadIdx.x;
    const float v = in[(size_t)row * D_ + t];
    float s = v, q = v * v;
#pragma unroll
    for (int o = 16; o; o >>= 1) {
        s += __shfl_xor_sync(~0u, s, o);
        q += __shfl_xor_sync(~0u, q, o);
    }
    if ((t & 31) == 0) { r1[t >> 5] = s; r2[t >> 5] = q; }
    __syncthreads();
    float S = 0.f, Q = 0.f;
#pragma unroll
    for (int i = 0; i < 8; i++) { S += r1[i]; Q += r2[i]; }
    const float mean = S * (1.f / D_);
    const float var = Q * (1.f / D_) - mean * mean;
    const float y = (v - mean) * rsqrtf(var + EPS_) * g[t] + be[t];
    out[(size_t)row * D_ + t] = y;
    if (out_r) out_r[(size_t)row * D_ + t] = f2tf_f(y);
}

// --------------------------- host: tensormap encoding ------------------------
typedef CUresult (*EncFn)(CUtensorMap*, CUtensorMapDataType, cuuint32_t, void*,
                          const cuuint64_t*, const cuuint64_t*, const cuuint32_t*,
                          const cuuint32_t*, CUtensorMapInterleave, CUtensorMapSwizzle,
                          CUtensorMapL2promotion, CUtensorMapFloatOOBfill);

static EncFn get_enc() {
    static EncFn fn = nullptr;
    if (!fn) {
        void* p = nullptr;
        cudaDriverEntryPointQueryResult st;
        cudaGetDriverEntryPoint("cuTensorMapEncodeTiled", &p, cudaEnableDefault, &st);
        fn = (EncFn)p;
    }
    return fn;
}

static void mk3d(CUtensorMap* tm, void* ptr, CUtensorMapDataType dt,
                 unsigned long long d0, unsigned long long d1, unsigned long long d2,
                 unsigned long long s1B, unsigned long long s2B,
                 unsigned b0, unsigned b1)
{
    cuuint64_t dims[3] = {d0, d1, d2};
    cuuint64_t strides[2] = {s1B, s2B};
    cuuint32_t box[3] = {b0, b1, 1};
    cuuint32_t es[3] = {1, 1, 1};
    get_enc()(tm, dt, 3, ptr, dims, strides, box, es,
              CU_TENSOR_MAP_INTERLEAVE_NONE, CU_TENSOR_MAP_SWIZZLE_128B,
              CU_TENSOR_MAP_L2_PROMOTION_L2_128B, CU_TENSOR_MAP_FLOAT_OOB_FILL_NONE);
}

static inline int ncta(int ntiles) { return ntiles < 148 ? ntiles : 148; }

// --------------------------- launch ------------------------------------------
extern "C" void kernel_launch(void* const* d_in, const int* in_sizes, int n_in,
                              void* d_out, int out_size)
{
    const float* x   = (const float*)d_in[0];
    const float* Wq  = (const float*)d_in[1];
    const float* Wk  = (const float*)d_in[2];
    const float* Wv  = (const float*)d_in[3];
    const float* Wu  = (const float*)d_in[4];
    const float* bu  = (const float*)d_in[5];
    const float* W1  = (const float*)d_in[6];
    const float* b1  = (const float*)d_in[7];
    const float* W2  = (const float*)d_in[8];
    const float* b2  = (const float*)d_in[9];
    const float* g1  = (const float*)d_in[10];
    const float* be1 = (const float*)d_in[11];
    const float* g2  = (const float*)d_in[12];
    const float* be2 = (const float*)d_in[13];
    float* out = (float*)d_out;

    __nv_bfloat16 *QKVh, *Vth, *Sh;
    float *O, *R1, *Z1, *Z1r, *Hb, *F, *Lb, *xr, *Wqkvr, *Wur, *W1r, *W2r;
    cudaGetSymbolAddress((void**)&QKVh, g_QKVh);
    cudaGetSymbolAddress((void**)&Vth, g_Vth);
    cudaGetSymbolAddress((void**)&Sh,  g_Sh);
    cudaGetSymbolAddress((void**)&O,  g_O);
    cudaGetSymbolAddress((void**)&R1, g_R1);
    cudaGetSymbolAddress((void**)&Z1, g_Z1);
    cudaGetSymbolAddress((void**)&Z1r, g_Z1r);
    cudaGetSymbolAddress((void**)&Hb, g_Hb);
    cudaGetSymbolAddress((void**)&F,  g_F);
    cudaGetSymbolAddress((void**)&Lb, g_L);
    cudaGetSymbolAddress((void**)&xr,  g_xr);
    cudaGetSymbolAddress((void**)&Wqkvr, g_Wqkvr);
    cudaGetSymbolAddress((void**)&Wur, g_Wur);
    cudaGetSymbolAddress((void**)&W1r, g_W1r);
    cudaGetSymbolAddress((void**)&W2r, g_W2r);

    // ---- tensor maps
    CUtensorMap tXr, tWqkv, tQ, tK, tS, tVt, tO, tWu, tZ1, tW1, tHb, tW2;
    const unsigned long long F4 = 4, F2 = 2;
    const CUtensorMapDataType DF = CU_TENSOR_MAP_DATA_TYPE_FLOAT32;
    const CUtensorMapDataType DB = CU_TENSOR_MAP_DATA_TYPE_BFLOAT16;
    mk3d(&tXr,  xr,   DF, D_, ROWS_, 1, D_ * F4, 0, 32, 128);
    mk3d(&tWqkv, Wqkvr, DF, D_, QKVW_, 1, D_ * F4, 0, 32, 256);
    mk3d(&tQ, QKVh,       DB, HD_, L_, B_, (unsigned long long)QKVW_ * F2,
         (unsigned long long)L_ * QKVW_ * F2, 64, 128);
    mk3d(&tK, QKVh + HD_, DB, HD_, L_, B_, (unsigned long long)QKVW_ * F2,
         (unsigned long long)L_ * QKVW_ * F2, 64, 256);
    mk3d(&tS, Sh,  DB, L_, L_, B_ * H_, (unsigned long long)L_ * F2,
         (unsigned long long)L_ * L_ * F2, 64, 128);
    mk3d(&tVt, Vth, DB, L_, D_, B_ * H_, (unsigned long long)L_ * F2,
         (unsigned long long)D_ * L_ * F2, 64, 256);
    mk3d(&tO,  O,   DF, HD_, ROWS_, 1, (unsigned long long)HD_ * F4, 0, 32, 128);
    mk3d(&tWu, Wur, DF, HD_, D_,    1, (unsigned long long)HD_ * F4, 0, 32, 128);
    mk3d(&tZ1, Z1r, DF, D_,  ROWS_, 1, D_ * F4, 0, 32, 128);
    mk3d(&tW1, W1r, DF, D_,  F_,    1, D_ * F4, 0, 32, 256);
    mk3d(&tHb, Hb,  DF, F_,  ROWS_, 1, (unsigned long long)F_ * F4, 0, 32, 128);
    mk3d(&tW2, W2r, DF, F_,  D_,    1, (unsigned long long)F_ * F4, 0, 32, 128);

    constexpr int SM256 = 3 * 49152 + 8 * 32 * 9 * 16 + 128;
    constexpr int SM128 = 4 * 32768 + 8 * 32 * 9 * 16 + 128;
    cudaFuncSetAttribute(gemm_tc<256,3,4,1>, cudaFuncAttributeMaxDynamicSharedMemorySize, SM256);
    cudaFuncSetAttribute(gemm_tc<256,3,2,1>, cudaFuncAttributeMaxDynamicSharedMemorySize, SM256);
    cudaFuncSetAttribute(gemm_tc<256,3,2,0>, cudaFuncAttributeMaxDynamicSharedMemorySize, SM256);
    cudaFuncSetAttribute(gemm_tc<256,3,4,0>, cudaFuncAttributeMaxDynamicSharedMemorySize, SM256);
    cudaFuncSetAttribute(gemm_tc<128,4,4,0>, cudaFuncAttributeMaxDynamicSharedMemorySize, SM128);

    cvt_all_kernel<<<1184, 256>>>((const float4*)x, (float4*)xr,
                                  (const float4*)Wq, (const float4*)Wk, (const float4*)Wv,
                                  (float4*)Wqkvr,
                                  (const float4*)Wu, (float4*)Wur,
                                  (const float4*)W1, (float4*)W1r,
                                  (const float4*)W2, (float4*)W2r);

    const long long LL2 = (long long)L_ * L_;

    // fused QKV: [8192,256] @ [6144,256]^T -> QKVh bf16 [8192,6144]
    gemm_tc<256,3,4,1><<<148, 320, SM256>>>(tXr, tWqkv, QKVh,
        D_, QKVW_, 0, 0,
        1536, 24, 1536, 0, 0,
        nullptr, nullptr, 0, 0, 0, 0.f, nullptr, nullptr);

    transpose_v<<<dim3(L_/32, D_/32, B_*H_), dim3(32, 8)>>>(QKVh, Vth);

    // scores (bf16 in/out) + fused exp & row-sum
    cudaMemsetAsync(Lb, 0, (size_t)B_ * H_ * L_ * sizeof(float));
    gemm_tc<256,3,2,1><<<148, 320, SM256>>>(tQ, tK, Sh,
        D_, L_, 8 * LL2, LL2,
        2048, 4, 32, 3, 256,
        nullptr, nullptr, 0, 0, 0, 0.0625f, Lb, nullptr);

    // PV (bf16 in, f32 out): O = (S @ Vt^T) / rowsum, tf32-rounded
    gemm_tc<256,3,2,0><<<148, 320, SM256>>>(tS, tVt, O,
        L_, HD_, (long long)L_ * HD_, D_,
        512, 1, 8, 0, 0,
        nullptr, nullptr, 0, 0, 1, 0.f, nullptr, Lb);

    // output projection + bias + residual(x)
    gemm_tc<128,4,4,0><<<128, 320, SM128>>>(tO, tWu, R1,
        HD_, D_, 0, 0,
        128, 2, 128, 0, 0,
        bu, x, D_, 0, 0, 0.f, nullptr, nullptr);
    ln_kernel<<<ROWS_, 256>>>(R1, Z1, Z1r, g1, be1);

    // FFN
    gemm_tc<256,3,4,0><<<148, 320, SM256>>>(tZ1, tW1, Hb,
        D_, F_, 0, 0,
        256, 4, 256, 0, 0,
        b1, nullptr, 0, 1, 1, 0.f, nullptr, nullptr);
    gemm_tc<128,4,4,0><<<128, 320, SM128>>>(tHb, tW2, F,
        F_, D_, 0, 0,
        128, 2, 128, 0, 0,
        b2, Z1, D_, 0, 0, 0.f, nullptr, nullptr);
    ln_kernel<<<ROWS_, 256>>>(F, out, nullptr, g2, be2);
}

// round 17
// speedup vs baseline: 3.2375x; 1.1641x over previous
#include <cuda_runtime.h>
#include <cuda.h>
#include <cuda_bf16.h>
#include <cstdint>

#define B_  8
#define L_  1024
#define D_  256
#define H_  8
#define HD_ 2048
#define QKVW_ 6144
#define F_  1024
#define ROWS_ (B_*L_)
#define EPS_ 1e-5f

#if defined(__CUDA_ARCH_FEAT_SM103_ALL) || defined(__CUDA_ARCH_FEAT_SM100_ALL)
#define TC_OK 1
#else
#define TC_OK 0
#endif

// --------------------------- scratch (device globals) ------------------------
__device__ __nv_bfloat16 g_QKVh[(size_t)ROWS_ * QKVW_];
__device__ __nv_bfloat16 g_Vth[(size_t)B_ * H_ * D_ * L_];
__device__ float g_O[(size_t)ROWS_ * HD_];
__device__ float g_R1[(size_t)ROWS_ * D_];
__device__ float g_Z1[(size_t)ROWS_ * D_];
__device__ float g_Z1r[(size_t)ROWS_ * D_];
__device__ float g_Hb[(size_t)ROWS_ * F_];
__device__ float g_F[(size_t)ROWS_ * D_];
__device__ float g_xr[(size_t)ROWS_ * D_];
__device__ float g_Wqkvr[(size_t)QKVW_ * D_];
__device__ float g_Wur[(size_t)D_ * HD_];
__device__ float g_W1r[(size_t)F_ * D_];
__device__ float g_W2r[(size_t)D_ * F_];

// --------------------------- common helpers ----------------------------------
__device__ __forceinline__ uint32_t f2tf(float f) {
    uint32_t u; asm("cvt.rna.tf32.f32 %0, %1;" : "=r"(u) : "f"(f)); return u;
}
__device__ __forceinline__ float f2tf_f(float f) { return __uint_as_float(f2tf(f)); }
__device__ __forceinline__ float bf16r(float f) {
    return __bfloat162float(__float2bfloat16(f));
}

#if TC_OK
// --------------------------- tcgen05/TMA helpers -----------------------------
__device__ __forceinline__ bool elect1() {
    uint32_t p;
    asm volatile("{\n\t.reg .pred p;\n\telect.sync _|p, 0xFFFFFFFF;\n\tselp.b32 %0,1,0,p;\n\t}" : "=r"(p));
    return p != 0;
}
__device__ __forceinline__ void mbar_init(uint32_t a, uint32_t cnt) {
    asm volatile("mbarrier.init.shared.b64 [%0], %1;" :: "r"(a), "r"(cnt) : "memory");
}
__device__ __forceinline__ void mbar_wait(uint32_t a, uint32_t parity) {
    asm volatile(
        "{\n\t.reg .pred P;\n\t"
        "WL%=:\n\t"
        "mbarrier.try_wait.parity.acquire.cta.shared::cta.b64 P, [%0], %1, 0x989680;\n\t"
        "@P bra WD%=;\n\t"
        "bra WL%=;\n\t"
        "WD%=:\n\t}"
        :: "r"(a), "r"(parity) : "memory");
}
__device__ __forceinline__ void mbar_arrive(uint32_t a) {
    asm volatile("mbarrier.arrive.shared.b64 _, [%0];" :: "r"(a) : "memory");
}
__device__ __forceinline__ void mbar_expect_tx(uint32_t a, uint32_t bytes) {
    asm volatile("mbarrier.arrive.expect_tx.shared.b64 _, [%0], %1;"
                 :: "r"(a), "r"(bytes) : "memory");
}
__device__ __forceinline__ void tma3d(uint32_t smem, const void* tm,
                                      int c0, int c1, int c2, uint32_t mbar) {
    asm volatile(
        "cp.async.bulk.tensor.3d.shared::cta.global.tile.mbarrier::complete_tx::bytes "
        "[%0], [%1, {%2, %3, %4}], [%5];"
        :: "r"(smem), "l"(tm), "r"(c0), "r"(c1), "r"(c2), "r"(mbar) : "memory");
}
__device__ __forceinline__ void tc_fence_after() {
    asm volatile("tcgen05.fence::after_thread_sync;" ::: "memory");
}
__device__ __forceinline__ void tcalloc(uint32_t smem_addr, uint32_t ncols) {
    asm volatile("tcgen05.alloc.cta_group::1.sync.aligned.shared::cta.b32 [%0], %1;"
                 :: "r"(smem_addr), "r"(ncols) : "memory");
}
__device__ __forceinline__ void tcdealloc(uint32_t tmem, uint32_t ncols) {
    asm volatile("tcgen05.dealloc.cta_group::1.sync.aligned.b32 %0, %1;" :: "r"(tmem), "r"(ncols));
}
__device__ __forceinline__ void tcrelinquish() {
    asm volatile("tcgen05.relinquish_alloc_permit.cta_group::1.sync.aligned;");
}
__device__ __forceinline__ void tc_commit(uint32_t mbar) {
    asm volatile("tcgen05.commit.cta_group::1.mbarrier::arrive::one.shared::cluster.b64 [%0];"
                 :: "r"(mbar) : "memory");
}
__device__ __forceinline__ void wait_ld() {
    asm volatile("tcgen05.wait::ld.sync.aligned;" ::: "memory");
}
__device__ __forceinline__ void mma_tf32_ss(uint32_t d, uint64_t ad, uint64_t bd,
                                            uint32_t idesc, uint32_t en) {
    asm volatile(
        "{\n\t.reg .pred p;\n\tsetp.ne.u32 p, %4, 0;\n\t"
        "tcgen05.mma.cta_group::1.kind::tf32 [%0], %1, %2, %3, {%5,%5,%5,%5}, p;\n\t}"
        :: "r"(d), "l"(ad), "l"(bd), "r"(idesc), "r"(en), "r"(0u) : "memory");
}
__device__ __forceinline__ void mma_f16_ss(uint32_t d, uint64_t ad, uint64_t bd,
                                           uint32_t idesc, uint32_t en) {
    asm volatile(
        "{\n\t.reg .pred p;\n\tsetp.ne.u32 p, %4, 0;\n\t"
        "tcgen05.mma.cta_group::1.kind::f16 [%0], %1, %2, %3, {%5,%5,%5,%5}, p;\n\t}"
        :: "r"(d), "l"(ad), "l"(bd), "r"(idesc), "r"(en), "r"(0u) : "memory");
}
__device__ __forceinline__ void ldtm32(uint32_t* r, uint32_t a) {
    asm volatile(
        "tcgen05.ld.sync.aligned.32x32b.x32.b32 "
        "{%0,%1,%2,%3,%4,%5,%6,%7,%8,%9,%10,%11,%12,%13,%14,%15,"
        "%16,%17,%18,%19,%20,%21,%22,%23,%24,%25,%26,%27,%28,%29,%30,%31}, [%32];"
        : "=r"(r[0]), "=r"(r[1]), "=r"(r[2]), "=r"(r[3]),
          "=r"(r[4]), "=r"(r[5]), "=r"(r[6]), "=r"(r[7]),
          "=r"(r[8]), "=r"(r[9]), "=r"(r[10]), "=r"(r[11]),
          "=r"(r[12]), "=r"(r[13]), "=r"(r[14]), "=r"(r[15]),
          "=r"(r[16]), "=r"(r[17]), "=r"(r[18]), "=r"(r[19]),
          "=r"(r[20]), "=r"(r[21]), "=r"(r[22]), "=r"(r[23]),
          "=r"(r[24]), "=r"(r[25]), "=r"(r[26]), "=r"(r[27]),
          "=r"(r[28]), "=r"(r[29]), "=r"(r[30]), "=r"(r[31])
        : "r"(a));
}
static constexpr uint64_t DESC_BASE =
    (uint64_t(2) << 61) | (uint64_t(1) << 46) | (uint64_t(64) << 32) | (uint64_t(1) << 16);
__device__ __forceinline__ uint64_t mk_desc(uint32_t a) {
    return DESC_BASE | ((uint64_t)(a >> 4) & 0x3FFFull);
}
#endif // TC_OK

// ============================================================================
// Persistent GEMM: C = A @ B^T, tile 128 x NT.
// ============================================================================
template<int NT, int NST, int EB, int OBF>
__global__ __launch_bounds__(320, 1)
void gemm_tc(const __grid_constant__ CUtensorMap tmA,
             const __grid_constant__ CUtensorMap tmB,
             void* __restrict__ Cv, int K, int ldc,
             long long sC1, long long sC2,
             int ntiles, int gx, int gxy, int zsh, int koMul,
             const float* __restrict__ bias, const float* __restrict__ resid, int ldres,
             int relu, int round_out)
{
    extern __shared__ __align__(1024) uint8_t smraw[];

    const int tid = threadIdx.x, wid = tid >> 5, lane = tid & 31;
    const int nCTA = gridDim.x, bx = blockIdx.x;
    const int KCE = 128 / EB;
    const int T = K / KCE;

#if TC_OK
    constexpr int ABYTES = 16384;
    constexpr int BBYTES = NT * 128;
    constexpr int STGB = ABYTES + BBYTES;
    constexpr int EPIOFF = NST * STGB;
    constexpr int CTRL = EPIOFF + 8 * 32 * 9 * 16;
    constexpr uint32_t TYC = (EB == 4) ? 2u : 1u;
    constexpr uint32_t IDESC =
        (1u << 4) | (TYC << 7) | (TYC << 10) | ((uint32_t)(NT / 8) << 17) | (8u << 24);

    const uint32_t smb  = (uint32_t)__cvta_generic_to_shared(smraw);
    const uint32_t tptr = smb + CTRL;
    const uint32_t mbF  = tptr + 8;
    const uint32_t mbE  = mbF + 8 * NST;
    const uint32_t mbD  = mbE + 8 * NST;
    const uint32_t mbR  = mbD + 16;

    if (wid == 0) tcalloc(tptr, 512);
    if (tid == 0) {
        for (int s = 0; s < NST; ++s) { mbar_init(mbF + 8 * s, 1); mbar_init(mbE + 8 * s, 1); }
        mbar_init(mbD, 1);     mbar_init(mbD + 8, 1);
        mbar_init(mbR, 8);     mbar_init(mbR + 8, 8);
    }
    __syncthreads();
    uint32_t tmem;
    asm volatile("ld.shared.b32 %0, [%1];" : "=r"(tmem) : "r"(tptr));

    if (wid == 0) {
        if (elect1()) {
            int eph[NST];
#pragma unroll
            for (int s = 0; s < NST; ++s) eph[s] = 1;
            int s = 0;
            for (int t = bx; t < ntiles; t += nCTA) {
                const int tz = t / gxy, rem = t - tz * gxy;
                const int ty = rem / gx, tx = rem - ty * gx;
                const int row0 = ty * 128, col0 = tx * NT;
                const int zA = tz >> zsh;
                const int ko = (tz & ((1 << zsh) - 1)) * koMul;
                for (int c = 0; c < T; ++c) {
                    mbar_wait(mbE + 8 * s, eph[s]); eph[s] ^= 1;
                    const uint32_t bA = smb + s * STGB;
                    const uint32_t fb = mbF + 8 * s;
                    const int kc = ko + c * KCE;
                    mbar_expect_tx(fb, STGB);
                    tma3d(bA, &tmA, kc, row0, zA, fb);
                    tma3d(bA + ABYTES, &tmB, kc, col0, zA, fb);
                    if (++s == NST) s = 0;
                }
            }
        }
    } else if (wid == 1) {
        if (elect1()) {
            int fph[NST];
#pragma unroll
            for (int s = 0; s < NST; ++s) fph[s] = 0;
            int phF[2] = {1, 1};
            int s = 0, pk = 0;
            for (int t = bx; t < ntiles; t += nCTA) {
                const int p = pk & 1;
                mbar_wait(mbR + 8 * p, phF[p]); phF[p] ^= 1;
                const uint32_t dacc = tmem + p * NT;
                for (int c = 0; c < T; ++c) {
                    mbar_wait(mbF + 8 * s, fph[s]); fph[s] ^= 1;
                    const uint32_t bA = smb + s * STGB, bB = bA + ABYTES;
                    const uint64_t ad = mk_desc(bA), bd = mk_desc(bB);
#pragma unroll
                    for (int k8 = 0; k8 < 4; ++k8) {
                        const uint32_t en = (c > 0 || k8 > 0) ? 1u : 0u;
                        if (EB == 4) mma_tf32_ss(dacc, ad + 2 * k8, bd + 2 * k8, IDESC, en);
                        else         mma_f16_ss (dacc, ad + 2 * k8, bd + 2 * k8, IDESC, en);
                    }
                    tc_commit(mbE + 8 * s);
                    if (++s == NST) s = 0;
                }
                tc_commit(mbD + 8 * p);
                ++pk;
            }
        }
    } else {
        const int ew = wid - 2;
        const int sub = wid & 3;
        const int colhalf = ew >> 2;
        const int cbN = NT / 64;
        float4* wsm4 = (float4*)(smraw + EPIOFF) + ew * (32 * 9);
        int phD[2] = {0, 0};
        int pk = 0;
        for (int t = bx; t < ntiles; t += nCTA) {
            const int tz = t / gxy, rem = t - tz * gxy;
            const int ty = rem / gx, tx = rem - ty * gx;
            const int row0 = ty * 128, col0 = tx * NT;
            const size_t coff = (size_t)(tz >> 3) * sC1 + (size_t)(tz & 7) * sC2;
            const int p = pk & 1;
            mbar_wait(mbD + 8 * p, phD[p]); phD[p] ^= 1;
            tc_fence_after();

#pragma unroll 1
            for (int ci = 0; ci < cbN; ++ci) {
                const int cb = colhalf * cbN + ci;
                uint32_t rg[32];
                ldtm32(rg, tmem + p * NT + cb * 32);
                wait_ld();
                __syncwarp();
#pragma unroll
                for (int jq = 0; jq < 8; ++jq)
                    wsm4[lane * 9 + jq] = make_float4(__uint_as_float(rg[jq * 4 + 0]),
                                                      __uint_as_float(rg[jq * 4 + 1]),
                                                      __uint_as_float(rg[jq * 4 + 2]),
                                                      __uint_as_float(rg[jq * 4 + 3]));
                __syncwarp();
                const int cq = lane & 7, rsub = lane >> 3;
#pragma unroll 1
                for (int it = 0; it < 8; ++it) {
                    const int r = it * 4 + rsub;
                    float4 v = wsm4[r * 9 + cq];
                    const int orow = row0 + sub * 32 + r;
                    const int ocol = col0 + cb * 32 + cq * 4;
                    if (bias) {
                        const float4 bv = *(const float4*)&bias[ocol];
                        v.x += bv.x; v.y += bv.y; v.z += bv.z; v.w += bv.w;
                    }
                    if (resid) {
                        const float4 rv = *(const float4*)&resid[(size_t)orow * ldres + ocol];
                        v.x += rv.x; v.y += rv.y; v.z += rv.z; v.w += rv.w;
                    }
                    if (relu) {
                        v.x = fmaxf(v.x, 0.f); v.y = fmaxf(v.y, 0.f);
                        v.z = fmaxf(v.z, 0.f); v.w = fmaxf(v.w, 0.f);
                    }
                    if (round_out) {
                        v.x = f2tf_f(v.x); v.y = f2tf_f(v.y);
                        v.z = f2tf_f(v.z); v.w = f2tf_f(v.w);
                    }
                    if (OBF) {
                        __nv_bfloat16* Ch = (__nv_bfloat16*)Cv + coff;
                        __nv_bfloat162 p0 = __floats2bfloat162_rn(v.x, v.y);
                        __nv_bfloat162 p1 = __floats2bfloat162_rn(v.z, v.w);
                        uint2 u = make_uint2(*(uint32_t*)&p0, *(uint32_t*)&p1);
                        *(uint2*)&Ch[(size_t)orow * ldc + ocol] = u;
                    } else {
                        float* Cf = (float*)Cv + coff;
                        *(float4*)&Cf[(size_t)orow * ldc + ocol] = v;
                    }
                }
                __syncwarp();
            }
            __syncwarp();
            if (lane == 0) mbar_arrive(mbR + 8 * p);
            ++pk;
        }
    }

    __syncthreads();
    if (wid == 0) { tcrelinquish(); tcdealloc(tmem, 512); }
#else
    (void)Cv; (void)K; (void)ldc; (void)sC1; (void)sC2; (void)ntiles; (void)gx;
    (void)gxy; (void)zsh; (void)koMul; (void)bias; (void)resid; (void)ldres;
    (void)relu; (void)round_out; (void)T; (void)KCE; (void)nCTA; (void)bx;
    (void)lane; (void)wid; (void)tid;
#endif
}

// ============================================================================
// Flash attention (persistent): per unit (z, qtile) compute
//   O[qtile] = softmax_noshift(Q K^T / 16) V   with rowsum normalization.
// S-acc = TMEM[0..255], O-acc = TMEM[256..511]. P staged bf16 in smem (SW128).
// 320 threads: w0 TMA producer, w1 MMA issuer, w2-9 epilogue.
// ============================================================================
__global__ __launch_bounds__(320, 1)
void flash_attn(const __grid_constant__ CUtensorMap tmQ,
                const __grid_constant__ CUtensorMap tmK,
                const __grid_constant__ CUtensorMap tmV,
                float* __restrict__ O)
{
    extern __shared__ __align__(1024) uint8_t smraw[];
    const int tid = threadIdx.x, wid = tid >> 5, lane = tid & 31;
#if TC_OK
    constexpr int QOFF = 0, POFF = 65536, RING = 131072, STGB = 32768, NST = 3;
    constexpr int CTRL = RING + NST * STGB;     // 229376
    constexpr uint32_t IDESC = (1u<<4)|(1u<<7)|(1u<<10)|(32u<<17)|(8u<<24);
    constexpr int NUNITS = 512;

    const uint32_t smb = (uint32_t)__cvta_generic_to_shared(smraw);
    const uint32_t tptr = smb + CTRL;
    const uint32_t mbF  = tptr + 8;       // full[3]
    const uint32_t mbE  = mbF + 24;       // empty[3]
    const uint32_t mbS  = mbE + 24;       // S done (per kt)
    const uint32_t mbP  = mbS + 8;        // P ready (count 8, per kt)
    const uint32_t mbO  = mbP + 8;        // O done (per unit)
    const uint32_t mbOF = mbO + 8;        // O free (count 8, per unit)
    const uint32_t mbQL = mbOF + 8;       // Q loaded (per unit)
    const uint32_t mbQF = mbQL + 8;       // Q free (per unit)

    if (wid == 0) tcalloc(tptr, 512);
    if (tid == 0) {
        for (int s = 0; s < NST; ++s) { mbar_init(mbF + 8*s, 1); mbar_init(mbE + 8*s, 1); }
        mbar_init(mbS, 1); mbar_init(mbP, 8); mbar_init(mbO, 1);
        mbar_init(mbOF, 8); mbar_init(mbQL, 1); mbar_init(mbQF, 1);
    }
    __syncthreads();
    uint32_t tmem;
    asm volatile("ld.shared.b32 %0, [%1];" : "=r"(tmem) : "r"(tptr));

    const int nCTA = gridDim.x, bx = blockIdx.x;

    if (wid == 0) {
        if (elect1()) {
            // ------------------ TMA producer ------------------
            int eph[NST] = {1, 1, 1};
            int qfph = 1, s = 0;
            for (int u = bx; u < NUNITS; u += nCTA) {
                const int z = u >> 3, qt = u & 7, b = z >> 3, h = z & 7;
                mbar_wait(mbQF, qfph); qfph ^= 1;
                mbar_expect_tx(mbQL, 65536);
#pragma unroll
                for (int c = 0; c < 4; ++c)
                    tma3d(smb + QOFF + c * 16384, &tmQ, h * 256 + c * 64, qt * 128, b, mbQL);
                for (int kt = 0; kt < 4; ++kt) {
#pragma unroll
                    for (int c = 0; c < 4; ++c) {
                        mbar_wait(mbE + 8*s, eph[s]); eph[s] ^= 1;
                        mbar_expect_tx(mbF + 8*s, STGB);
                        tma3d(smb + RING + s * STGB, &tmK, h * 256 + c * 64, kt * 256, b, mbF + 8*s);
                        if (++s == NST) s = 0;
                    }
#pragma unroll
                    for (int c = 0; c < 4; ++c) {
                        mbar_wait(mbE + 8*s, eph[s]); eph[s] ^= 1;
                        mbar_expect_tx(mbF + 8*s, STGB);
                        tma3d(smb + RING + s * STGB, &tmV, kt * 256 + c * 64, 0, z, mbF + 8*s);
                        if (++s == NST) s = 0;
                    }
                }
            }
        }
    } else if (wid == 1) {
        if (elect1()) {
            // ------------------ MMA issuer ------------------
            int fph[NST] = {0, 0, 0};
            int qph = 0, pph = 0, ofph = 1, s = 0;
            for (int u = bx; u < NUNITS; u += nCTA) {
                mbar_wait(mbQL, qph); qph ^= 1;
                for (int kt = 0; kt < 4; ++kt) {
                    // GEMM1: S = Q @ K^T
#pragma unroll
                    for (int c = 0; c < 4; ++c) {
                        mbar_wait(mbF + 8*s, fph[s]); fph[s] ^= 1;
                        const uint64_t ad = mk_desc(smb + QOFF + c * 16384);
                        const uint64_t bd = mk_desc(smb + RING + s * STGB);
#pragma unroll
                        for (int k8 = 0; k8 < 4; ++k8)
                            mma_f16_ss(tmem, ad + 2*k8, bd + 2*k8, IDESC, (c > 0 || k8 > 0) ? 1u : 0u);
                        tc_commit(mbE + 8*s);
                        if (++s == NST) s = 0;
                    }
                    tc_commit(mbS);
                    mbar_wait(mbP, pph); pph ^= 1;
                    if (kt == 0) { mbar_wait(mbOF, ofph); ofph ^= 1; }
                    // GEMM2: O += P @ V^T
#pragma unroll
                    for (int c = 0; c < 4; ++c) {
                        mbar_wait(mbF + 8*s, fph[s]); fph[s] ^= 1;
                        const uint64_t ad = mk_desc(smb + POFF + c * 16384);
                        const uint64_t bd = mk_desc(smb + RING + s * STGB);
#pragma unroll
                        for (int k8 = 0; k8 < 4; ++k8)
                            mma_f16_ss(tmem + 256, ad + 2*k8, bd + 2*k8, IDESC,
                                       (kt > 0 || c > 0 || k8 > 0) ? 1u : 0u);
                        tc_commit(mbE + 8*s);
                        if (++s == NST) s = 0;
                    }
                }
                tc_commit(mbO);
                tc_commit(mbQF);
            }
        }
    } else {
        // ------------------ epilogue warps 2..9 ------------------
        const int ew = wid - 2, sub = ew & 3, colhalf = ew >> 2;
        float* wsum = (float*)(smraw + POFF + 40960);
        float4* wsm4 = (float4*)(smraw + POFF) + ew * (32 * 9);
        const int xr7 = lane & 7;
        const uint32_t pbase = smb + POFF + (uint32_t)(sub * 32 + lane) * 128;
        int sph = 0, oph = 0;
        for (int u = bx; u < NUNITS; u += nCTA) {
            const int z = u >> 3, qt = u & 7, b = z >> 3, h = z & 7;
            float rowsum = 0.f;
            for (int kt = 0; kt < 4; ++kt) {
                mbar_wait(mbS, sph); sph ^= 1;
                tc_fence_after();
#pragma unroll
                for (int ci = 0; ci < 4; ++ci) {
                    const int cb = colhalf * 4 + ci;
                    uint32_t rg[32];
                    ldtm32(rg, tmem + cb * 32);
                    wait_ld();
                    uint32_t w[16];
#pragma unroll
                    for (int j = 0; j < 16; ++j) {
                        float a0 = __expf(__uint_as_float(rg[2*j])     * 0.0625f);
                        float a1 = __expf(__uint_as_float(rg[2*j + 1]) * 0.0625f);
                        __nv_bfloat162 pk2 = __floats2bfloat162_rn(a0, a1);
                        w[j] = *(uint32_t*)&pk2;
                        rowsum += __bfloat162float(__low2bfloat16(pk2)) +
                                  __bfloat162float(__high2bfloat16(pk2));
                    }
                    const uint32_t cbase = pbase + (uint32_t)(cb >> 1) * 16384u;
                    const int q0 = (cb & 1) * 4;
#pragma unroll
                    for (int qq = 0; qq < 4; ++qq) {
                        const uint32_t addr = cbase + (uint32_t)(((q0 + qq) ^ xr7) << 4);
                        asm volatile("st.shared.v4.b32 [%0], {%1,%2,%3,%4};"
                                     :: "r"(addr), "r"(w[qq*4]), "r"(w[qq*4+1]),
                                        "r"(w[qq*4+2]), "r"(w[qq*4+3]) : "memory");
                    }
                }
                asm volatile("fence.proxy.async.shared::cta;" ::: "memory");
                __syncwarp();
                if (lane == 0) mbar_arrive(mbP);
            }
            // ---- O drain ----
            mbar_wait(mbO, oph); oph ^= 1;
            tc_fence_after();
            wsum[ew * 32 + lane] = rowsum;
            asm volatile("bar.sync 1, 256;" ::: "memory");
            const float inv = __frcp_rn(wsum[sub * 32 + lane] + wsum[(sub + 4) * 32 + lane]);
            const int row0 = b * L_ + qt * 128;
            const int col0 = h * 256;
#pragma unroll 1
            for (int ci = 0; ci < 4; ++ci) {
                const int cb = colhalf * 4 + ci;
                uint32_t rg[32];
                ldtm32(rg, tmem + 256 + cb * 32);
                wait_ld();
                __syncwarp();
#pragma unroll
                for (int jq = 0; jq < 8; ++jq)
                    wsm4[lane * 9 + jq] = make_float4(
                        f2tf_f(__uint_as_float(rg[jq*4+0]) * inv),
                        f2tf_f(__uint_as_float(rg[jq*4+1]) * inv),
                        f2tf_f(__uint_as_float(rg[jq*4+2]) * inv),
                        f2tf_f(__uint_as_float(rg[jq*4+3]) * inv));
                __syncwarp();
                const int cq = lane & 7, rsub = lane >> 3;
#pragma unroll 1
                for (int it = 0; it < 8; ++it) {
                    const int r = it * 4 + rsub;
                    float4 v = wsm4[r * 9 + cq];
                    const int orow = row0 + sub * 32 + r;
                    const int ocol = col0 + cb * 32 + cq * 4;
                    *(float4*)&O[(size_t)orow * HD_ + ocol] = v;
                }
                __syncwarp();
            }
            __syncwarp();
            if (lane == 0) mbar_arrive(mbOF);
        }
    }
    __syncthreads();
    if (wid == 0) { tcrelinquish(); tcdealloc(tmem, 512); }
#else
    (void)O; (void)tid; (void)wid; (void)lane;
#endif
}

// --------------------------- merged tf32 rounding pass -----------------------
__global__ void cvt_all_kernel(const float4* x, float4* xr,
                               const float4* wq, const float4* wk, const float4* wv,
                               float4* wqkv,
                               const float4* wu, float4* wur,
                               const float4* w1, float4* w1r,
                               const float4* w2, float4* w2r)
{
    const int WSEG = HD_ * D_ / 4;
    const int total = 524288 + 4 * WSEG + 2 * 65536;
    for (int i = blockIdx.x * blockDim.x + threadIdx.x; i < total; i += gridDim.x * blockDim.x) {
        const float4* in; float4* out; int j = i;
        if (j < 524288) { in = x; out = xr; }
        else if ((j -= 524288) < WSEG) { in = wq; out = wqkv; }
        else if ((j -= WSEG) < WSEG)   { in = wk; out = wqkv + WSEG; }
        else if ((j -= WSEG) < WSEG)   { in = wv; out = wqkv + 2 * WSEG; }
        else if ((j -= WSEG) < WSEG)   { in = wu; out = wur; }
        else if ((j -= WSEG) < 65536)  { in = w1; out = w1r; }
        else { j -= 65536; in = w2; out = w2r; }
        float4 v = in[j];
        v.x = f2tf_f(v.x); v.y = f2tf_f(v.y); v.z = f2tf_f(v.z); v.w = f2tf_f(v.w);
        out[j] = v;
    }
}

// -------- V transpose (bf16): Vt[z][e][j] = QKV[b*L+j][2*HD + h*256 + e] -----
__global__ void transpose_v(const __nv_bfloat16* __restrict__ QKV,
                            __nv_bfloat16* __restrict__ Vt)
{
    __shared__ __nv_bfloat16 t[32][33];
    const int z = blockIdx.z, b = z >> 3, h = z & 7;
    const int j0 = blockIdx.x * 32, e0 = blockIdx.y * 32;
    const int tx = threadIdx.x, ty = threadIdx.y;
#pragma unroll
    for (int k = 0; k < 4; k++)
        t[ty + k * 8][tx] = QKV[(size_t)(b * L_ + j0 + ty + k * 8) * QKVW_ + 2 * HD_ + h * D_ + e0 + tx];
    __syncthreads();
#pragma unroll
    for (int k = 0; k < 4; k++)
        Vt[(size_t)z * D_ * L_ + (size_t)(e0 + ty + k * 8) * L_ + j0 + tx] = t[tx][ty + k * 8];
}

// --------------------------- layernorm over d=256 ----------------------------
__global__ void ln_kernel(const float* __restrict__ in, float* __restrict__ out,
                          float* __restrict__ out_r,
                          const float* __restrict__ g, const float* __restrict__ be)
{
    __shared__ float r1[8], r2[8];
    const int row = blockIdx.x, t = threadIdx.x;
    const float v = in[(size_t)row * D_ + t];
    float s = v, q = v * v;
#pragma unroll
    for (int o = 16; o; o >>= 1) {
        s += __shfl_xor_sync(~0u, s, o);
        q += __shfl_xor_sync(~0u, q, o);
    }
    if ((t & 31) == 0) { r1[t >> 5] = s; r2[t >> 5] = q; }
    __syncthreads();
    float S = 0.f, Q = 0.f;
#pragma unroll
    for (int i = 0; i < 8; i++) { S += r1[i]; Q += r2[i]; }
    const float mean = S * (1.f / D_);
    const float var = Q * (1.f / D_) - mean * mean;
    const float y = (v - mean) * rsqrtf(var + EPS_) * g[t] + be[t];
    out[(size_t)row * D_ + t] = y;
    if (out_r) out_r[(size_t)row * D_ + t] = f2tf_f(y);
}

// --------------------------- host: tensormap encoding ------------------------
typedef CUresult (*EncFn)(CUtensorMap*, CUtensorMapDataType, cuuint32_t, void*,
                          const cuuint64_t*, const cuuint64_t*, const cuuint32_t*,
                          const cuuint32_t*, CUtensorMapInterleave, CUtensorMapSwizzle,
                          CUtensorMapL2promotion, CUtensorMapFloatOOBfill);

static EncFn get_enc() {
    static EncFn fn = nullptr;
    if (!fn) {
        void* p = nullptr;
        cudaDriverEntryPointQueryResult st;
        cudaGetDriverEntryPoint("cuTensorMapEncodeTiled", &p, cudaEnableDefault, &st);
        fn = (EncFn)p;
    }
    return fn;
}

static void mk3d(CUtensorMap* tm, void* ptr, CUtensorMapDataType dt,
                 unsigned long long d0, unsigned long long d1, unsigned long long d2,
                 unsigned long long s1B, unsigned long long s2B,
                 unsigned b0, unsigned b1)
{
    cuuint64_t dims[3] = {d0, d1, d2};
    cuuint64_t strides[2] = {s1B, s2B};
    cuuint32_t box[3] = {b0, b1, 1};
    cuuint32_t es[3] = {1, 1, 1};
    get_enc()(tm, dt, 3, ptr, dims, strides, box, es,
              CU_TENSOR_MAP_INTERLEAVE_NONE, CU_TENSOR_MAP_SWIZZLE_128B,
              CU_TENSOR_MAP_L2_PROMOTION_L2_128B, CU_TENSOR_MAP_FLOAT_OOB_FILL_NONE);
}

// --------------------------- launch ------------------------------------------
extern "C" void kernel_launch(void* const* d_in, const int* in_sizes, int n_in,
                              void* d_out, int out_size)
{
    const float* x   = (const float*)d_in[0];
    const float* Wq  = (const float*)d_in[1];
    const float* Wk  = (const float*)d_in[2];
    const float* Wv  = (const float*)d_in[3];
    const float* Wu  = (const float*)d_in[4];
    const float* bu  = (const float*)d_in[5];
    const float* W1  = (const float*)d_in[6];
    const float* b1  = (const float*)d_in[7];
    const float* W2  = (const float*)d_in[8];
    const float* b2  = (const float*)d_in[9];
    const float* g1  = (const float*)d_in[10];
    const float* be1 = (const float*)d_in[11];
    const float* g2  = (const float*)d_in[12];
    const float* be2 = (const float*)d_in[13];
    float* out = (float*)d_out;

    __nv_bfloat16 *QKVh, *Vth;
    float *O, *R1, *Z1, *Z1r, *Hb, *F, *xr, *Wqkvr, *Wur, *W1r, *W2r;
    cudaGetSymbolAddress((void**)&QKVh, g_QKVh);
    cudaGetSymbolAddress((void**)&Vth, g_Vth);
    cudaGetSymbolAddress((void**)&O,  g_O);
    cudaGetSymbolAddress((void**)&R1, g_R1);
    cudaGetSymbolAddress((void**)&Z1, g_Z1);
    cudaGetSymbolAddress((void**)&Z1r, g_Z1r);
    cudaGetSymbolAddress((void**)&Hb, g_Hb);
    cudaGetSymbolAddress((void**)&F,  g_F);
    cudaGetSymbolAddress((void**)&xr,  g_xr);
    cudaGetSymbolAddress((void**)&Wqkvr, g_Wqkvr);
    cudaGetSymbolAddress((void**)&Wur, g_Wur);
    cudaGetSymbolAddress((void**)&W1r, g_W1r);
    cudaGetSymbolAddress((void**)&W2r, g_W2r);

    // ---- tensor maps
    CUtensorMap tXr, tWqkv, tQ, tK, tV, tO, tWu, tZ1, tW1, tHb, tW2;
    const unsigned long long F4 = 4, F2 = 2;
    const CUtensorMapDataType DF = CU_TENSOR_MAP_DATA_TYPE_FLOAT32;
    const CUtensorMapDataType DB = CU_TENSOR_MAP_DATA_TYPE_BFLOAT16;
    mk3d(&tXr,  xr,    DF, D_, ROWS_, 1, D_ * F4, 0, 32, 128);
    mk3d(&tWqkv, Wqkvr, DF, D_, QKVW_, 1, D_ * F4, 0, 32, 256);
    mk3d(&tQ, QKVh,       DB, HD_, L_, B_, (unsigned long long)QKVW_ * F2,
         (unsigned long long)L_ * QKVW_ * F2, 64, 128);
    mk3d(&tK, QKVh + HD_, DB, HD_, L_, B_, (unsigned long long)QKVW_ * F2,
         (unsigned long long)L_ * QKVW_ * F2, 64, 256);
    mk3d(&tV, Vth, DB, L_, D_, B_ * H_, (unsigned long long)L_ * F2,
         (unsigned long long)D_ * L_ * F2, 64, 256);
    mk3d(&tO,  O,   DF, HD_, ROWS_, 1, (unsigned long long)HD_ * F4, 0, 32, 128);
    mk3d(&tWu, Wur, DF, HD_, D_,    1, (unsigned long long)HD_ * F4, 0, 32, 128);
    mk3d(&tZ1, Z1r, DF, D_,  ROWS_, 1, D_ * F4, 0, 32, 128);
    mk3d(&tW1, W1r, DF, D_,  F_,    1, D_ * F4, 0, 32, 256);
    mk3d(&tHb, Hb,  DF, F_,  ROWS_, 1, (unsigned long long)F_ * F4, 0, 32, 128);
    mk3d(&tW2, W2r, DF, F_,  D_,    1, (unsigned long long)F_ * F4, 0, 32, 128);

    constexpr int SM256 = 3 * 49152 + 8 * 32 * 9 * 16 + 128;
    constexpr int SM128 = 4 * 32768 + 8 * 32 * 9 * 16 + 128;
    constexpr int SMFL  = 229504;
    cudaFuncSetAttribute(gemm_tc<256,3,4,1>, cudaFuncAttributeMaxDynamicSharedMemorySize, SM256);
    cudaFuncSetAttribute(gemm_tc<256,3,4,0>, cudaFuncAttributeMaxDynamicSharedMemorySize, SM256);
    cudaFuncSetAttribute(gemm_tc<128,4,4,0>, cudaFuncAttributeMaxDynamicSharedMemorySize, SM128);
    cudaFuncSetAttribute(flash_attn, cudaFuncAttributeMaxDynamicSharedMemorySize, SMFL);

    cvt_all_kernel<<<1184, 256>>>((const float4*)x, (float4*)xr,
                                  (const float4*)Wq, (const float4*)Wk, (const float4*)Wv,
                                  (float4*)Wqkvr,
                                  (const float4*)Wu, (float4*)Wur,
                                  (const float4*)W1, (float4*)W1r,
                                  (const float4*)W2, (float4*)W2r);

    // fused QKV: [8192,256] @ [6144,256]^T -> QKVh bf16
    gemm_tc<256,3,4,1><<<148, 320, SM256>>>(tXr, tWqkv, QKVh,
        D_, QKVW_, 0, 0,
        1536, 24, 1536, 0, 0,
        nullptr, nullptr, 0, 0, 0);

    transpose_v<<<dim3(L_/32, D_/32, B_*H_), dim3(32, 8)>>>(QKVh, Vth);

    // fused attention: O = softmax(QK^T/16) V
    flash_attn<<<148, 320, SMFL>>>(tQ, tK, tV, O);

    // output projection + bias + residual(x)
    gemm_tc<128,4,4,0><<<128, 320, SM128>>>(tO, tWu, R1,
        HD_, D_, 0, 0,
        128, 2, 128, 0, 0,
        bu, x, D_, 0, 0);
    ln_kernel<<<ROWS_, 256>>>(R1, Z1, Z1r, g1, be1);

    // FFN
    gemm_tc<256,3,4,0><<<148, 320, SM256>>>(tZ1, tW1, Hb,
        D_, F_, 0, 0,
        256, 4, 256, 0, 0,
        b1, nullptr, 0, 1, 1);
    gemm_tc<128,4,4,0><<<128, 320, SM128>>>(tHb, tW2, F,
        F_, D_, 0, 0,
        128, 2, 128, 0, 0,
        b2, Z1, D_, 0, 0);
    ln_kernel<<<ROWS_, 256>>>(F, out, nullptr, g2, be2);
}